// round 5
// baseline (speedup 1.0000x reference)
#include <cuda_runtime.h>
#include <cuda_bf16.h>
#include <mma.h>
#include <cstdint>
#include <math.h>

using namespace nvcuda;

#define DEPTH  15
#define NNODES 65535
#define NEDGE  65534
#define MPAD   65536
#define HID    128
#define NF     13
#define EFDIM  4
#define NL     3

// ---------------- scratch (device globals; no allocs) ----------------
__device__ float g_x13[NNODES * NF];
__device__ float g_xA [MPAD * HID];
__device__ float g_xB [MPAD * HID];
__device__ float g_y  [MPAD * HID];
__device__ float g_es [MPAD * 4];
__device__ float g_ed [MPAD * 4];
__device__ float g_wsd[NL * HID * 8];
__device__ __align__(16) __nv_bfloat16 g_Ah[(MPAD + 8) * HID];
__device__ __align__(16) __nv_bfloat16 g_Al[(MPAD + 8) * HID];
__device__ __align__(16) __nv_bfloat16 g_Zh[MPAD * 512];
__device__ __align__(16) __nv_bfloat16 g_Zl[MPAD * 512];
__device__ __align__(16) __nv_bfloat16 g_Bh[512 * HID];
__device__ __align__(16) __nv_bfloat16 g_Bl[512 * HID];

// ---------------- weight split: W[K,N] row-major -> [N][K] bf16 hi/lo ----------------
__global__ void k_splitT(const float* __restrict__ W, __nv_bfloat16* __restrict__ bh,
                         __nv_bfloat16* __restrict__ bl, int K, int N) {
    int i = blockIdx.x * blockDim.x + threadIdx.x;
    if (i >= K * N) return;
    int k = i / N, n = i - k * N;
    float v = W[(size_t)k * N + n];
    __nv_bfloat16 h = __float2bfloat16(v);
    bh[(size_t)n * K + k] = h;
    bl[(size_t)n * K + k] = __float2bfloat16(v - __bfloat162float(h));
}
// GAT stacked weight: B[d][h*128+k] = W[k][h*128+d] * 0.25 (mean over heads folded)
__global__ void k_splitTg(const float* __restrict__ W) {
    int i = blockIdx.x * blockDim.x + threadIdx.x;
    if (i >= 128 * 512) return;
    int d = i >> 9, kk = i & 511;
    int h = kk >> 7, k = kk & 127;
    float v = W[(size_t)k * 512 + h * 128 + d] * 0.25f;
    __nv_bfloat16 hh = __float2bfloat16(v);
    g_Bh[(size_t)d * 512 + kk] = hh;
    g_Bl[(size_t)d * 512 + kk] = __float2bfloat16(v - __bfloat162float(hh));
}

// ---------------- WMMA bf16x3 GEMM, 128x128 tile, K = KC*128, N = 128 ----------------
// EDGE: A rows gathered from node matrix (chunk0: e>>1, chunk1: e+1).
// Epilogue staged through smem: bias, relu, guarded fp32 C write, bf16 hi/lo split write.
template <int KC, bool EDGE, bool GUARD, bool RELU, bool WC, bool WSPLIT>
__global__ void __launch_bounds__(256, 1)
k_mm(const __nv_bfloat16* __restrict__ Ah, const __nv_bfloat16* __restrict__ Al,
     const __nv_bfloat16* __restrict__ Bh, const __nv_bfloat16* __restrict__ Bl,
     const float* __restrict__ bias, float* __restrict__ C, int Mg,
     __nv_bfloat16* __restrict__ OAh, __nv_bfloat16* __restrict__ OAl) {
    extern __shared__ __nv_bfloat16 sm[];
    __nv_bfloat16* sAh = sm;
    __nv_bfloat16* sAl = sm + 128 * 136;
    __nv_bfloat16* sBh = sm + 2 * 128 * 136;
    __nv_bfloat16* sBl = sBh + 128 * 136;

    const int tid = threadIdx.x;
    const int wid = tid >> 5;
    const int rowBase = blockIdx.x * 128;
    const int wm = wid & 3, wn = wid >> 2;
    const int row_off = wm * 32, col_off = wn * 64;

    wmma::fragment<wmma::accumulator, 16, 16, 16, float> acc[2][4];
#pragma unroll
    for (int i = 0; i < 2; i++)
#pragma unroll
        for (int j = 0; j < 4; j++) wmma::fill_fragment(acc[i][j], 0.0f);

    const uint4* gAh = (const uint4*)Ah;
    const uint4* gAl = (const uint4*)Al;
    const uint4* gBh = (const uint4*)Bh;
    const uint4* gBl = (const uint4*)Bl;

#pragma unroll
    for (int c = 0; c < KC; c++) {
        for (int id = tid; id < 128 * 16; id += 256) {
            int r = id >> 4, q = id & 15;
            size_t g;
            if (EDGE) {
                int e = rowBase + r;
                g = (size_t)((c == 0) ? (e >> 1) : (e + 1)) * 16 + q;
            } else {
                g = (size_t)(rowBase + r) * (KC * 16) + c * 16 + q;
            }
            *(uint4*)&sAh[r * 136 + q * 8] = gAh[g];
            *(uint4*)&sAl[r * 136 + q * 8] = gAl[g];
        }
        for (int id = tid; id < 128 * 16; id += 256) {
            int r = id >> 4, q = id & 15;
            size_t g = (size_t)r * (KC * 16) + c * 16 + q;
            *(uint4*)&sBh[r * 136 + q * 8] = gBh[g];
            *(uint4*)&sBl[r * 136 + q * 8] = gBl[g];
        }
        __syncthreads();

#pragma unroll
        for (int ks = 0; ks < 8; ks++) {
            wmma::fragment<wmma::matrix_a, 16, 16, 16, __nv_bfloat16, wmma::row_major> ah[2], al[2];
            wmma::fragment<wmma::matrix_b, 16, 16, 16, __nv_bfloat16, wmma::col_major> bh[4], bl[4];
#pragma unroll
            for (int i = 0; i < 2; i++) {
                wmma::load_matrix_sync(ah[i], sAh + (row_off + i * 16) * 136 + ks * 16, 136);
                wmma::load_matrix_sync(al[i], sAl + (row_off + i * 16) * 136 + ks * 16, 136);
            }
#pragma unroll
            for (int j = 0; j < 4; j++) {
                wmma::load_matrix_sync(bh[j], sBh + (col_off + j * 16) * 136 + ks * 16, 136);
                wmma::load_matrix_sync(bl[j], sBl + (col_off + j * 16) * 136 + ks * 16, 136);
            }
#pragma unroll
            for (int i = 0; i < 2; i++)
#pragma unroll
                for (int j = 0; j < 4; j++) {
                    wmma::mma_sync(acc[i][j], ah[i], bh[j], acc[i][j]);
                    wmma::mma_sync(acc[i][j], ah[i], bl[j], acc[i][j]);
                    wmma::mma_sync(acc[i][j], al[i], bh[j], acc[i][j]);
                }
        }
        __syncthreads();
    }

    // ---- staged epilogue ----
    float* stage = (float*)sm;   // 128 x 132 fp32 (fits in A region)
#pragma unroll
    for (int i = 0; i < 2; i++)
#pragma unroll
        for (int j = 0; j < 4; j++)
            wmma::store_matrix_sync(stage + (row_off + i * 16) * 132 + col_off + j * 16,
                                    acc[i][j], 132, wmma::mem_row_major);
    __syncthreads();
    for (int id = tid; id < 128 * 64; id += 256) {
        int r = id >> 6, c2 = (id & 63) * 2;
        float v0 = stage[r * 132 + c2];
        float v1 = stage[r * 132 + c2 + 1];
        if (bias) { v0 += bias[c2]; v1 += bias[c2 + 1]; }
        if (RELU) { v0 = fmaxf(v0, 0.f); v1 = fmaxf(v1, 0.f); }
        int row = rowBase + r;
        if (WC && (!GUARD || row < Mg)) {
            float2 f2 = make_float2(v0, v1);
            *(float2*)&C[(size_t)row * 128 + c2] = f2;
        }
        if (WSPLIT) {
            __nv_bfloat16 h0 = __float2bfloat16(v0);
            __nv_bfloat16 h1 = __float2bfloat16(v1);
            __nv_bfloat162 hp; hp.x = h0; hp.y = h1;
            *(__nv_bfloat162*)&OAh[(size_t)row * 128 + c2] = hp;
            __nv_bfloat162 lp;
            lp.x = __float2bfloat16(v0 - __bfloat162float(h0));
            lp.y = __float2bfloat16(v1 - __bfloat162float(h1));
            *(__nv_bfloat162*)&OAl[(size_t)row * 128 + c2] = lp;
        }
    }
}

// ---------------- propagate ----------------
__global__ void k_copy(const float* __restrict__ src, float* __restrict__ dst, int n) {
    int i = blockIdx.x * blockDim.x + threadIdx.x;
    if (i < n) dst[i] = src[i];
}
__global__ void k_prop(int start, int count) {
    int i = blockIdx.x * blockDim.x + threadIdx.x;
    if (i >= count * NF) return;
    int n = start + i / NF;
    int f = i - (i / NF) * NF;
    g_x13[n * NF + f] = 0.5f * (g_x13[(2 * n + 1) * NF + f] + g_x13[(2 * n + 2) * NF + f]);
}
__global__ void k_prop_top() {
    for (int d = 8; d >= 0; d--) {
        int start = (1 << d) - 1, count = 1 << d, tot = count * NF;
        for (int i = threadIdx.x; i < tot; i += blockDim.x) {
            int n = start + i / NF, f = i % NF;
            g_x13[n * NF + f] = 0.5f * (g_x13[(2 * n + 1) * NF + f] + g_x13[(2 * n + 2) * NF + f]);
        }
        __syncthreads();
    }
}

// ---------------- node MLP layer 1: relu(x13 @ W1 + b1) -> bf16 hi/lo ----------------
__global__ void k_mlp1(const float* __restrict__ x13, const float* __restrict__ W1,
                       const float* __restrict__ b1) {
    __shared__ float sW[NF * HID];
    __shared__ float srow[2][NF];
    int tid = threadIdx.x;
    for (int i = tid; i < NF * HID; i += 256) sW[i] = W1[i];
    for (int n0 = blockIdx.x * 2; n0 < MPAD; n0 += gridDim.x * 2) {
        __syncthreads();
        if (tid < 2 * NF) {
            int rr = tid / NF, f = tid - rr * NF;
            int nn = n0 + rr;
            srow[rr][f] = (nn < NNODES) ? x13[nn * NF + f] : 0.f;
        }
        __syncthreads();
        int half = tid >> 7, c = tid & 127;
        int n = n0 + half;
        float acc = b1[c];
#pragma unroll
        for (int k = 0; k < NF; k++) acc = fmaf(srow[half][k], sW[k * HID + c], acc);
        acc = fmaxf(acc, 0.f);
        __nv_bfloat16 h = __float2bfloat16(acc);
        g_Ah[(size_t)n * HID + c] = h;
        g_Al[(size_t)n * HID + c] = __float2bfloat16(acc - __bfloat162float(h));
    }
}

// ---------------- folded attention vectors (all 3 layers) ----------------
__global__ void k_wsd3(const float* __restrict__ W, const float* __restrict__ as,
                       const float* __restrict__ ad) {
    int l = blockIdx.x;
    int tid = threadIdx.x;           // 512
    int k = tid >> 2, h = tid & 3;
    const float* wr = W + (size_t)l * HID * 512 + (size_t)k * 512 + h * 128;
    const float* av = as + l * 512 + h * 128;
    const float* dv = ad + l * 512 + h * 128;
    float s = 0.f, d2 = 0.f;
    for (int dd = 0; dd < 128; dd++) {
        float w = wr[dd];
        s  = fmaf(w, av[dd], s);
        d2 = fmaf(w, dv[dd], d2);
    }
    g_wsd[l * 1024 + k * 8 + h]     = s;
    g_wsd[l * 1024 + k * 8 + 4 + h] = d2;
}

// ---------------- es/ed from fp32 x (layer 0 only) ----------------
__global__ void k_esed(const float* __restrict__ x, const float* __restrict__ wsd) {
    int warp = (blockIdx.x * blockDim.x + threadIdx.x) >> 5;
    if (warp >= MPAD) return;
    int lane = threadIdx.x & 31;
    int d0 = lane * 4;
    float4 xv = *(const float4*)&x[(size_t)warp * HID + d0];
    float v[4] = {xv.x, xv.y, xv.z, xv.w};
    float pr[8];
#pragma unroll
    for (int p = 0; p < 8; p++) pr[p] = 0.f;
#pragma unroll
    for (int k = 0; k < 4; k++) {
        const float* w = wsd + (d0 + k) * 8;
#pragma unroll
        for (int p = 0; p < 8; p++) pr[p] = fmaf(v[k], w[p], pr[p]);
    }
#pragma unroll
    for (int o = 16; o > 0; o >>= 1)
#pragma unroll
        for (int p = 0; p < 8; p++) pr[p] += __shfl_xor_sync(0xffffffffu, pr[p], o);
    if (lane == 0) {
#pragma unroll
        for (int h = 0; h < 4; h++) {
            g_es[warp * 4 + h] = pr[h];
            g_ed[warp * 4 + h] = pr[4 + h];
        }
    }
}

// ---------------- z gather: Z[n, h*128+d] = sum_j alpha_jh * x[nb_j][d] (bf16 hi/lo) ----
__global__ void k_zgat() {
    int warp = (blockIdx.x * blockDim.x + threadIdx.x) >> 5;
    if (warp >= MPAD) return;
    int lane = threadIdx.x & 31;
    int n = warp;
    bool vp = (n > 0);
    int p = vp ? (n - 1) >> 1 : 0;
    int c1 = 2 * n + 1;
    bool vc = (c1 < NNODES);
    int nb[4]  = {n, p, c1, c1 + 1};
    bool v[4]  = {true, vp, vc, vc};

    float edv[4], e[4][4], m[4], sum[4], a[4][4];
#pragma unroll
    for (int h = 0; h < 4; h++) { edv[h] = g_ed[n * 4 + h]; m[h] = -1e30f; sum[h] = 0.f; }
#pragma unroll
    for (int j = 0; j < 4; j++) if (v[j]) {
#pragma unroll
        for (int h = 0; h < 4; h++) {
            float s = g_es[nb[j] * 4 + h] + edv[h];
            s = (s >= 0.f) ? s : 0.2f * s;
            e[j][h] = s;
            m[h] = fmaxf(m[h], s);
        }
    }
#pragma unroll
    for (int j = 0; j < 4; j++) if (v[j]) {
#pragma unroll
        for (int h = 0; h < 4; h++) { e[j][h] = expf(e[j][h] - m[h]); sum[h] += e[j][h]; }
    }
#pragma unroll
    for (int h = 0; h < 4; h++) {
        float inv = 1.f / sum[h];
#pragma unroll
        for (int j = 0; j < 4; j++) a[h][j] = v[j] ? e[j][h] * inv : 0.f;
    }

    float z[4][4];
#pragma unroll
    for (int h = 0; h < 4; h++)
#pragma unroll
        for (int d = 0; d < 4; d++) z[h][d] = 0.f;

#pragma unroll
    for (int j = 0; j < 4; j++) if (v[j]) {
        const __nv_bfloat162* ph = (const __nv_bfloat162*)&g_Ah[(size_t)nb[j] * HID + lane * 4];
        const __nv_bfloat162* pl = (const __nv_bfloat162*)&g_Al[(size_t)nb[j] * HID + lane * 4];
        __nv_bfloat162 h0 = ph[0], h1 = ph[1], l0 = pl[0], l1 = pl[1];
        float x0 = __bfloat162float(h0.x) + __bfloat162float(l0.x);
        float x1 = __bfloat162float(h0.y) + __bfloat162float(l0.y);
        float x2 = __bfloat162float(h1.x) + __bfloat162float(l1.x);
        float x3 = __bfloat162float(h1.y) + __bfloat162float(l1.y);
#pragma unroll
        for (int h = 0; h < 4; h++) {
            float al = a[h][j];
            z[h][0] = fmaf(al, x0, z[h][0]);
            z[h][1] = fmaf(al, x1, z[h][1]);
            z[h][2] = fmaf(al, x2, z[h][2]);
            z[h][3] = fmaf(al, x3, z[h][3]);
        }
    }
#pragma unroll
    for (int h = 0; h < 4; h++) {
        __nv_bfloat162 zh0, zh1, zl0, zl1;
        __nv_bfloat16 a0 = __float2bfloat16(z[h][0]);
        __nv_bfloat16 a1 = __float2bfloat16(z[h][1]);
        __nv_bfloat16 a2 = __float2bfloat16(z[h][2]);
        __nv_bfloat16 a3 = __float2bfloat16(z[h][3]);
        zh0.x = a0; zh0.y = a1; zh1.x = a2; zh1.y = a3;
        zl0.x = __float2bfloat16(z[h][0] - __bfloat162float(a0));
        zl0.y = __float2bfloat16(z[h][1] - __bfloat162float(a1));
        zl1.x = __float2bfloat16(z[h][2] - __bfloat162float(a2));
        zl1.y = __float2bfloat16(z[h][3] - __bfloat162float(a3));
        size_t o = (size_t)n * 512 + h * 128 + lane * 4;
        *(__nv_bfloat162*)&g_Zh[o]     = zh0;
        *(__nv_bfloat162*)&g_Zh[o + 2] = zh1;
        *(__nv_bfloat162*)&g_Zl[o]     = zl0;
        *(__nv_bfloat162*)&g_Zl[o + 2] = zl1;
    }
}

// ---------------- post: residual + LN + split + next-layer es/ed ----------------
__global__ void k_post(const float* __restrict__ y, const float* __restrict__ xin,
                       float* __restrict__ xout, __nv_bfloat16* __restrict__ OAh,
                       __nv_bfloat16* __restrict__ OAl, const float* __restrict__ lg,
                       const float* __restrict__ lb, const float* __restrict__ wsd) {
    int warp = (blockIdx.x * blockDim.x + threadIdx.x) >> 5;
    if (warp >= MPAD) return;
    int lane = threadIdx.x & 31;
    int d0 = lane * 4;
    size_t base = (size_t)warp * HID + d0;
    float4 yv = *(const float4*)&y[base];
    float4 xv = *(const float4*)&xin[base];
    float v[4] = {yv.x + xv.x, yv.y + xv.y, yv.z + xv.z, yv.w + xv.w};
    float s = v[0] + v[1] + v[2] + v[3];
#pragma unroll
    for (int o = 16; o > 0; o >>= 1) s += __shfl_xor_sync(0xffffffffu, s, o);
    float mean = s * (1.f / HID);
    float dv[4] = {v[0] - mean, v[1] - mean, v[2] - mean, v[3] - mean};
    float s2 = dv[0] * dv[0] + dv[1] * dv[1] + dv[2] * dv[2] + dv[3] * dv[3];
#pragma unroll
    for (int o = 16; o > 0; o >>= 1) s2 += __shfl_xor_sync(0xffffffffu, s2, o);
    float r = rsqrtf(s2 * (1.f / HID) + 1e-5f);
    float out[4];
#pragma unroll
    for (int k = 0; k < 4; k++) out[k] = dv[k] * r * lg[d0 + k] + lb[d0 + k];
    float4 o4 = make_float4(out[0], out[1], out[2], out[3]);
    *(float4*)&xout[base] = o4;
    __nv_bfloat16 h0 = __float2bfloat16(out[0]);
    __nv_bfloat16 h1 = __float2bfloat16(out[1]);
    __nv_bfloat16 h2 = __float2bfloat16(out[2]);
    __nv_bfloat16 h3 = __float2bfloat16(out[3]);
    __nv_bfloat162 hp0, hp1, lp0, lp1;
    hp0.x = h0; hp0.y = h1; hp1.x = h2; hp1.y = h3;
    lp0.x = __float2bfloat16(out[0] - __bfloat162float(h0));
    lp0.y = __float2bfloat16(out[1] - __bfloat162float(h1));
    lp1.x = __float2bfloat16(out[2] - __bfloat162float(h2));
    lp1.y = __float2bfloat16(out[3] - __bfloat162float(h3));
    *(__nv_bfloat162*)&OAh[base]     = hp0;
    *(__nv_bfloat162*)&OAh[base + 2] = hp1;
    *(__nv_bfloat162*)&OAl[base]     = lp0;
    *(__nv_bfloat162*)&OAl[base + 2] = lp1;

    if (wsd) {
        float pr[8];
#pragma unroll
        for (int p2 = 0; p2 < 8; p2++) pr[p2] = 0.f;
#pragma unroll
        for (int k = 0; k < 4; k++) {
            const float* w = wsd + (d0 + k) * 8;
#pragma unroll
            for (int p2 = 0; p2 < 8; p2++) pr[p2] = fmaf(out[k], w[p2], pr[p2]);
        }
#pragma unroll
        for (int o = 16; o > 0; o >>= 1)
#pragma unroll
            for (int p2 = 0; p2 < 8; p2++) pr[p2] += __shfl_xor_sync(0xffffffffu, pr[p2], o);
        if (lane == 0) {
#pragma unroll
            for (int h = 0; h < 4; h++) {
                g_es[warp * 4 + h] = pr[h];
                g_ed[warp * 4 + h] = pr[4 + h];
            }
        }
    }
}

// ---------------- edge MLP finish: relu(y + ef@W1c + b1) -> bf16 hi/lo ----------------
__global__ void k_efb(const float* __restrict__ y, const float* __restrict__ ef,
                      const float* __restrict__ W1c, const float* __restrict__ b1) {
    int i = blockIdx.x * blockDim.x + threadIdx.x;
    if (i >= MPAD * HID) return;
    int e = i >> 7, c = i & 127;
    float v = b1[c];
    if (e < NEDGE) {
        v += y[i];
        const float* efr = ef + e * EFDIM;
#pragma unroll
        for (int j = 0; j < EFDIM; j++) v = fmaf(efr[j], W1c[j * HID + c], v);
    }
    v = fmaxf(v, 0.f);
    __nv_bfloat16 h = __float2bfloat16(v);
    g_Ah[(size_t)e * HID + c] = h;
    g_Al[(size_t)e * HID + c] = __float2bfloat16(v - __bfloat162float(h));
}

// ---------------- final head: logits = H @ W(128x2) + b2 (H already relu(b1)'d) -------
__global__ void k_out2(const float* __restrict__ H, const float* __restrict__ W,
                       const float* __restrict__ b2, float* __restrict__ out) {
    int gw   = (blockIdx.x * blockDim.x + threadIdx.x) >> 5;
    int lane = threadIdx.x & 31;
    if (gw >= NEDGE) return;
    const float* h = H + (size_t)gw * HID;
    float s0 = 0.f, s1 = 0.f;
    for (int k = lane; k < HID; k += 32) {
        float hv = h[k];
        s0 = fmaf(hv, W[k * 2], s0);
        s1 = fmaf(hv, W[k * 2 + 1], s1);
    }
#pragma unroll
    for (int o = 16; o > 0; o >>= 1) {
        s0 += __shfl_xor_sync(0xffffffffu, s0, o);
        s1 += __shfl_xor_sync(0xffffffffu, s1, o);
    }
    if (lane == 0) {
        out[(size_t)gw * 2]     = s0 + b2[0];
        out[(size_t)gw * 2 + 1] = s1 + b2[1];
    }
}

// ---------------- launch ----------------
extern "C" void kernel_launch(void* const* d_in, const int* in_sizes, int n_in,
                              void* d_out, int out_size) {
    const float* nf    = (const float*)d_in[0];
    const float* ef    = (const float*)d_in[2];
    const float* npW1  = (const float*)d_in[4];
    const float* npb1  = (const float*)d_in[5];
    const float* npW2  = (const float*)d_in[6];
    const float* npb2  = (const float*)d_in[7];
    const float* gatW  = (const float*)d_in[8];
    const float* gatAs = (const float*)d_in[9];
    const float* gatAd = (const float*)d_in[10];
    const float* gatB  = (const float*)d_in[11];
    const float* lnG   = (const float*)d_in[12];
    const float* lnB   = (const float*)d_in[13];
    const float* emW1  = (const float*)d_in[14];
    const float* emb1  = (const float*)d_in[15];
    const float* emW2  = (const float*)d_in[16];
    const float* emb2  = (const float*)d_in[17];
    const float* whW1  = (const float*)d_in[18];
    const float* whb1  = (const float*)d_in[19];
    const float* whW2  = (const float*)d_in[20];
    const float* whb2  = (const float*)d_in[21];

    float* out    = (float*)d_out;
    float* embOut = out + (size_t)NEDGE * 2;

    float *x13, *xA, *xB, *y, *wsd;
    __nv_bfloat16 *Ah, *Al, *Zh, *Zl, *Bh, *Bl;
    cudaGetSymbolAddress((void**)&x13, g_x13);
    cudaGetSymbolAddress((void**)&xA,  g_xA);
    cudaGetSymbolAddress((void**)&xB,  g_xB);
    cudaGetSymbolAddress((void**)&y,   g_y);
    cudaGetSymbolAddress((void**)&wsd, g_wsd);
    cudaGetSymbolAddress((void**)&Ah,  g_Ah);
    cudaGetSymbolAddress((void**)&Al,  g_Al);
    cudaGetSymbolAddress((void**)&Zh,  g_Zh);
    cudaGetSymbolAddress((void**)&Zl,  g_Zl);
    cudaGetSymbolAddress((void**)&Bh,  g_Bh);
    cudaGetSymbolAddress((void**)&Bl,  g_Bl);

    constexpr int SMEM = 4 * 128 * 136 * 2;  // 139264
    auto mmA = k_mm<1, false, false, false, true,  true >;  // nodeMLP2: +b2 -> xA + split
    auto mmB = k_mm<4, false, false, false, true,  false>;  // GAT: Z @ Bstk + gb -> y
    auto mmC = k_mm<2, true,  false, false, true,  false>;  // edge1 (gathered) -> y
    auto mmD = k_mm<1, false, true,  false, true,  true >;  // edge2: +emb2 -> embOut + split
    auto mmE = k_mm<1, false, false, true,  true,  false>;  // head1: +b1, relu -> xA
    cudaFuncSetAttribute(mmA, cudaFuncAttributeMaxDynamicSharedMemorySize, SMEM);
    cudaFuncSetAttribute(mmB, cudaFuncAttributeMaxDynamicSharedMemorySize, SMEM);
    cudaFuncSetAttribute(mmC, cudaFuncAttributeMaxDynamicSharedMemorySize, SMEM);
    cudaFuncSetAttribute(mmD, cudaFuncAttributeMaxDynamicSharedMemorySize, SMEM);
    cudaFuncSetAttribute(mmE, cudaFuncAttributeMaxDynamicSharedMemorySize, SMEM);

    const int WGRID = (MPAD * 32) / 256;   // warp-per-row kernels

    // 1) propagate
    int n13 = NNODES * NF;
    k_copy<<<(n13 + 255) / 256, 256>>>(nf, x13, n13);
    for (int d = DEPTH - 1; d >= 9; d--) {
        int start = (1 << d) - 1, count = 1 << d;
        int tn = count * NF;
        k_prop<<<(tn + 255) / 256, 256>>>(start, count);
    }
    k_prop_top<<<1, 512>>>();

    // 2) folded attention vectors (all layers)
    k_wsd3<<<NL, 512>>>(gatW, gatAs, gatAd);

    // 3) node MLP
    k_mlp1<<<4096, 256>>>(x13, npW1, npb1);                       // H1 -> Ah/Al
    k_splitT<<<(HID * HID + 255) / 256, 256>>>(npW2, Bh, Bl, HID, HID);
    mmA<<<512, 256, SMEM>>>(Ah, Al, Bh, Bl, npb2, xA, MPAD, Ah, Al);
    k_esed<<<WGRID, 256>>>(xA, wsd);                              // layer-0 scores

    // 4) GAT layers
    float* bufs[2] = {xA, xB};
    for (int l = 0; l < NL; l++) {
        float* xi = bufs[l & 1];
        float* xo = bufs[(l + 1) & 1];
        k_splitTg<<<(128 * 512 + 255) / 256, 256>>>(gatW + (size_t)l * HID * 512);
        k_zgat<<<WGRID, 256>>>();
        mmB<<<512, 256, SMEM>>>(Zh, Zl, Bh, Bl, gatB + l * HID, y, MPAD, nullptr, nullptr);
        k_post<<<WGRID, 256>>>(y, xi, xo, Ah, Al, lnG + l * HID, lnB + l * HID,
                               (l + 1 < NL) ? (wsd + (l + 1) * 1024) : nullptr);
    }

    // 5) edge MLP (A gathered from node Ah/Al) + head
    k_splitT<<<(256 * HID + 255) / 256, 256>>>(emW1, Bh, Bl, 256, HID);
    mmC<<<512, 256, SMEM>>>(Ah, Al, Bh, Bl, nullptr, y, MPAD, nullptr, nullptr);
    k_efb<<<(MPAD * HID + 255) / 256, 256>>>(y, ef, emW1 + 256 * HID, emb1);
    k_splitT<<<(HID * HID + 255) / 256, 256>>>(emW2, Bh, Bl, HID, HID);
    mmD<<<512, 256, SMEM>>>(Ah, Al, Bh, Bl, emb2, embOut, NEDGE, Ah, Al);
    k_splitT<<<(HID * HID + 255) / 256, 256>>>(whW1, Bh, Bl, HID, HID);
    mmE<<<512, 256, SMEM>>>(Ah, Al, Bh, Bl, whb1, xA, MPAD, nullptr, nullptr);
    k_out2<<<(NEDGE * 32 + 255) / 256, 256>>>(xA, whW2, whb2, out);
}

// round 8
// speedup vs baseline: 1.4657x; 1.4657x over previous
#include <cuda_runtime.h>
#include <cuda_bf16.h>
#include <mma.h>
#include <cstdint>
#include <math.h>

using namespace nvcuda;

#define NNODES 65535
#define NEDGE  65534
#define NINT   32767
#define MPAD   65536
#define HID    128
#define NF     13
#define NL     3

// ---------------- device-global scratch ----------------
__device__ float g_x13[NINT * NF];                       // internal-node averages only
__device__ float g_xA [MPAD * HID];
__device__ float g_xB [MPAD * HID];
__device__ __align__(16) float g_es0[MPAD * 4];
__device__ __align__(16) float g_ed0[MPAD * 4];
__device__ __align__(16) float g_es1[MPAD * 4];
__device__ __align__(16) float g_ed1[MPAD * 4];
__device__ float g_wsd[NL * HID * 8];
__device__ __align__(16) __nv_bfloat16 g_Ah0[(MPAD + 8) * HID];
__device__ __align__(16) __nv_bfloat16 g_Al0[(MPAD + 8) * HID];
__device__ __align__(16) __nv_bfloat16 g_Ah1[(MPAD + 8) * HID];
__device__ __align__(16) __nv_bfloat16 g_Al1[(MPAD + 8) * HID];
__device__ __align__(16) __nv_bfloat16 g_Bh [512 * HID];
__device__ __align__(16) __nv_bfloat16 g_Bl [512 * HID];

// ---------------- weight splits ----------------
__global__ void k_splitT(const float* __restrict__ W, __nv_bfloat16* __restrict__ bh,
                         __nv_bfloat16* __restrict__ bl, int K, int N) {
    int i = blockIdx.x * blockDim.x + threadIdx.x;
    if (i >= K * N) return;
    int k = i / N, n = i - k * N;
    float v = W[(size_t)k * N + n];
    __nv_bfloat16 h = __float2bfloat16(v);
    bh[(size_t)n * K + k] = h;
    bl[(size_t)n * K + k] = __float2bfloat16(v - __bfloat162float(h));
}
// GAT stacked: B[d][h*128+k] = W[k][h*128+d] * 0.25
__global__ void k_splitTg(const float* __restrict__ W) {
    int i = blockIdx.x * blockDim.x + threadIdx.x;
    if (i >= 128 * 512) return;
    int d = i >> 9, kk = i & 511;
    int h = kk >> 7, k = kk & 127;
    float v = W[(size_t)k * 512 + h * 128 + d] * 0.25f;
    __nv_bfloat16 hh = __float2bfloat16(v);
    g_Bh[(size_t)d * 512 + kk] = hh;
    g_Bl[(size_t)d * 512 + kk] = __float2bfloat16(v - __bfloat162float(hh));
}

// ---------------- propagate (2 kernels) ----------------
__global__ void k_prop1(const float* __restrict__ nf, float* __restrict__ x13) {
    __shared__ float bufA[64 * NF], bufB[32 * NF];
    int m = 511 + blockIdx.x;
    int tid = threadIdx.x;
    size_t lbase = (size_t)(64 * m + 63) * NF;
    for (int i = tid; i < 64 * NF; i += 256) bufA[i] = nf[lbase + i];
    __syncthreads();
    float* cur = bufA; float* nxt = bufB;
    int cnt = 32;
#pragma unroll
    for (int s = 1; s <= 6; s++) {
        int start = m * cnt + (cnt - 1);
        for (int i = tid; i < cnt * NF; i += 256) {
            int r = i / NF, f = i - r * NF;
            float v = 0.5f * (cur[(2 * r) * NF + f] + cur[(2 * r + 1) * NF + f]);
            nxt[i] = v;
            x13[(size_t)(start + r) * NF + f] = v;
        }
        __syncthreads();
        float* t = cur; cur = nxt; nxt = t;
        cnt >>= 1;
    }
}
__global__ void k_prop2(float* __restrict__ x13) {
    extern __shared__ float buf[];   // 1023*13 floats
    int tid = threadIdx.x;
    for (int i = tid; i < 512 * NF; i += 512) buf[511 * NF + i] = x13[511 * NF + i];
    __syncthreads();
    for (int d = 8; d >= 0; d--) {
        int start = (1 << d) - 1, cnt = 1 << d;
        for (int i = tid; i < cnt * NF; i += 512) {
            int r = i / NF, f = i - r * NF;
            int n = start + r;
            buf[n * NF + f] = 0.5f * (buf[(2 * n + 1) * NF + f] + buf[(2 * n + 2) * NF + f]);
        }
        __syncthreads();
    }
    for (int i = tid; i < 511 * NF; i += 512) x13[i] = buf[i];
}

// ---------------- node MLP layer 1 -> split pair1 ----------------
__global__ void k_mlp1(const float* __restrict__ nf, const float* __restrict__ x13,
                       const float* __restrict__ W1, const float* __restrict__ b1) {
    __shared__ float sW[NF * HID];
    __shared__ float srow[2][NF];
    int tid = threadIdx.x;
    for (int i = tid; i < NF * HID; i += 256) sW[i] = W1[i];
    for (int n0 = blockIdx.x * 2; n0 < MPAD; n0 += gridDim.x * 2) {
        __syncthreads();
        if (tid < 2 * NF) {
            int rr = tid / NF, f = tid - rr * NF;
            int nn = n0 + rr;
            float v = 0.f;
            if (nn < NINT)        v = x13[(size_t)nn * NF + f];
            else if (nn < NNODES) v = nf[(size_t)nn * NF + f];
            srow[rr][f] = v;
        }
        __syncthreads();
        int half = tid >> 7, c = tid & 127;
        int n = n0 + half;
        float acc = b1[c];
#pragma unroll
        for (int k = 0; k < NF; k++) acc = fmaf(srow[half][k], sW[k * HID + c], acc);
        acc = fmaxf(acc, 0.f);
        __nv_bfloat16 h = __float2bfloat16(acc);
        g_Ah1[(size_t)n * HID + c] = h;
        g_Al1[(size_t)n * HID + c] = __float2bfloat16(acc - __bfloat162float(h));
    }
}

// ---------------- folded attention vectors ----------------
__global__ void k_wsd3(const float* __restrict__ W, const float* __restrict__ as,
                       const float* __restrict__ ad) {
    int l = blockIdx.x;
    int tid = threadIdx.x;           // 512
    int k = tid >> 2, h = tid & 3;
    const float* wr = W + (size_t)l * HID * 512 + (size_t)k * 512 + h * 128;
    const float* av = as + l * 512 + h * 128;
    const float* dv = ad + l * 512 + h * 128;
    float s = 0.f, d2 = 0.f;
    for (int dd = 0; dd < 128; dd++) {
        float w = wr[dd];
        s  = fmaf(w, av[dd], s);
        d2 = fmaf(w, dv[dd], d2);
    }
    g_wsd[l * 1024 + k * 8 + h]     = s;
    g_wsd[l * 1024 + k * 8 + 4 + h] = d2;
}

// =================== fused WMMA bf16x3 GEMM ===================
// 128x128 tile, K = KC*128. STAGE: 0 normal rows, 1 edge gather, 2 attention aggregate.
// EPI: 0 ATTN(bias+write x+split+scores)  1 GAT(bias+residual+LN+split[+scores])
//      2 EF(bias+ef@W1c+relu+split)  3 BIASO(bias+guarded C+split)  4 HEAD(bias+relu+logits)
template <int KC, int STAGE, int EPI, int WSD>
__global__ void __launch_bounds__(256, 1)
k_mm(const __nv_bfloat16* __restrict__ Ah, const __nv_bfloat16* __restrict__ Al,
     const __nv_bfloat16* __restrict__ Bh, const __nv_bfloat16* __restrict__ Bl,
     const float* __restrict__ bias, const float* __restrict__ xin,
     float* __restrict__ xout, __nv_bfloat16* __restrict__ OAh, __nv_bfloat16* __restrict__ OAl,
     const float* __restrict__ esIn, const float* __restrict__ edIn,
     float* __restrict__ esOut, float* __restrict__ edOut,
     const float* __restrict__ wsd, const float* __restrict__ lg, const float* __restrict__ lb,
     const float* __restrict__ ef, const float* __restrict__ W1c,
     const float* __restrict__ W2, const float* __restrict__ b2, float* __restrict__ lout) {
    extern __shared__ char smem[];
    __nv_bfloat16* sAh = (__nv_bfloat16*)smem;
    __nv_bfloat16* sAl = sAh + 128 * 136;
    __nv_bfloat16* sBh = sAh + 2 * 128 * 136;
    __nv_bfloat16* sBl = sBh + 128 * 136;
    float4* salpha = (float4*)(smem + 139264);               // 128*4 float4 = 8KB
    float*  rs1    = (float*)(smem + 139264 + 8192);         // 256 floats
    float*  rs2    = rs1 + 256;

    const int tid = threadIdx.x;
    const int wid = tid >> 5;
    const int rowBase = blockIdx.x * 128;
    const int wm = wid & 3, wn = wid >> 2;
    const int row_off = wm * 32, col_off = wn * 64;

    // ---- alpha precompute (attention staging) ----
    if (STAGE == 2 && tid < 128) {
        int n = rowBase + tid;
        bool vp = n > 0;
        int p  = vp ? (n - 1) >> 1 : 0;
        int c1 = 2 * n + 1;
        bool vc = c1 < NNODES;
        int ca = vc ? c1 : 0, cb = vc ? c1 + 1 : 0;
        float4 e4[4];
        e4[0] = ((const float4*)esIn)[n];
        e4[1] = ((const float4*)esIn)[p];
        e4[2] = ((const float4*)esIn)[ca];
        e4[3] = ((const float4*)esIn)[cb];
        float4 dD = ((const float4*)edIn)[n];
        float esv[4][4], edv[4] = {dD.x, dD.y, dD.z, dD.w};
#pragma unroll
        for (int j = 0; j < 4; j++) { esv[j][0]=e4[j].x; esv[j][1]=e4[j].y; esv[j][2]=e4[j].z; esv[j][3]=e4[j].w; }
        bool val[4] = {true, vp, vc, vc};
#pragma unroll
        for (int h = 0; h < 4; h++) {
            float e[4], m = -1e30f;
#pragma unroll
            for (int j = 0; j < 4; j++) {
                float s = esv[j][h] + edv[h];
                s = (s >= 0.f) ? s : 0.2f * s;
                e[j] = s;
                if (val[j]) m = fmaxf(m, s);
            }
            float sum = 0.f;
#pragma unroll
            for (int j = 0; j < 4; j++) { e[j] = val[j] ? expf(e[j] - m) : 0.f; sum += e[j]; }
            float inv = 1.f / sum;
            salpha[tid * 4 + h] = make_float4(e[0]*inv, e[1]*inv, e[2]*inv, e[3]*inv);
        }
    }
    if (STAGE == 2) __syncthreads();

    wmma::fragment<wmma::accumulator, 16, 16, 16, float> acc[2][4];
#pragma unroll
    for (int i = 0; i < 2; i++)
#pragma unroll
        for (int j = 0; j < 4; j++) wmma::fill_fragment(acc[i][j], 0.0f);

    const uint4* gAh = (const uint4*)Ah;
    const uint4* gAl = (const uint4*)Al;
    const uint4* gBh = (const uint4*)Bh;
    const uint4* gBl = (const uint4*)Bl;

#pragma unroll
    for (int c = 0; c < KC; c++) {
        // ---- stage A ----
        for (int id = tid; id < 128 * 16; id += 256) {
            int r = id >> 4, q = id & 15;
            if (STAGE == 0) {
                size_t g = (size_t)(rowBase + r) * (KC * 16) + c * 16 + q;
                *(uint4*)&sAh[r * 136 + q * 8] = gAh[g];
                *(uint4*)&sAl[r * 136 + q * 8] = gAl[g];
            } else if (STAGE == 1) {
                int e = rowBase + r;
                size_t row = (c == 0) ? (size_t)(e >> 1) : (size_t)(e + 1);
                *(uint4*)&sAh[r * 136 + q * 8] = gAh[row * 16 + q];
                *(uint4*)&sAl[r * 136 + q * 8] = gAl[row * 16 + q];
            } else {
                int n = rowBase + r;
                int p  = (n > 0) ? (n - 1) >> 1 : 0;
                int c1 = 2 * n + 1;
                bool vc = c1 < NNODES;
                int nb[4] = {n, p, vc ? c1 : 0, vc ? c1 + 1 : 0};
                float4 af = salpha[r * 4 + c];
                float aj[4] = {af.x, af.y, af.z, af.w};
                float z[8] = {0,0,0,0,0,0,0,0};
#pragma unroll
                for (int j = 0; j < 4; j++) {
                    uint4 hv = gAh[(size_t)nb[j] * 16 + q];
                    uint4 lv = gAl[(size_t)nb[j] * 16 + q];
                    const __nv_bfloat162* hp = (const __nv_bfloat162*)&hv;
                    const __nv_bfloat162* lp = (const __nv_bfloat162*)&lv;
                    float a = aj[j];
#pragma unroll
                    for (int u = 0; u < 4; u++) {
                        float2 fh = __bfloat1622float2(hp[u]);
                        float2 fl = __bfloat1622float2(lp[u]);
                        z[2*u]   = fmaf(a, fh.x + fl.x, z[2*u]);
                        z[2*u+1] = fmaf(a, fh.y + fl.y, z[2*u+1]);
                    }
                }
                union { uint4 v; __nv_bfloat162 b[4]; } oh, ol;
#pragma unroll
                for (int u = 0; u < 4; u++) {
                    __nv_bfloat162 h2 = __float22bfloat162_rn(make_float2(z[2*u], z[2*u+1]));
                    float2 fh = __bfloat1622float2(h2);
                    __nv_bfloat162 l2 = __float22bfloat162_rn(make_float2(z[2*u] - fh.x, z[2*u+1] - fh.y));
                    oh.b[u] = h2; ol.b[u] = l2;
                }
                *(uint4*)&sAh[r * 136 + q * 8] = oh.v;
                *(uint4*)&sAl[r * 136 + q * 8] = ol.v;
            }
        }
        // ---- stage B ----
        for (int id = tid; id < 128 * 16; id += 256) {
            int r = id >> 4, q = id & 15;
            size_t g = (size_t)r * (KC * 16) + c * 16 + q;
            *(uint4*)&sBh[r * 136 + q * 8] = gBh[g];
            *(uint4*)&sBl[r * 136 + q * 8] = gBl[g];
        }
        __syncthreads();

#pragma unroll
        for (int ks = 0; ks < 8; ks++) {
            wmma::fragment<wmma::matrix_a, 16, 16, 16, __nv_bfloat16, wmma::row_major> ah[2], al[2];
            wmma::fragment<wmma::matrix_b, 16, 16, 16, __nv_bfloat16, wmma::col_major> bh[4], bl[4];
#pragma unroll
            for (int i = 0; i < 2; i++) {
                wmma::load_matrix_sync(ah[i], sAh + (row_off + i * 16) * 136 + ks * 16, 136);
                wmma::load_matrix_sync(al[i], sAl + (row_off + i * 16) * 136 + ks * 16, 136);
            }
#pragma unroll
            for (int j = 0; j < 4; j++) {
                wmma::load_matrix_sync(bh[j], sBh + (col_off + j * 16) * 136 + ks * 16, 136);
                wmma::load_matrix_sync(bl[j], sBl + (col_off + j * 16) * 136 + ks * 16, 136);
            }
#pragma unroll
            for (int i = 0; i < 2; i++)
#pragma unroll
                for (int j = 0; j < 4; j++) {
                    wmma::mma_sync(acc[i][j], ah[i], bh[j], acc[i][j]);
                    wmma::mma_sync(acc[i][j], ah[i], bl[j], acc[i][j]);
                    wmma::mma_sync(acc[i][j], al[i], bh[j], acc[i][j]);
                }
        }
        __syncthreads();
    }

    // ---- epilogue ----
    float* stage = (float*)smem;     // 128 x 132
#pragma unroll
    for (int i = 0; i < 2; i++)
#pragma unroll
        for (int j = 0; j < 4; j++)
            wmma::store_matrix_sync(stage + (row_off + i * 16) * 132 + col_off + j * 16,
                                    acc[i][j], 132, wmma::mem_row_major);
    __syncthreads();

    // phase A: bias / residual / relu, write back to stage; GAT row sums
    for (int id = tid; id < 128 * 64; id += 256) {
        int r = id >> 6, c2 = (id & 63) * 2;
        int row = rowBase + r;
        float v0 = stage[r * 132 + c2]     + bias[c2];
        float v1 = stage[r * 132 + c2 + 1] + bias[c2 + 1];
        if (EPI == 1) {
            float2 xv = *(const float2*)&xin[(size_t)row * HID + c2];
            v0 += xv.x; v1 += xv.y;
        }
        if (EPI == 2) {
            if (row < NEDGE) {
                float4 e4 = ((const float4*)ef)[row];
                v0 += e4.x * W1c[c2]       + e4.y * W1c[128 + c2]
                    + e4.z * W1c[256 + c2] + e4.w * W1c[384 + c2];
                v1 += e4.x * W1c[c2 + 1]       + e4.y * W1c[128 + c2 + 1]
                    + e4.z * W1c[256 + c2 + 1] + e4.w * W1c[384 + c2 + 1];
            }
            v0 = fmaxf(v0, 0.f); v1 = fmaxf(v1, 0.f);
        }
        if (EPI == 4) { v0 = fmaxf(v0, 0.f); v1 = fmaxf(v1, 0.f); }
        stage[r * 132 + c2]     = v0;
        stage[r * 132 + c2 + 1] = v1;
        if (EPI == 1) {
            float s1 = v0 + v1, s2 = v0 * v0 + v1 * v1;
#pragma unroll
            for (int o = 16; o > 0; o >>= 1) {
                s1 += __shfl_xor_sync(0xffffffffu, s1, o);
                s2 += __shfl_xor_sync(0xffffffffu, s2, o);
            }
            if ((tid & 31) == 0) {
                int hf = (id >> 5) & 1;
                rs1[r * 2 + hf] = s1;
                rs2[r * 2 + hf] = s2;
            }
        }
    }
    __syncthreads();

    // phase B: LN / writes
    for (int id = tid; id < 128 * 64; id += 256) {
        int r = id >> 6, c2 = (id & 63) * 2;
        int row = rowBase + r;
        float v0 = stage[r * 132 + c2];
        float v1 = stage[r * 132 + c2 + 1];
        if (EPI == 1) {
            float mean = (rs1[r * 2] + rs1[r * 2 + 1]) * (1.f / HID);
            float var  = (rs2[r * 2] + rs2[r * 2 + 1]) * (1.f / HID) - mean * mean;
            float rstd = rsqrtf(var + 1e-5f);
            v0 = (v0 - mean) * rstd * lg[c2]     + lb[c2];
            v1 = (v1 - mean) * rstd * lg[c2 + 1] + lb[c2 + 1];
            if (xout) *(float2*)&xout[(size_t)row * HID + c2] = make_float2(v0, v1);
            if (WSD) { stage[r * 132 + c2] = v0; stage[r * 132 + c2 + 1] = v1; }
        }
        if (EPI == 0) *(float2*)&xout[(size_t)row * HID + c2] = make_float2(v0, v1);
        if (EPI == 3 && row < NEDGE) *(float2*)&xout[(size_t)row * HID + c2] = make_float2(v0, v1);
        if (EPI <= 3) {
            __nv_bfloat162 h2 = __float22bfloat162_rn(make_float2(v0, v1));
            float2 fh = __bfloat1622float2(h2);
            __nv_bfloat162 l2 = __float22bfloat162_rn(make_float2(v0 - fh.x, v1 - fh.y));
            *(__nv_bfloat162*)&OAh[(size_t)row * HID + c2] = h2;
            *(__nv_bfloat162*)&OAl[(size_t)row * HID + c2] = l2;
        }
    }

    // phase C: per-row dots (scores / logits)
    constexpr bool PHC = (EPI == 0) || (EPI == 4) || (EPI == 1 && WSD);
    if (PHC) {
        __syncthreads();
        int r = tid >> 1, half = tid & 1;
        int row = rowBase + r;
        if (EPI == 4) {
            float s0 = 0.f, s1 = 0.f;
            for (int c = 0; c < 64; c++) {
                int col = half * 64 + c;
                float v = stage[r * 132 + col];
                s0 = fmaf(v, W2[col * 2], s0);
                s1 = fmaf(v, W2[col * 2 + 1], s1);
            }
            s0 += __shfl_xor_sync(0xffffffffu, s0, 1);
            s1 += __shfl_xor_sync(0xffffffffu, s1, 1);
            if (half == 0 && row < NEDGE) {
                lout[(size_t)row * 2]     = s0 + b2[0];
                lout[(size_t)row * 2 + 1] = s1 + b2[1];
            }
        } else {
            float pr[8] = {0,0,0,0,0,0,0,0};
            for (int c = 0; c < 64; c++) {
                int col = half * 64 + c;
                float v = stage[r * 132 + col];
                const float* w = wsd + col * 8;
#pragma unroll
                for (int p = 0; p < 8; p++) pr[p] = fmaf(v, w[p], pr[p]);
            }
#pragma unroll
            for (int p = 0; p < 8; p++) pr[p] += __shfl_xor_sync(0xffffffffu, pr[p], 1);
            if (half == 0) {
                ((float4*)esOut)[row] = make_float4(pr[0], pr[1], pr[2], pr[3]);
                ((float4*)edOut)[row] = make_float4(pr[4], pr[5], pr[6], pr[7]);
            }
        }
    }
}

// ---------------- launch ----------------
extern "C" void kernel_launch(void* const* d_in, const int* in_sizes, int n_in,
                              void* d_out, int out_size) {
    const float* nf    = (const float*)d_in[0];
    const float* ef    = (const float*)d_in[2];
    const float* npW1  = (const float*)d_in[4];
    const float* npb1  = (const float*)d_in[5];
    const float* npW2  = (const float*)d_in[6];
    const float* npb2  = (const float*)d_in[7];
    const float* gatW  = (const float*)d_in[8];
    const float* gatAs = (const float*)d_in[9];
    const float* gatAd = (const float*)d_in[10];
    const float* gatB  = (const float*)d_in[11];
    const float* lnG   = (const float*)d_in[12];
    const float* lnB   = (const float*)d_in[13];
    const float* emW1  = (const float*)d_in[14];
    const float* emb1  = (const float*)d_in[15];
    const float* emW2  = (const float*)d_in[16];
    const float* emb2  = (const float*)d_in[17];
    const float* whW1  = (const float*)d_in[18];
    const float* whb1  = (const float*)d_in[19];
    const float* whW2  = (const float*)d_in[20];
    const float* whb2  = (const float*)d_in[21];

    float* out    = (float*)d_out;
    float* embOut = out + (size_t)NEDGE * 2;

    float *x13, *xA, *xB, *wsd, *es0, *ed0, *es1, *ed1;
    __nv_bfloat16 *Ah0, *Al0, *Ah1, *Al1, *Bh, *Bl;
    cudaGetSymbolAddress((void**)&x13, g_x13);
    cudaGetSymbolAddress((void**)&xA,  g_xA);
    cudaGetSymbolAddress((void**)&xB,  g_xB);
    cudaGetSymbolAddress((void**)&wsd, g_wsd);
    cudaGetSymbolAddress((void**)&es0, g_es0);
    cudaGetSymbolAddress((void**)&ed0, g_ed0);
    cudaGetSymbolAddress((void**)&es1, g_es1);
    cudaGetSymbolAddress((void**)&ed1, g_ed1);
    cudaGetSymbolAddress((void**)&Ah0, g_Ah0);
    cudaGetSymbolAddress((void**)&Al0, g_Al0);
    cudaGetSymbolAddress((void**)&Ah1, g_Ah1);
    cudaGetSymbolAddress((void**)&Al1, g_Al1);
    cudaGetSymbolAddress((void**)&Bh,  g_Bh);
    cudaGetSymbolAddress((void**)&Bl,  g_Bl);

    constexpr int SMEM = 139264 + 8192 + 2048;   // 149504
    auto mmA  = k_mm<1, 0, 0, 1>;   // node MLP2: +b2 -> xA + split0 + scores(es0)
    auto mmB1 = k_mm<4, 2, 1, 1>;   // GAT with next-scores
    auto mmB0 = k_mm<4, 2, 1, 0>;   // GAT last layer
    auto mmC  = k_mm<2, 1, 2, 0>;   // edge MLP1 gathered + ef + relu -> split
    auto mmD  = k_mm<1, 0, 3, 0>;   // edge MLP2: +emb2 -> embOut + split
    auto mmE  = k_mm<1, 0, 4, 0>;   // head: relu(+b1), logits
    cudaFuncSetAttribute(mmA,  cudaFuncAttributeMaxDynamicSharedMemorySize, SMEM);
    cudaFuncSetAttribute(mmB1, cudaFuncAttributeMaxDynamicSharedMemorySize, SMEM);
    cudaFuncSetAttribute(mmB0, cudaFuncAttributeMaxDynamicSharedMemorySize, SMEM);
    cudaFuncSetAttribute(mmC,  cudaFuncAttributeMaxDynamicSharedMemorySize, SMEM);
    cudaFuncSetAttribute(mmD,  cudaFuncAttributeMaxDynamicSharedMemorySize, SMEM);
    cudaFuncSetAttribute(mmE,  cudaFuncAttributeMaxDynamicSharedMemorySize, SMEM);
    cudaFuncSetAttribute(k_prop2, cudaFuncAttributeMaxDynamicSharedMemorySize, 1023 * NF * 4);

    // 1) propagate (2 launches)
    k_prop1<<<512, 256>>>(nf, x13);
    k_prop2<<<1, 512, 1023 * NF * 4>>>(x13);

    // 2) folded attention vectors
    k_wsd3<<<NL, 512>>>(gatW, gatAs, gatAd);

    // 3) node MLP: H1 -> split pair1; MLP2 -> xA + split pair0 + es0/ed0
    k_mlp1<<<4096, 256>>>(nf, x13, npW1, npb1);
    k_splitT<<<(HID * HID + 255) / 256, 256>>>(npW2, Bh, Bl, HID, HID);
    mmA<<<512, 256, SMEM>>>(Ah1, Al1, Bh, Bl, npb2, nullptr, xA, Ah0, Al0,
                            nullptr, nullptr, es0, ed0, wsd, nullptr, nullptr,
                            nullptr, nullptr, nullptr, nullptr, nullptr);

    // 4) GAT layers (fully fused)
    k_splitTg<<<256, 256>>>(gatW);
    mmB1<<<512, 256, SMEM>>>(Ah0, Al0, Bh, Bl, gatB, xA, xB, Ah1, Al1,
                             es0, ed0, es1, ed1, wsd + 1024, lnG, lnB,
                             nullptr, nullptr, nullptr, nullptr, nullptr);
    k_splitTg<<<256, 256>>>(gatW + (size_t)HID * 512);
    mmB1<<<512, 256, SMEM>>>(Ah1, Al1, Bh, Bl, gatB + HID, xB, xA, Ah0, Al0,
                             es1, ed1, es0, ed0, wsd + 2048, lnG + HID, lnB + HID,
                             nullptr, nullptr, nullptr, nullptr, nullptr);
    k_splitTg<<<256, 256>>>(gatW + (size_t)2 * HID * 512);
    mmB0<<<512, 256, SMEM>>>(Ah0, Al0, Bh, Bl, gatB + 2 * HID, xA, nullptr, Ah1, Al1,
                             es0, ed0, nullptr, nullptr, nullptr, lnG + 2 * HID, lnB + 2 * HID,
                             nullptr, nullptr, nullptr, nullptr, nullptr);

    // 5) edge MLP (gather pair1) + head
    k_splitT<<<(256 * HID + 255) / 256, 256>>>(emW1, Bh, Bl, 256, HID);
    mmC<<<512, 256, SMEM>>>(Ah1, Al1, Bh, Bl, emb1, nullptr, nullptr, Ah0, Al0,
                            nullptr, nullptr, nullptr, nullptr, nullptr, nullptr, nullptr,
                            ef, emW1 + 256 * HID, nullptr, nullptr, nullptr);
    k_splitT<<<(HID * HID + 255) / 256, 256>>>(emW2, Bh, Bl, HID, HID);
    mmD<<<512, 256, SMEM>>>(Ah0, Al0, Bh, Bl, emb2, nullptr, embOut, Ah1, Al1,
                            nullptr, nullptr, nullptr, nullptr, nullptr, nullptr, nullptr,
                            nullptr, nullptr, nullptr, nullptr, nullptr);
    k_splitT<<<(HID * HID + 255) / 256, 256>>>(whW1, Bh, Bl, HID, HID);
    mmE<<<512, 256, SMEM>>>(Ah1, Al1, Bh, Bl, whb1, nullptr, nullptr, nullptr, nullptr,
                            nullptr, nullptr, nullptr, nullptr, nullptr, nullptr, nullptr,
                            nullptr, nullptr, whW2, whb2, out);
}

// round 10
// speedup vs baseline: 1.5418x; 1.0519x over previous
#include <cuda_runtime.h>
#include <cuda_bf16.h>
#include <mma.h>
#include <cstdint>
#include <math.h>

using namespace nvcuda;

#define NNODES 65535
#define NEDGE  65534
#define NINT   32767
#define MPAD   65536
#define HID    128
#define NF     13
#define NL     3

// ---------------- device-global scratch ----------------
__device__ float g_x13[NINT * NF];
__device__ float g_xA [MPAD * HID];
__device__ float g_xB [MPAD * HID];
__device__ __align__(16) float g_es0[MPAD * 4];
__device__ __align__(16) float g_ed0[MPAD * 4];
__device__ __align__(16) float g_es1[MPAD * 4];
__device__ __align__(16) float g_ed1[MPAD * 4];
__device__ __align__(16) float g_alp[MPAD * 16];
__device__ float g_wsd[NL * HID * 8];
__device__ __align__(16) __nv_bfloat16 g_Ah0[(MPAD + 8) * HID];
__device__ __align__(16) __nv_bfloat16 g_Al0[(MPAD + 8) * HID];
__device__ __align__(16) __nv_bfloat16 g_Ah1[(MPAD + 8) * HID];
__device__ __align__(16) __nv_bfloat16 g_Al1[(MPAD + 8) * HID];
__device__ __align__(16) __nv_bfloat16 g_Bh [512 * HID];
__device__ __align__(16) __nv_bfloat16 g_Bl [512 * HID];

// ---------------- weight splits ----------------
__global__ void k_splitT(const float* __restrict__ W, __nv_bfloat16* __restrict__ bh,
                         __nv_bfloat16* __restrict__ bl, int K, int N) {
    int i = blockIdx.x * blockDim.x + threadIdx.x;
    if (i >= K * N) return;
    int k = i / N, n = i - k * N;
    float v = W[(size_t)k * N + n];
    __nv_bfloat16 h = __float2bfloat16(v);
    bh[(size_t)n * K + k] = h;
    bl[(size_t)n * K + k] = __float2bfloat16(v - __bfloat162float(h));
}
// GAT stacked: B[d][h*128+k] = W[k][h*128+d] * 0.25
__global__ void k_splitTg(const float* __restrict__ W) {
    int i = blockIdx.x * blockDim.x + threadIdx.x;
    if (i >= 128 * 512) return;
    int d = i >> 9, kk = i & 511;
    int h = kk >> 7, k = kk & 127;
    float v = W[(size_t)k * 512 + h * 128 + d] * 0.25f;
    __nv_bfloat16 hh = __float2bfloat16(v);
    g_Bh[(size_t)d * 512 + kk] = hh;
    g_Bl[(size_t)d * 512 + kk] = __float2bfloat16(v - __bfloat162float(hh));
}

// ---------------- propagate ----------------
__global__ void k_prop1(const float* __restrict__ nf, float* __restrict__ x13) {
    __shared__ float bufA[64 * NF], bufB[32 * NF];
    int m = 511 + blockIdx.x;
    int tid = threadIdx.x;
    size_t lbase = (size_t)(64 * m + 63) * NF;
    for (int i = tid; i < 64 * NF; i += 256) bufA[i] = nf[lbase + i];
    __syncthreads();
    float* cur = bufA; float* nxt = bufB;
    int cnt = 32;
#pragma unroll
    for (int s = 1; s <= 6; s++) {
        int start = m * cnt + (cnt - 1);
        for (int i = tid; i < cnt * NF; i += 256) {
            int r = i / NF, f = i - r * NF;
            float v = 0.5f * (cur[(2 * r) * NF + f] + cur[(2 * r + 1) * NF + f]);
            nxt[i] = v;
            x13[(size_t)(start + r) * NF + f] = v;
        }
        __syncthreads();
        float* t = cur; cur = nxt; nxt = t;
        cnt >>= 1;
    }
}
__global__ void k_prop2(float* __restrict__ x13) {
    extern __shared__ float buf[];
    int tid = threadIdx.x;
    for (int i = tid; i < 512 * NF; i += 512) buf[511 * NF + i] = x13[511 * NF + i];
    __syncthreads();
    for (int d = 8; d >= 0; d--) {
        int start = (1 << d) - 1, cnt = 1 << d;
        for (int i = tid; i < cnt * NF; i += 512) {
            int r = i / NF, f = i - r * NF;
            int n = start + r;
            buf[n * NF + f] = 0.5f * (buf[(2 * n + 1) * NF + f] + buf[(2 * n + 2) * NF + f]);
        }
        __syncthreads();
    }
    for (int i = tid; i < 511 * NF; i += 512) x13[i] = buf[i];
}

// ---------------- node MLP layer 1 -> split pair1 (thread-per-element) ----------------
__global__ void k_mlp1(const float* __restrict__ nf, const float* __restrict__ x13,
                       const float* __restrict__ W1, const float* __restrict__ b1) {
    int i = blockIdx.x * blockDim.x + threadIdx.x;
    if (i >= MPAD * HID) return;
    int n = i >> 7, c = i & 127;
    float acc = b1[c];
    const float* src = nullptr;
    if (n < NINT)        src = x13 + (size_t)n * NF;
    else if (n < NNODES) src = nf  + (size_t)n * NF;
    if (src) {
#pragma unroll
        for (int k = 0; k < NF; k++) acc = fmaf(__ldg(src + k), W1[k * HID + c], acc);
    }
    acc = fmaxf(acc, 0.f);
    __nv_bfloat16 h = __float2bfloat16(acc);
    g_Ah1[i] = h;
    g_Al1[i] = __float2bfloat16(acc - __bfloat162float(h));
}

// ---------------- folded attention vectors ----------------
__global__ void k_wsd3(const float* __restrict__ W, const float* __restrict__ as,
                       const float* __restrict__ ad) {
    int l = blockIdx.x;
    int tid = threadIdx.x;           // 512
    int k = tid >> 2, h = tid & 3;
    const float* wr = W + (size_t)l * HID * 512 + (size_t)k * 512 + h * 128;
    const float* av = as + l * 512 + h * 128;
    const float* dv = ad + l * 512 + h * 128;
    float s = 0.f, d2 = 0.f;
    for (int dd = 0; dd < 128; dd++) {
        float w = wr[dd];
        s  = fmaf(w, av[dd], s);
        d2 = fmaf(w, dv[dd], d2);
    }
    g_wsd[l * 1024 + k * 8 + h]     = s;
    g_wsd[l * 1024 + k * 8 + 4 + h] = d2;
}

// ---------------- alpha precompute: g_alp[n*4+h] = float4(alpha_j) ----------------
__global__ void k_alpha(const float* __restrict__ es, const float* __restrict__ ed) {
    int n = blockIdx.x * blockDim.x + threadIdx.x;
    if (n >= MPAD) return;
    bool vp = n > 0;
    int p  = vp ? (n - 1) >> 1 : 0;
    int c1 = 2 * n + 1;
    bool vc = c1 < NNODES;
    int ca = vc ? c1 : 0, cb = vc ? c1 + 1 : 0;
    float4 e4[4];
    e4[0] = ((const float4*)es)[n];
    e4[1] = ((const float4*)es)[p];
    e4[2] = ((const float4*)es)[ca];
    e4[3] = ((const float4*)es)[cb];
    float4 dD = ((const float4*)ed)[n];
    float esv[4][4], edv[4] = {dD.x, dD.y, dD.z, dD.w};
#pragma unroll
    for (int j = 0; j < 4; j++) { esv[j][0]=e4[j].x; esv[j][1]=e4[j].y; esv[j][2]=e4[j].z; esv[j][3]=e4[j].w; }
    bool val[4] = {true, vp, vc, vc};
#pragma unroll
    for (int h = 0; h < 4; h++) {
        float e[4], m = -1e30f;
#pragma unroll
        for (int j = 0; j < 4; j++) {
            float s = esv[j][h] + edv[h];
            s = (s >= 0.f) ? s : 0.2f * s;
            e[j] = s;
            if (val[j]) m = fmaxf(m, s);
        }
        float sum = 0.f;
#pragma unroll
        for (int j = 0; j < 4; j++) { e[j] = val[j] ? expf(e[j] - m) : 0.f; sum += e[j]; }
        float inv = 1.f / sum;
        ((float4*)g_alp)[(size_t)n * 4 + h] = make_float4(e[0]*inv, e[1]*inv, e[2]*inv, e[3]*inv);
    }
}

// =================== fused WMMA bf16x3 GEMM, 256x128 tile ===================
// STAGE: 0 plain, 1 edge gather, 2 attention aggregate (alpha from g_alp).
// EPI: 0 ATTN  1 GAT(residual+LN[+scores])  2 EF  3 BIASO(guarded)  4 HEAD(logits)
template <int KC, int STAGE, int EPI, int WSD>
__global__ void __launch_bounds__(256, 1)
k_mm(const __nv_bfloat16* __restrict__ Ah, const __nv_bfloat16* __restrict__ Al,
     const __nv_bfloat16* __restrict__ Bh, const __nv_bfloat16* __restrict__ Bl,
     const float* __restrict__ bias, const float* __restrict__ xin,
     float* __restrict__ xout, __nv_bfloat16* __restrict__ OAh, __nv_bfloat16* __restrict__ OAl,
     float* __restrict__ esOut, float* __restrict__ edOut,
     const float* __restrict__ wsd, const float* __restrict__ lg, const float* __restrict__ lb,
     const float* __restrict__ ef, const float* __restrict__ W1c,
     const float* __restrict__ W2, const float* __restrict__ b2, float* __restrict__ lout) {
    extern __shared__ char smem[];
    __nv_bfloat16* sAh = (__nv_bfloat16*)smem;            // 256*136
    __nv_bfloat16* sAl = sAh + 256 * 136;
    __nv_bfloat16* sBh = sAh + 2 * 256 * 136;             // 128*136
    __nv_bfloat16* sBl = sBh + 128 * 136;
    float* rs1 = (float*)(smem + 208896);                 // 512 floats
    float* rs2 = rs1 + 512;

    const int tid = threadIdx.x;
    const int wid = tid >> 5;
    const int rowBase = blockIdx.x * 256;
    const int row_off = (wid & 3) * 64;
    const int col_off = (wid >> 2) * 64;

    wmma::fragment<wmma::accumulator, 16, 16, 16, float> acc[4][4];
#pragma unroll
    for (int i = 0; i < 4; i++)
#pragma unroll
        for (int j = 0; j < 4; j++) wmma::fill_fragment(acc[i][j], 0.0f);

    const uint4* gAh = (const uint4*)Ah;
    const uint4* gAl = (const uint4*)Al;
    const uint4* gBh = (const uint4*)Bh;
    const uint4* gBl = (const uint4*)Bl;

#pragma unroll
    for (int c = 0; c < KC; c++) {
        // ---- stage A (256 rows x 128 k) ----
        for (int id = tid; id < 256 * 16; id += 256) {
            int r = id >> 4, q = id & 15;
            if (STAGE == 0) {
                size_t g = (size_t)(rowBase + r) * (KC * 16) + c * 16 + q;
                *(uint4*)&sAh[r * 136 + q * 8] = gAh[g];
                *(uint4*)&sAl[r * 136 + q * 8] = gAl[g];
            } else if (STAGE == 1) {
                int e = rowBase + r;
                size_t row = (c == 0) ? (size_t)(e >> 1) : (size_t)(e + 1);
                *(uint4*)&sAh[r * 136 + q * 8] = gAh[row * 16 + q];
                *(uint4*)&sAl[r * 136 + q * 8] = gAl[row * 16 + q];
            } else {
                int n = rowBase + r;
                int p  = (n > 0) ? (n - 1) >> 1 : 0;
                int c1 = 2 * n + 1;
                bool vc = c1 < NNODES;
                int nb[4] = {n, p, vc ? c1 : 0, vc ? c1 + 1 : 0};
                float4 af = ((const float4*)g_alp)[(size_t)n * 4 + c];
                float aj[4] = {af.x, af.y, af.z, af.w};
                float z[8] = {0,0,0,0,0,0,0,0};
#pragma unroll
                for (int j = 0; j < 4; j++) {
                    uint4 hv = gAh[(size_t)nb[j] * 16 + q];
                    uint4 lv = gAl[(size_t)nb[j] * 16 + q];
                    const __nv_bfloat162* hp = (const __nv_bfloat162*)&hv;
                    const __nv_bfloat162* lp = (const __nv_bfloat162*)&lv;
                    float a = aj[j];
#pragma unroll
                    for (int u = 0; u < 4; u++) {
                        float2 fh = __bfloat1622float2(hp[u]);
                        float2 fl = __bfloat1622float2(lp[u]);
                        z[2*u]   = fmaf(a, fh.x + fl.x, z[2*u]);
                        z[2*u+1] = fmaf(a, fh.y + fl.y, z[2*u+1]);
                    }
                }
                union { uint4 v; __nv_bfloat162 b[4]; } oh, ol;
#pragma unroll
                for (int u = 0; u < 4; u++) {
                    __nv_bfloat162 h2 = __float22bfloat162_rn(make_float2(z[2*u], z[2*u+1]));
                    float2 fh = __bfloat1622float2(h2);
                    __nv_bfloat162 l2 = __float22bfloat162_rn(make_float2(z[2*u] - fh.x, z[2*u+1] - fh.y));
                    oh.b[u] = h2; ol.b[u] = l2;
                }
                *(uint4*)&sAh[r * 136 + q * 8] = oh.v;
                *(uint4*)&sAl[r * 136 + q * 8] = ol.v;
            }
        }
        // ---- stage B (128 rows x 128 k) ----
        for (int id = tid; id < 128 * 16; id += 256) {
            int r = id >> 4, q = id & 15;
            size_t g = (size_t)r * (KC * 16) + c * 16 + q;
            *(uint4*)&sBh[r * 136 + q * 8] = gBh[g];
            *(uint4*)&sBl[r * 136 + q * 8] = gBl[g];
        }
        __syncthreads();

#pragma unroll
        for (int ks = 0; ks < 8; ks++) {
            wmma::fragment<wmma::matrix_a, 16, 16, 16, __nv_bfloat16, wmma::row_major> ah[4], al[4];
#pragma unroll
            for (int i = 0; i < 4; i++) {
                wmma::load_matrix_sync(ah[i], sAh + (row_off + i * 16) * 136 + ks * 16, 136);
                wmma::load_matrix_sync(al[i], sAl + (row_off + i * 16) * 136 + ks * 16, 136);
            }
#pragma unroll
            for (int j = 0; j < 4; j++) {
                wmma::fragment<wmma::matrix_b, 16, 16, 16, __nv_bfloat16, wmma::col_major> bh, bl;
                wmma::load_matrix_sync(bh, sBh + (col_off + j * 16) * 136 + ks * 16, 136);
                wmma::load_matrix_sync(bl, sBl + (col_off + j * 16) * 136 + ks * 16, 136);
#pragma unroll
                for (int i = 0; i < 4; i++) {
                    wmma::mma_sync(acc[i][j], ah[i], bh, acc[i][j]);
                    wmma::mma_sync(acc[i][j], ah[i], bl, acc[i][j]);
                    wmma::mma_sync(acc[i][j], al[i], bh, acc[i][j]);
                }
            }
        }
        __syncthreads();
    }

    // ---- epilogue ----
    float* stage = (float*)smem;     // 256 x 132 fp32 = 135168 B
#pragma unroll
    for (int i = 0; i < 4; i++)
#pragma unroll
        for (int j = 0; j < 4; j++)
            wmma::store_matrix_sync(stage + (row_off + i * 16) * 132 + col_off + j * 16,
                                    acc[i][j], 132, wmma::mem_row_major);
    __syncthreads();

    // phase A: bias / residual / relu / ef; GAT row sums
    for (int id = tid; id < 256 * 64; id += 256) {
        int r = id >> 6, c2 = (id & 63) * 2;
        int row = rowBase + r;
        float v0 = stage[r * 132 + c2]     + bias[c2];
        float v1 = stage[r * 132 + c2 + 1] + bias[c2 + 1];
        if (EPI == 1) {
            float2 xv = *(const float2*)&xin[(size_t)row * HID + c2];
            v0 += xv.x; v1 += xv.y;
        }
        if (EPI == 2) {
            if (row < NEDGE) {
                float4 e4 = ((const float4*)ef)[row];
                v0 += e4.x * W1c[c2]       + e4.y * W1c[128 + c2]
                    + e4.z * W1c[256 + c2] + e4.w * W1c[384 + c2];
                v1 += e4.x * W1c[c2 + 1]       + e4.y * W1c[128 + c2 + 1]
                    + e4.z * W1c[256 + c2 + 1] + e4.w * W1c[384 + c2 + 1];
            }
            v0 = fmaxf(v0, 0.f); v1 = fmaxf(v1, 0.f);
        }
        if (EPI == 4) { v0 = fmaxf(v0, 0.f); v1 = fmaxf(v1, 0.f); }
        stage[r * 132 + c2]     = v0;
        stage[r * 132 + c2 + 1] = v1;
        if (EPI == 1) {
            float s1 = v0 + v1, s2 = v0 * v0 + v1 * v1;
#pragma unroll
            for (int o = 16; o > 0; o >>= 1) {
                s1 += __shfl_xor_sync(0xffffffffu, s1, o);
                s2 += __shfl_xor_sync(0xffffffffu, s2, o);
            }
            if ((tid & 31) == 0) {
                int hf = (id >> 5) & 1;
                rs1[r * 2 + hf] = s1;
                rs2[r * 2 + hf] = s2;
            }
        }
    }
    __syncthreads();

    // phase B: LN / writes / splits
    for (int id = tid; id < 256 * 64; id += 256) {
        int r = id >> 6, c2 = (id & 63) * 2;
        int row = rowBase + r;
        float v0 = stage[r * 132 + c2];
        float v1 = stage[r * 132 + c2 + 1];
        if (EPI == 1) {
            float mean = (rs1[r * 2] + rs1[r * 2 + 1]) * (1.f / HID);
            float var  = (rs2[r * 2] + rs2[r * 2 + 1]) * (1.f / HID) - mean * mean;
            float rstd = rsqrtf(var + 1e-5f);
            v0 = (v0 - mean) * rstd * lg[c2]     + lb[c2];
            v1 = (v1 - mean) * rstd * lg[c2 + 1] + lb[c2 + 1];
            if (xout) *(float2*)&xout[(size_t)row * HID + c2] = make_float2(v0, v1);
            if (WSD) { stage[r * 132 + c2] = v0; stage[r * 132 + c2 + 1] = v1; }
        }
        if (EPI == 0) *(float2*)&xout[(size_t)row * HID + c2] = make_float2(v0, v1);
        if (EPI == 3 && row < NEDGE) *(float2*)&xout[(size_t)row * HID + c2] = make_float2(v0, v1);
        if (EPI <= 3) {
            __nv_bfloat162 h2 = __float22bfloat162_rn(make_float2(v0, v1));
            float2 fh = __bfloat1622float2(h2);
            __nv_bfloat162 l2 = __float22bfloat162_rn(make_float2(v0 - fh.x, v1 - fh.y));
            *(__nv_bfloat162*)&OAh[(size_t)row * HID + c2] = h2;
            *(__nv_bfloat162*)&OAl[(size_t)row * HID + c2] = l2;
        }
    }

    // phase C: per-row dots (scores / logits), 2 rounds of 128 rows
    constexpr bool PHC = (EPI == 0) || (EPI == 4) || (EPI == 1 && WSD);
    if (PHC) {
        __syncthreads();
#pragma unroll
        for (int r0 = 0; r0 < 256; r0 += 128) {
            int r = r0 + (tid >> 1), half = tid & 1;
            int row = rowBase + r;
            if (EPI == 4) {
                float s0 = 0.f, s1 = 0.f;
                for (int c = 0; c < 64; c++) {
                    int col = half * 64 + c;
                    float v = stage[r * 132 + col];
                    s0 = fmaf(v, W2[col * 2], s0);
                    s1 = fmaf(v, W2[col * 2 + 1], s1);
                }
                s0 += __shfl_xor_sync(0xffffffffu, s0, 1);
                s1 += __shfl_xor_sync(0xffffffffu, s1, 1);
                if (half == 0 && row < NEDGE) {
                    lout[(size_t)row * 2]     = s0 + b2[0];
                    lout[(size_t)row * 2 + 1] = s1 + b2[1];
                }
            } else {
                float pr[8] = {0,0,0,0,0,0,0,0};
                for (int c = 0; c < 64; c++) {
                    int col = half * 64 + c;
                    float v = stage[r * 132 + col];
                    const float* w = wsd + col * 8;
#pragma unroll
                    for (int p = 0; p < 8; p++) pr[p] = fmaf(v, w[p], pr[p]);
                }
#pragma unroll
                for (int p = 0; p < 8; p++) pr[p] += __shfl_xor_sync(0xffffffffu, pr[p], 1);
                if (half == 0) {
                    ((float4*)esOut)[row] = make_float4(pr[0], pr[1], pr[2], pr[3]);
                    ((float4*)edOut)[row] = make_float4(pr[4], pr[5], pr[6], pr[7]);
                }
            }
        }
    }
}

// ---------------- launch ----------------
extern "C" void kernel_launch(void* const* d_in, const int* in_sizes, int n_in,
                              void* d_out, int out_size) {
    const float* nf    = (const float*)d_in[0];
    const float* ef    = (const float*)d_in[2];
    const float* npW1  = (const float*)d_in[4];
    const float* npb1  = (const float*)d_in[5];
    const float* npW2  = (const float*)d_in[6];
    const float* npb2  = (const float*)d_in[7];
    const float* gatW  = (const float*)d_in[8];
    const float* gatAs = (const float*)d_in[9];
    const float* gatAd = (const float*)d_in[10];
    const float* gatB  = (const float*)d_in[11];
    const float* lnG   = (const float*)d_in[12];
    const float* lnB   = (const float*)d_in[13];
    const float* emW1  = (const float*)d_in[14];
    const float* emb1  = (const float*)d_in[15];
    const float* emW2  = (const float*)d_in[16];
    const float* emb2  = (const float*)d_in[17];
    const float* whW1  = (const float*)d_in[18];
    const float* whb1  = (const float*)d_in[19];
    const float* whW2  = (const float*)d_in[20];
    const float* whb2  = (const float*)d_in[21];

    float* out    = (float*)d_out;
    float* embOut = out + (size_t)NEDGE * 2;

    float *x13, *xA, *xB, *wsd, *es0, *ed0, *es1, *ed1;
    __nv_bfloat16 *Ah0, *Al0, *Ah1, *Al1, *Bh, *Bl;
    cudaGetSymbolAddress((void**)&x13, g_x13);
    cudaGetSymbolAddress((void**)&xA,  g_xA);
    cudaGetSymbolAddress((void**)&xB,  g_xB);
    cudaGetSymbolAddress((void**)&wsd, g_wsd);
    cudaGetSymbolAddress((void**)&es0, g_es0);
    cudaGetSymbolAddress((void**)&ed0, g_ed0);
    cudaGetSymbolAddress((void**)&es1, g_es1);
    cudaGetSymbolAddress((void**)&ed1, g_ed1);
    cudaGetSymbolAddress((void**)&Ah0, g_Ah0);
    cudaGetSymbolAddress((void**)&Al0, g_Al0);
    cudaGetSymbolAddress((void**)&Ah1, g_Ah1);
    cudaGetSymbolAddress((void**)&Al1, g_Al1);
    cudaGetSymbolAddress((void**)&Bh,  g_Bh);
    cudaGetSymbolAddress((void**)&Bl,  g_Bl);

    constexpr int SMEM = 208896 + 4096;   // 212992
    auto mmA  = k_mm<1, 0, 0, 1>;
    auto mmB1 = k_mm<4, 2, 1, 1>;
    auto mmB0 = k_mm<4, 2, 1, 0>;
    auto mmC  = k_mm<2, 1, 2, 0>;
    auto mmD  = k_mm<1, 0, 3, 0>;
    auto mmE  = k_mm<1, 0, 4, 0>;
    cudaFuncSetAttribute(mmA,  cudaFuncAttributeMaxDynamicSharedMemorySize, SMEM);
    cudaFuncSetAttribute(mmB1, cudaFuncAttributeMaxDynamicSharedMemorySize, SMEM);
    cudaFuncSetAttribute(mmB0, cudaFuncAttributeMaxDynamicSharedMemorySize, SMEM);
    cudaFuncSetAttribute(mmC,  cudaFuncAttributeMaxDynamicSharedMemorySize, SMEM);
    cudaFuncSetAttribute(mmD,  cudaFuncAttributeMaxDynamicSharedMemorySize, SMEM);
    cudaFuncSetAttribute(mmE,  cudaFuncAttributeMaxDynamicSharedMemorySize, SMEM);
    cudaFuncSetAttribute(k_prop2, cudaFuncAttributeMaxDynamicSharedMemorySize, 1023 * NF * 4);

    // 1) propagate
    k_prop1<<<512, 256>>>(nf, x13);
    k_prop2<<<1, 512, 1023 * NF * 4>>>(x13);

    // 2) folded attention vectors
    k_wsd3<<<NL, 512>>>(gatW, gatAs, gatAd);

    // 3) node MLP
    k_mlp1<<<(MPAD * HID) / 256, 256>>>(nf, x13, npW1, npb1);
    k_splitT<<<(HID * HID + 255) / 256, 256>>>(npW2, Bh, Bl, HID, HID);
    mmA<<<256, 256, SMEM>>>(Ah1, Al1, Bh, Bl, npb2, nullptr, xA, Ah0, Al0,
                            es0, ed0, wsd, nullptr, nullptr,
                            nullptr, nullptr, nullptr, nullptr, nullptr);

    // 4) GAT layers
    k_alpha<<<MPAD / 256, 256>>>(es0, ed0);
    k_splitTg<<<256, 256>>>(gatW);
    mmB1<<<256, 256, SMEM>>>(Ah0, Al0, Bh, Bl, gatB, xA, xB, Ah1, Al1,
                             es1, ed1, wsd + 1024, lnG, lnB,
                             nullptr, nullptr, nullptr, nullptr, nullptr);
    k_alpha<<<MPAD / 256, 256>>>(es1, ed1);
    k_splitTg<<<256, 256>>>(gatW + (size_t)HID * 512);
    mmB1<<<256, 256, SMEM>>>(Ah1, Al1, Bh, Bl, gatB + HID, xB, xA, Ah0, Al0,
                             es0, ed0, wsd + 2048, lnG + HID, lnB + HID,
                             nullptr, nullptr, nullptr, nullptr, nullptr);
    k_alpha<<<MPAD / 256, 256>>>(es0, ed0);
    k_splitTg<<<256, 256>>>(gatW + (size_t)2 * HID * 512);
    mmB0<<<256, 256, SMEM>>>(Ah0, Al0, Bh, Bl, gatB + 2 * HID, xA, nullptr, Ah1, Al1,
                             nullptr, nullptr, nullptr, lnG + 2 * HID, lnB + 2 * HID,
                             nullptr, nullptr, nullptr, nullptr, nullptr);

    // 5) edge MLP + head
    k_splitT<<<(256 * HID + 255) / 256, 256>>>(emW1, Bh, Bl, 256, HID);
    mmC<<<256, 256, SMEM>>>(Ah1, Al1, Bh, Bl, emb1, nullptr, nullptr, Ah0, Al0,
                            nullptr, nullptr, nullptr, nullptr, nullptr,
                            ef, emW1 + 256 * HID, nullptr, nullptr, nullptr);
    k_splitT<<<(HID * HID + 255) / 256, 256>>>(emW2, Bh, Bl, HID, HID);
    mmD<<<256, 256, SMEM>>>(Ah0, Al0, Bh, Bl, emb2, nullptr, embOut, Ah1, Al1,
                            nullptr, nullptr, nullptr, nullptr, nullptr,
                            nullptr, nullptr, nullptr, nullptr, nullptr);
    k_splitT<<<(HID * HID + 255) / 256, 256>>>(whW1, Bh, Bl, HID, HID);
    mmE<<<256, 256, SMEM>>>(Ah1, Al1, Bh, Bl, whb1, nullptr, nullptr, nullptr, nullptr,
                            nullptr, nullptr, nullptr, nullptr, nullptr,
                            nullptr, nullptr, whW2, whb2, out);
}

// round 11
// speedup vs baseline: 2.0506x; 1.3300x over previous
#include <cuda_runtime.h>
#include <cuda_fp16.h>
#include <mma.h>
#include <cstdint>
#include <math.h>

using namespace nvcuda;

#define NNODES 65535
#define NEDGE  65534
#define NINT   32767
#define MPAD   65536
#define HID    128
#define NF     13
#define NL     3

// ---------------- device-global scratch ----------------
__device__ float g_x13[NINT * NF];
__device__ float g_xA [MPAD * HID];
__device__ float g_xB [MPAD * HID];
__device__ __align__(16) float g_es0[MPAD * 4];
__device__ __align__(16) float g_ed0[MPAD * 4];
__device__ __align__(16) float g_es1[MPAD * 4];
__device__ __align__(16) float g_ed1[MPAD * 4];
__device__ __align__(16) float g_alp[MPAD * 16];
__device__ float g_wsd[NL * HID * 8];
__device__ __align__(16) __half g_Ah0[(MPAD + 8) * HID];   // activations, single fp16
__device__ __align__(16) __half g_Ah1[(MPAD + 8) * HID];
// weights: [hi | lo], dest layout [N][K]
__device__ __align__(16) __half g_Bnp [2 * 128 * 128];
__device__ __align__(16) __half g_Bg0 [2 * 128 * 512];
__device__ __align__(16) __half g_Bg1 [2 * 128 * 512];
__device__ __align__(16) __half g_Bg2 [2 * 128 * 512];
__device__ __align__(16) __half g_Bem1[2 * 128 * 256];
__device__ __align__(16) __half g_Bem2[2 * 128 * 128];
__device__ __align__(16) __half g_Bwh [2 * 128 * 128];

// ---------------- all weight splits in ONE kernel ----------------
__device__ __forceinline__ void splitW(const float* __restrict__ W, __half* __restrict__ D,
                                       int K, int e) {
    int n = e / K, k = e - n * K;
    float v = W[(size_t)k * 128 + n];
    __half h = __float2half_rn(v);
    D[e] = h;
    D[(size_t)K * 128 + e] = __float2half_rn(v - __half2float(h));
}
__global__ void k_wprep(const float* __restrict__ npW2, const float* __restrict__ gatW,
                        const float* __restrict__ emW1, const float* __restrict__ emW2,
                        const float* __restrict__ whW1) {
    int i = blockIdx.x * 256 + threadIdx.x;
    if (i < 16384) { splitW(npW2, g_Bnp, 128, i); return; }
    if (i < 212992) {
        int j = i - 16384;
        int l = j >> 16, e = j & 65535;
        int d = e >> 9, kk = e & 511;
        int h = kk >> 7, k = kk & 127;
        float v = gatW[(size_t)l * 65536 + (size_t)k * 512 + h * 128 + d] * 0.25f;
        __half hh = __float2half_rn(v);
        __half* B = (l == 0) ? g_Bg0 : (l == 1) ? g_Bg1 : g_Bg2;
        B[(size_t)d * 512 + kk] = hh;
        B[65536 + (size_t)d * 512 + kk] = __float2half_rn(v - __half2float(hh));
        return;
    }
    if (i < 245760) { splitW(emW1, g_Bem1, 256, i - 212992); return; }
    if (i < 262144) { splitW(emW2, g_Bem2, 128, i - 245760); return; }
    if (i < 278528) { splitW(whW1, g_Bwh, 128, i - 262144); return; }
}

// ---------------- propagate ----------------
__global__ void k_prop1(const float* __restrict__ nf, float* __restrict__ x13) {
    __shared__ float bufA[64 * NF], bufB[32 * NF];
    int m = 511 + blockIdx.x;
    int tid = threadIdx.x;
    size_t lbase = (size_t)(64 * m + 63) * NF;
    for (int i = tid; i < 64 * NF; i += 256) bufA[i] = nf[lbase + i];
    __syncthreads();
    float* cur = bufA; float* nxt = bufB;
    int cnt = 32;
#pragma unroll
    for (int s = 1; s <= 6; s++) {
        int start = m * cnt + (cnt - 1);
        for (int i = tid; i < cnt * NF; i += 256) {
            int r = i / NF, f = i - r * NF;
            float v = 0.5f * (cur[(2 * r) * NF + f] + cur[(2 * r + 1) * NF + f]);
            nxt[i] = v;
            x13[(size_t)(start + r) * NF + f] = v;
        }
        __syncthreads();
        float* t = cur; cur = nxt; nxt = t;
        cnt >>= 1;
    }
}
__global__ void k_prop2(float* __restrict__ x13) {
    extern __shared__ float buf[];
    int tid = threadIdx.x;
    for (int i = tid; i < 512 * NF; i += 512) buf[511 * NF + i] = x13[511 * NF + i];
    __syncthreads();
    for (int d = 8; d >= 0; d--) {
        int start = (1 << d) - 1, cnt = 1 << d;
        for (int i = tid; i < cnt * NF; i += 512) {
            int r = i / NF, f = i - r * NF;
            int n = start + r;
            buf[n * NF + f] = 0.5f * (buf[(2 * n + 1) * NF + f] + buf[(2 * n + 2) * NF + f]);
        }
        __syncthreads();
    }
    for (int i = tid; i < 511 * NF; i += 512) x13[i] = buf[i];
}

// ---------------- node MLP layer 1 -> fp16 (8 outputs/thread, uint4 store) ----------------
__global__ void k_mlp1(const float* __restrict__ nf, const float* __restrict__ x13,
                       const float* __restrict__ W1, const float* __restrict__ b1) {
    int idx = blockIdx.x * blockDim.x + threadIdx.x;
    if (idx >= MPAD * 16) return;
    int n = idx >> 4, c0 = (idx & 15) << 3;
    float acc[8];
#pragma unroll
    for (int j = 0; j < 8; j++) acc[j] = b1[c0 + j];
    const float* src = nullptr;
    if (n < NINT)        src = x13 + (size_t)n * NF;
    else if (n < NNODES) src = nf  + (size_t)n * NF;
    if (src) {
#pragma unroll
        for (int k = 0; k < NF; k++) {
            float xv = __ldg(src + k);
#pragma unroll
            for (int j = 0; j < 8; j++) acc[j] = fmaf(xv, W1[k * HID + c0 + j], acc[j]);
        }
    }
    union { uint4 v; __half2 h[4]; } o;
#pragma unroll
    for (int u = 0; u < 4; u++)
        o.h[u] = __floats2half2_rn(fmaxf(acc[2 * u], 0.f), fmaxf(acc[2 * u + 1], 0.f));
    *(uint4*)&g_Ah1[(size_t)n * HID + c0] = o.v;
}

// ---------------- folded attention vectors ----------------
__global__ void k_wsd3(const float* __restrict__ W, const float* __restrict__ as,
                       const float* __restrict__ ad) {
    int l = blockIdx.x;
    int tid = threadIdx.x;           // 512
    int k = tid >> 2, h = tid & 3;
    const float* wr = W + (size_t)l * HID * 512 + (size_t)k * 512 + h * 128;
    const float* av = as + l * 512 + h * 128;
    const float* dv = ad + l * 512 + h * 128;
    float s = 0.f, d2 = 0.f;
    for (int dd = 0; dd < 128; dd++) {
        float w = wr[dd];
        s  = fmaf(w, av[dd], s);
        d2 = fmaf(w, dv[dd], d2);
    }
    g_wsd[l * 1024 + k * 8 + h]     = s;
    g_wsd[l * 1024 + k * 8 + 4 + h] = d2;
}

// ---------------- alpha precompute ----------------
__global__ void k_alpha(const float* __restrict__ es, const float* __restrict__ ed) {
    int n = blockIdx.x * blockDim.x + threadIdx.x;
    if (n >= MPAD) return;
    bool vp = n > 0;
    int p  = vp ? (n - 1) >> 1 : 0;
    int c1 = 2 * n + 1;
    bool vc = c1 < NNODES;
    int ca = vc ? c1 : 0, cb = vc ? c1 + 1 : 0;
    float4 e4[4];
    e4[0] = ((const float4*)es)[n];
    e4[1] = ((const float4*)es)[p];
    e4[2] = ((const float4*)es)[ca];
    e4[3] = ((const float4*)es)[cb];
    float4 dD = ((const float4*)ed)[n];
    float esv[4][4], edv[4] = {dD.x, dD.y, dD.z, dD.w};
#pragma unroll
    for (int j = 0; j < 4; j++) { esv[j][0]=e4[j].x; esv[j][1]=e4[j].y; esv[j][2]=e4[j].z; esv[j][3]=e4[j].w; }
    bool val[4] = {true, vp, vc, vc};
#pragma unroll
    for (int h = 0; h < 4; h++) {
        float e[4], m = -1e30f;
#pragma unroll
        for (int j = 0; j < 4; j++) {
            float s = esv[j][h] + edv[h];
            s = (s >= 0.f) ? s : 0.2f * s;
            e[j] = s;
            if (val[j]) m = fmaxf(m, s);
        }
        float sum = 0.f;
#pragma unroll
        for (int j = 0; j < 4; j++) { e[j] = val[j] ? expf(e[j] - m) : 0.f; sum += e[j]; }
        float inv = 1.f / sum;
        ((float4*)g_alp)[(size_t)n * 4 + h] = make_float4(e[0]*inv, e[1]*inv, e[2]*inv, e[3]*inv);
    }
}

// =================== fused WMMA fp16 2-pass GEMM, 256x128 tile ===================
// A single fp16; B split hi/lo fp16. STAGE: 0 plain, 1 edge gather, 2 attention aggregate.
// EPI: 0 ATTN  1 GAT(residual+LN[+scores])  2 EF  3 BIASO(guarded)  4 HEAD(logits)
template <int KC, int STAGE, int EPI, int WSD>
__global__ void __launch_bounds__(256, 1)
k_mm(const __half* __restrict__ A, const __half* __restrict__ Bh, const __half* __restrict__ Bl,
     const float* __restrict__ bias, const float* __restrict__ xin,
     float* __restrict__ xout, __half* __restrict__ OA,
     float* __restrict__ esOut, float* __restrict__ edOut,
     const float* __restrict__ wsd, const float* __restrict__ lg, const float* __restrict__ lb,
     const float* __restrict__ ef, const float* __restrict__ W1c,
     const float* __restrict__ W2, const float* __restrict__ b2, float* __restrict__ lout) {
    extern __shared__ char smem[];
    __half* sA  = (__half*)smem;                          // 256*136 = 69632B
    __half* sBh = sA + 256 * 136;                         // 128*136 = 34816B
    __half* sBl = sBh + 128 * 136;                        // 34816B   (total 139264)
    float* rs1 = (float*)(smem + 139264);                 // 512 floats
    float* rs2 = rs1 + 512;

    const int tid = threadIdx.x;
    const int wid = tid >> 5;
    const int rowBase = blockIdx.x * 256;
    const int row_off = (wid & 3) * 64;
    const int col_off = (wid >> 2) * 64;

    wmma::fragment<wmma::accumulator, 16, 16, 16, float> acc[4][4];
#pragma unroll
    for (int i = 0; i < 4; i++)
#pragma unroll
        for (int j = 0; j < 4; j++) wmma::fill_fragment(acc[i][j], 0.0f);

    const uint4* gA  = (const uint4*)A;
    const uint4* gBh = (const uint4*)Bh;
    const uint4* gBl = (const uint4*)Bl;

#pragma unroll
    for (int c = 0; c < KC; c++) {
        // ---- stage A (256 rows x 128 k, fp16) ----
        for (int id = tid; id < 256 * 16; id += 256) {
            int r = id >> 4, q = id & 15;
            if (STAGE == 0) {
                size_t g = (size_t)(rowBase + r) * (KC * 16) + c * 16 + q;
                *(uint4*)&sA[r * 136 + q * 8] = gA[g];
            } else if (STAGE == 1) {
                int e = rowBase + r;
                size_t row = (c == 0) ? (size_t)(e >> 1) : (size_t)(e + 1);
                *(uint4*)&sA[r * 136 + q * 8] = gA[row * 16 + q];
            } else {
                int n = rowBase + r;
                int p  = (n > 0) ? (n - 1) >> 1 : 0;
                int c1 = 2 * n + 1;
                bool vc = c1 < NNODES;
                int nb[4] = {n, p, vc ? c1 : 0, vc ? c1 + 1 : 0};
                float4 af = ((const float4*)g_alp)[(size_t)n * 4 + c];
                float aj[4] = {af.x, af.y, af.z, af.w};
                float z[8] = {0,0,0,0,0,0,0,0};
#pragma unroll
                for (int j = 0; j < 4; j++) {
                    uint4 hv = gA[(size_t)nb[j] * 16 + q];
                    const __half2* hp = (const __half2*)&hv;
                    float a = aj[j];
#pragma unroll
                    for (int u = 0; u < 4; u++) {
                        float2 fh = __half22float2(hp[u]);
                        z[2*u]   = fmaf(a, fh.x, z[2*u]);
                        z[2*u+1] = fmaf(a, fh.y, z[2*u+1]);
                    }
                }
                union { uint4 v; __half2 h[4]; } oz;
#pragma unroll
                for (int u = 0; u < 4; u++) oz.h[u] = __floats2half2_rn(z[2*u], z[2*u+1]);
                *(uint4*)&sA[r * 136 + q * 8] = oz.v;
            }
        }
        // ---- stage B hi/lo (128 rows x 128 k) ----
        for (int id = tid; id < 128 * 16; id += 256) {
            int r = id >> 4, q = id & 15;
            size_t g = (size_t)r * (KC * 16) + c * 16 + q;
            *(uint4*)&sBh[r * 136 + q * 8] = gBh[g];
            *(uint4*)&sBl[r * 136 + q * 8] = gBl[g];
        }
        __syncthreads();

#pragma unroll
        for (int ks = 0; ks < 8; ks++) {
            wmma::fragment<wmma::matrix_a, 16, 16, 16, __half, wmma::row_major> ah[4];
#pragma unroll
            for (int i = 0; i < 4; i++)
                wmma::load_matrix_sync(ah[i], sA + (row_off + i * 16) * 136 + ks * 16, 136);
#pragma unroll
            for (int j = 0; j < 4; j++) {
                wmma::fragment<wmma::matrix_b, 16, 16, 16, __half, wmma::col_major> bh, bl;
                wmma::load_matrix_sync(bh, sBh + (col_off + j * 16) * 136 + ks * 16, 136);
                wmma::load_matrix_sync(bl, sBl + (col_off + j * 16) * 136 + ks * 16, 136);
#pragma unroll
                for (int i = 0; i < 4; i++) {
                    wmma::mma_sync(acc[i][j], ah[i], bh, acc[i][j]);
                    wmma::mma_sync(acc[i][j], ah[i], bl, acc[i][j]);
                }
            }
        }
        __syncthreads();
    }

    // ---- epilogue ----
    float* stage = (float*)smem;     // 256 x 132 fp32 = 135168 B (aliases sA/sB)
#pragma unroll
    for (int i = 0; i < 4; i++)
#pragma unroll
        for (int j = 0; j < 4; j++)
            wmma::store_matrix_sync(stage + (row_off + i * 16) * 132 + col_off + j * 16,
                                    acc[i][j], 132, wmma::mem_row_major);
    __syncthreads();

    // phase A: bias / residual / relu / ef; GAT row sums
    for (int id = tid; id < 256 * 64; id += 256) {
        int r = id >> 6, c2 = (id & 63) * 2;
        int row = rowBase + r;
        float v0 = stage[r * 132 + c2]     + bias[c2];
        float v1 = stage[r * 132 + c2 + 1] + bias[c2 + 1];
        if (EPI == 1) {
            float2 xv = *(const float2*)&xin[(size_t)row * HID + c2];
            v0 += xv.x; v1 += xv.y;
        }
        if (EPI == 2) {
            if (row < NEDGE) {
                float4 e4 = ((const float4*)ef)[row];
                v0 += e4.x * W1c[c2]       + e4.y * W1c[128 + c2]
                    + e4.z * W1c[256 + c2] + e4.w * W1c[384 + c2];
                v1 += e4.x * W1c[c2 + 1]       + e4.y * W1c[128 + c2 + 1]
                    + e4.z * W1c[256 + c2 + 1] + e4.w * W1c[384 + c2 + 1];
            }
            v0 = fmaxf(v0, 0.f); v1 = fmaxf(v1, 0.f);
        }
        if (EPI == 4) { v0 = fmaxf(v0, 0.f); v1 = fmaxf(v1, 0.f); }
        stage[r * 132 + c2]     = v0;
        stage[r * 132 + c2 + 1] = v1;
        if (EPI == 1) {
            float s1 = v0 + v1, s2 = v0 * v0 + v1 * v1;
#pragma unroll
            for (int o = 16; o > 0; o >>= 1) {
                s1 += __shfl_xor_sync(0xffffffffu, s1, o);
                s2 += __shfl_xor_sync(0xffffffffu, s2, o);
            }
            if ((tid & 31) == 0) {
                int hf = (id >> 5) & 1;
                rs1[r * 2 + hf] = s1;
                rs2[r * 2 + hf] = s2;
            }
        }
    }
    __syncthreads();

    // phase B: LN / writes / fp16 store
    for (int id = tid; id < 256 * 64; id += 256) {
        int r = id >> 6, c2 = (id & 63) * 2;
        int row = rowBase + r;
        float v0 = stage[r * 132 + c2];
        float v1 = stage[r * 132 + c2 + 1];
        if (EPI == 1) {
            float mean = (rs1[r * 2] + rs1[r * 2 + 1]) * (1.f / HID);
            float var  = (rs2[r * 2] + rs2[r * 2 + 1]) * (1.f / HID) - mean * mean;
            float rstd = rsqrtf(var + 1e-5f);
            v0 = (v0 - mean) * rstd * lg[c2]     + lb[c2];
            v1 = (v1 - mean) * rstd * lg[c2 + 1] + lb[c2 + 1];
            if (xout) *(float2*)&xout[(size_t)row * HID + c2] = make_float2(v0, v1);
            if (WSD) { stage[r * 132 + c2] = v0; stage[r * 132 + c2 + 1] = v1; }
        }
        if (EPI == 0) *(float2*)&xout[(size_t)row * HID + c2] = make_float2(v0, v1);
        if (EPI == 3 && row < NEDGE) *(float2*)&xout[(size_t)row * HID + c2] = make_float2(v0, v1);
        if (EPI <= 3) {
            *(__half2*)&OA[(size_t)row * HID + c2] = __floats2half2_rn(v0, v1);
        }
    }

    // phase C: per-row dots (scores / logits)
    constexpr bool PHC = (EPI == 0) || (EPI == 4) || (EPI == 1 && WSD);
    if (PHC) {
        __syncthreads();
#pragma unroll
        for (int r0 = 0; r0 < 256; r0 += 128) {
            int r = r0 + (tid >> 1), half = tid & 1;
            int row = rowBase + r;
            if (EPI == 4) {
                float s0 = 0.f, s1 = 0.f;
                for (int c = 0; c < 64; c++) {
                    int col = half * 64 + c;
                    float v = stage[r * 132 + col];
                    s0 = fmaf(v, W2[col * 2], s0);
                    s1 = fmaf(v, W2[col * 2 + 1], s1);
                }
                s0 += __shfl_xor_sync(0xffffffffu, s0, 1);
                s1 += __shfl_xor_sync(0xffffffffu, s1, 1);
                if (half == 0 && row < NEDGE) {
                    lout[(size_t)row * 2]     = s0 + b2[0];
                    lout[(size_t)row * 2 + 1] = s1 + b2[1];
                }
            } else {
                float pr[8] = {0,0,0,0,0,0,0,0};
                for (int c = 0; c < 64; c++) {
                    int col = half * 64 + c;
                    float v = stage[r * 132 + col];
                    const float* w = wsd + col * 8;
#pragma unroll
                    for (int p = 0; p < 8; p++) pr[p] = fmaf(v, w[p], pr[p]);
                }
#pragma unroll
                for (int p = 0; p < 8; p++) pr[p] += __shfl_xor_sync(0xffffffffu, pr[p], 1);
                if (half == 0) {
                    ((float4*)esOut)[row] = make_float4(pr[0], pr[1], pr[2], pr[3]);
                    ((float4*)edOut)[row] = make_float4(pr[4], pr[5], pr[6], pr[7]);
                }
            }
        }
    }
}

// ---------------- launch ----------------
extern "C" void kernel_launch(void* const* d_in, const int* in_sizes, int n_in,
                              void* d_out, int out_size) {
    const float* nf    = (const float*)d_in[0];
    const float* ef    = (const float*)d_in[2];
    const float* npW1  = (const float*)d_in[4];
    const float* npb1  = (const float*)d_in[5];
    const float* npW2  = (const float*)d_in[6];
    const float* npb2  = (const float*)d_in[7];
    const float* gatW  = (const float*)d_in[8];
    const float* gatAs = (const float*)d_in[9];
    const float* gatAd = (const float*)d_in[10];
    const float* gatB  = (const float*)d_in[11];
    const float* lnG   = (const float*)d_in[12];
    const float* lnB   = (const float*)d_in[13];
    const float* emW1  = (const float*)d_in[14];
    const float* emb1  = (const float*)d_in[15];
    const float* emW2  = (const float*)d_in[16];
    const float* emb2  = (const float*)d_in[17];
    const float* whW1  = (const float*)d_in[18];
    const float* whb1  = (const float*)d_in[19];
    const float* whW2  = (const float*)d_in[20];
    const float* whb2  = (const float*)d_in[21];

    float* out    = (float*)d_out;
    float* embOut = out + (size_t)NEDGE * 2;

    float *x13, *xA, *xB, *wsd, *es0, *ed0, *es1, *ed1;
    __half *Ah0, *Ah1, *Bnp, *Bg0, *Bg1, *Bg2, *Bem1, *Bem2, *Bwh;
    cudaGetSymbolAddress((void**)&x13, g_x13);
    cudaGetSymbolAddress((void**)&xA,  g_xA);
    cudaGetSymbolAddress((void**)&xB,  g_xB);
    cudaGetSymbolAddress((void**)&wsd, g_wsd);
    cudaGetSymbolAddress((void**)&es0, g_es0);
    cudaGetSymbolAddress((void**)&ed0, g_ed0);
    cudaGetSymbolAddress((void**)&es1, g_es1);
    cudaGetSymbolAddress((void**)&ed1, g_ed1);
    cudaGetSymbolAddress((void**)&Ah0, g_Ah0);
    cudaGetSymbolAddress((void**)&Ah1, g_Ah1);
    cudaGetSymbolAddress((void**)&Bnp, g_Bnp);
    cudaGetSymbolAddress((void**)&Bg0, g_Bg0);
    cudaGetSymbolAddress((void**)&Bg1, g_Bg1);
    cudaGetSymbolAddress((void**)&Bg2, g_Bg2);
    cudaGetSymbolAddress((void**)&Bem1, g_Bem1);
    cudaGetSymbolAddress((void**)&Bem2, g_Bem2);
    cudaGetSymbolAddress((void**)&Bwh, g_Bwh);

    constexpr int SMEM = 139264 + 4096;   // 143360
    auto mmA  = k_mm<1, 0, 0, 1>;
    auto mmB1 = k_mm<4, 2, 1, 1>;
    auto mmB0 = k_mm<4, 2, 1, 0>;
    auto mmC  = k_mm<2, 1, 2, 0>;
    auto mmD  = k_mm<1, 0, 3, 0>;
    auto mmE  = k_mm<1, 0, 4, 0>;
    cudaFuncSetAttribute(mmA,  cudaFuncAttributeMaxDynamicSharedMemorySize, SMEM);
    cudaFuncSetAttribute(mmB1, cudaFuncAttributeMaxDynamicSharedMemorySize, SMEM);
    cudaFuncSetAttribute(mmB0, cudaFuncAttributeMaxDynamicSharedMemorySize, SMEM);
    cudaFuncSetAttribute(mmC,  cudaFuncAttributeMaxDynamicSharedMemorySize, SMEM);
    cudaFuncSetAttribute(mmD,  cudaFuncAttributeMaxDynamicSharedMemorySize, SMEM);
    cudaFuncSetAttribute(mmE,  cudaFuncAttributeMaxDynamicSharedMemorySize, SMEM);
    cudaFuncSetAttribute(k_prop2, cudaFuncAttributeMaxDynamicSharedMemorySize, 1023 * NF * 4);

    // 0) all weight splits upfront (one kernel)
    k_wprep<<<1089, 256>>>(npW2, gatW, emW1, emW2, whW1);
    k_wsd3<<<NL, 512>>>(gatW, gatAs, gatAd);

    // 1) propagate
    k_prop1<<<512, 256>>>(nf, x13);
    k_prop2<<<1, 512, 1023 * NF * 4>>>(x13);

    // 2) node MLP
    k_mlp1<<<(MPAD * 16) / 256, 256>>>(nf, x13, npW1, npb1);
    mmA<<<256, 256, SMEM>>>(Ah1, Bnp, Bnp + 16384, npb2, nullptr, xA, Ah0,
                            es0, ed0, wsd, nullptr, nullptr,
                            nullptr, nullptr, nullptr, nullptr, nullptr);

    // 3) GAT layers
    k_alpha<<<MPAD / 256, 256>>>(es0, ed0);
    mmB1<<<256, 256, SMEM>>>(Ah0, Bg0, Bg0 + 65536, gatB, xA, xB, Ah1,
                             es1, ed1, wsd + 1024, lnG, lnB,
                             nullptr, nullptr, nullptr, nullptr, nullptr);
    k_alpha<<<MPAD / 256, 256>>>(es1, ed1);
    mmB1<<<256, 256, SMEM>>>(Ah1, Bg1, Bg1 + 65536, gatB + HID, xB, xA, Ah0,
                             es0, ed0, wsd + 2048, lnG + HID, lnB + HID,
                             nullptr, nullptr, nullptr, nullptr, nullptr);
    k_alpha<<<MPAD / 256, 256>>>(es0, ed0);
    mmB0<<<256, 256, SMEM>>>(Ah0, Bg2, Bg2 + 65536, gatB + 2 * HID, xA, nullptr, Ah1,
                             nullptr, nullptr, nullptr, lnG + 2 * HID, lnB + 2 * HID,
                             nullptr, nullptr, nullptr, nullptr, nullptr);

    // 4) edge MLP + head
    mmC<<<256, 256, SMEM>>>(Ah1, Bem1, Bem1 + 32768, emb1, nullptr, nullptr, Ah0,
                            nullptr, nullptr, nullptr, nullptr, nullptr,
                            ef, emW1 + 256 * HID, nullptr, nullptr, nullptr);
    mmD<<<256, 256, SMEM>>>(Ah0, Bem2, Bem2 + 16384, emb2, nullptr, embOut, Ah1,
                            nullptr, nullptr, nullptr, nullptr, nullptr,
                            nullptr, nullptr, nullptr, nullptr, nullptr);
    mmE<<<256, 256, SMEM>>>(Ah1, Bwh, Bwh + 16384, whb1, nullptr, nullptr, nullptr,
                            nullptr, nullptr, nullptr, nullptr, nullptr,
                            nullptr, nullptr, whW2, whb2, out);
}

// round 12
// speedup vs baseline: 2.6588x; 1.2966x over previous
#include <cuda_runtime.h>
#include <cuda_fp16.h>
#include <mma.h>
#include <cstdint>
#include <math.h>

using namespace nvcuda;

#define NNODES 65535
#define NEDGE  65534
#define NINT   32767
#define MPAD   65536
#define HID    128
#define NF     13
#define NL     3

// ---------------- device-global scratch ----------------
__device__ float g_x13[NINT * NF];
__device__ float g_xA [MPAD * HID];
__device__ float g_xB [MPAD * HID];
__device__ __align__(16) float g_es0[MPAD * 4];
__device__ __align__(16) float g_ed0[MPAD * 4];
__device__ __align__(16) float g_es1[MPAD * 4];
__device__ __align__(16) float g_ed1[MPAD * 4];
__device__ __align__(16) float g_alp[MPAD * 16];
__device__ float g_wsd[NL * HID * 8];
__device__ __align__(16) __half g_Ah0[(MPAD + 8) * HID];   // activations, single fp16
__device__ __align__(16) __half g_Ah1[(MPAD + 8) * HID];
// weights: [hi | lo], dest layout [N][K]
__device__ __align__(16) __half g_Bnp [2 * 128 * 128];
__device__ __align__(16) __half g_Bg0 [2 * 128 * 512];
__device__ __align__(16) __half g_Bg1 [2 * 128 * 512];
__device__ __align__(16) __half g_Bg2 [2 * 128 * 512];
__device__ __align__(16) __half g_Bem1[2 * 128 * 256];
__device__ __align__(16) __half g_Bem2[2 * 128 * 128];
__device__ __align__(16) __half g_Bwh [2 * 128 * 128];

// ---------------- all weight splits in ONE kernel ----------------
__device__ __forceinline__ void splitW(const float* __restrict__ W, __half* __restrict__ D,
                                       int K, int e) {
    int n = e / K, k = e - n * K;
    float v = W[(size_t)k * 128 + n];
    __half h = __float2half_rn(v);
    D[e] = h;
    D[(size_t)K * 128 + e] = __float2half_rn(v - __half2float(h));
}
__global__ void k_wprep(const float* __restrict__ npW2, const float* __restrict__ gatW,
                        const float* __restrict__ emW1, const float* __restrict__ emW2,
                        const float* __restrict__ whW1) {
    int i = blockIdx.x * 256 + threadIdx.x;
    if (i < 16384) { splitW(npW2, g_Bnp, 128, i); return; }
    if (i < 212992) {
        int j = i - 16384;
        int l = j >> 16, e = j & 65535;
        int d = e >> 9, kk = e & 511;
        int h = kk >> 7, k = kk & 127;
        float v = gatW[(size_t)l * 65536 + (size_t)k * 512 + h * 128 + d] * 0.25f;
        __half hh = __float2half_rn(v);
        __half* B = (l == 0) ? g_Bg0 : (l == 1) ? g_Bg1 : g_Bg2;
        B[(size_t)d * 512 + kk] = hh;
        B[65536 + (size_t)d * 512 + kk] = __float2half_rn(v - __half2float(hh));
        return;
    }
    if (i < 245760) { splitW(emW1, g_Bem1, 256, i - 212992); return; }
    if (i < 262144) { splitW(emW2, g_Bem2, 128, i - 245760); return; }
    if (i < 278528) { splitW(whW1, g_Bwh, 128, i - 262144); return; }
}

// ---------------- propagate ----------------
__global__ void k_prop1(const float* __restrict__ nf, float* __restrict__ x13) {
    __shared__ float bufA[64 * NF], bufB[32 * NF];
    int m = 511 + blockIdx.x;
    int tid = threadIdx.x;
    size_t lbase = (size_t)(64 * m + 63) * NF;
    for (int i = tid; i < 64 * NF; i += 256) bufA[i] = nf[lbase + i];
    __syncthreads();
    float* cur = bufA; float* nxt = bufB;
    int cnt = 32;
#pragma unroll
    for (int s = 1; s <= 6; s++) {
        int start = m * cnt + (cnt - 1);
        for (int i = tid; i < cnt * NF; i += 256) {
            int r = i / NF, f = i - r * NF;
            float v = 0.5f * (cur[(2 * r) * NF + f] + cur[(2 * r + 1) * NF + f]);
            nxt[i] = v;
            x13[(size_t)(start + r) * NF + f] = v;
        }
        __syncthreads();
        float* t = cur; cur = nxt; nxt = t;
        cnt >>= 1;
    }
}
__global__ void k_prop2(float* __restrict__ x13) {
    extern __shared__ float buf[];
    int tid = threadIdx.x;
    for (int i = tid; i < 512 * NF; i += 512) buf[511 * NF + i] = x13[511 * NF + i];
    __syncthreads();
    for (int d = 8; d >= 0; d--) {
        int start = (1 << d) - 1, cnt = 1 << d;
        for (int i = tid; i < cnt * NF; i += 512) {
            int r = i / NF, f = i - r * NF;
            int n = start + r;
            buf[n * NF + f] = 0.5f * (buf[(2 * n + 1) * NF + f] + buf[(2 * n + 2) * NF + f]);
        }
        __syncthreads();
    }
    for (int i = tid; i < 511 * NF; i += 512) x13[i] = buf[i];
}

// ---------------- node MLP layer 1 -> fp16 ----------------
__global__ void k_mlp1(const float* __restrict__ nf, const float* __restrict__ x13,
                       const float* __restrict__ W1, const float* __restrict__ b1) {
    int idx = blockIdx.x * blockDim.x + threadIdx.x;
    if (idx >= MPAD * 16) return;
    int n = idx >> 4, c0 = (idx & 15) << 3;
    float acc[8];
#pragma unroll
    for (int j = 0; j < 8; j++) acc[j] = b1[c0 + j];
    const float* src = nullptr;
    if (n < NINT)        src = x13 + (size_t)n * NF;
    else if (n < NNODES) src = nf  + (size_t)n * NF;
    if (src) {
#pragma unroll
        for (int k = 0; k < NF; k++) {
            float xv = __ldg(src + k);
#pragma unroll
            for (int j = 0; j < 8; j++) acc[j] = fmaf(xv, W1[k * HID + c0 + j], acc[j]);
        }
    }
    union { uint4 v; __half2 h[4]; } o;
#pragma unroll
    for (int u = 0; u < 4; u++)
        o.h[u] = __floats2half2_rn(fmaxf(acc[2 * u], 0.f), fmaxf(acc[2 * u + 1], 0.f));
    *(uint4*)&g_Ah1[(size_t)n * HID + c0] = o.v;
}

// ---------------- folded attention vectors ----------------
__global__ void k_wsd3(const float* __restrict__ W, const float* __restrict__ as,
                       const float* __restrict__ ad) {
    int l = blockIdx.x;
    int tid = threadIdx.x;           // 512
    int k = tid >> 2, h = tid & 3;
    const float* wr = W + (size_t)l * HID * 512 + (size_t)k * 512 + h * 128;
    const float* av = as + l * 512 + h * 128;
    const float* dv = ad + l * 512 + h * 128;
    float s = 0.f, d2 = 0.f;
    for (int dd = 0; dd < 128; dd++) {
        float w = wr[dd];
        s  = fmaf(w, av[dd], s);
        d2 = fmaf(w, dv[dd], d2);
    }
    g_wsd[l * 1024 + k * 8 + h]     = s;
    g_wsd[l * 1024 + k * 8 + 4 + h] = d2;
}

// ---------------- alpha precompute ----------------
__global__ void k_alpha(const float* __restrict__ es, const float* __restrict__ ed) {
    int n = blockIdx.x * blockDim.x + threadIdx.x;
    if (n >= MPAD) return;
    bool vp = n > 0;
    int p  = vp ? (n - 1) >> 1 : 0;
    int c1 = 2 * n + 1;
    bool vc = c1 < NNODES;
    int ca = vc ? c1 : 0, cb = vc ? c1 + 1 : 0;
    float4 e4[4];
    e4[0] = ((const float4*)es)[n];
    e4[1] = ((const float4*)es)[p];
    e4[2] = ((const float4*)es)[ca];
    e4[3] = ((const float4*)es)[cb];
    float4 dD = ((const float4*)ed)[n];
    float esv[4][4], edv[4] = {dD.x, dD.y, dD.z, dD.w};
#pragma unroll
    for (int j = 0; j < 4; j++) { esv[j][0]=e4[j].x; esv[j][1]=e4[j].y; esv[j][2]=e4[j].z; esv[j][3]=e4[j].w; }
    bool val[4] = {true, vp, vc, vc};
#pragma unroll
    for (int h = 0; h < 4; h++) {
        float e[4], m = -1e30f;
#pragma unroll
        for (int j = 0; j < 4; j++) {
            float s = esv[j][h] + edv[h];
            s = (s >= 0.f) ? s : 0.2f * s;
            e[j] = s;
            if (val[j]) m = fmaxf(m, s);
        }
        float sum = 0.f;
#pragma unroll
        for (int j = 0; j < 4; j++) { e[j] = val[j] ? expf(e[j] - m) : 0.f; sum += e[j]; }
        float inv = 1.f / sum;
        ((float4*)g_alp)[(size_t)n * 4 + h] = make_float4(e[0]*inv, e[1]*inv, e[2]*inv, e[3]*inv);
    }
}

// =================== fused WMMA fp16 2-pass GEMM, 128x128 tile, 2 CTAs/SM ===================
// A single fp16; B split hi/lo fp16. STAGE: 0 plain, 1 edge gather, 2 attention aggregate.
// EPI: 0 ATTN  1 GAT(residual+LN[+scores])  2 EF  3 BIASO(guarded)  4 HEAD(logits)
template <int KC, int STAGE, int EPI, int WSD>
__global__ void __launch_bounds__(256, 2)
k_mm(const __half* __restrict__ A, const __half* __restrict__ Bh, const __half* __restrict__ Bl,
     const float* __restrict__ bias, const float* __restrict__ xin,
     float* __restrict__ xout, __half* __restrict__ OA,
     float* __restrict__ esOut, float* __restrict__ edOut,
     const float* __restrict__ wsd, const float* __restrict__ lg, const float* __restrict__ lb,
     const float* __restrict__ ef, const float* __restrict__ W1c,
     const float* __restrict__ W2, const float* __restrict__ b2, float* __restrict__ lout) {
    extern __shared__ char smem[];
    __half* sA  = (__half*)smem;                          // 128*136*2B = 34816
    __half* sBh = sA + 128 * 136;                         // 34816
    __half* sBl = sBh + 128 * 136;                        // 34816  (total 104448)
    float* rs1 = (float*)(smem + 104448);                 // 256 floats
    float* rs2 = rs1 + 256;                               // 256 floats (-> 106496)

    const int tid = threadIdx.x;
    const int wid = tid >> 5;
    const int rowBase = blockIdx.x * 128;
    const int row_off = (wid & 3) * 32;
    const int col_off = (wid >> 2) * 64;

    wmma::fragment<wmma::accumulator, 16, 16, 16, float> acc[2][4];
#pragma unroll
    for (int i = 0; i < 2; i++)
#pragma unroll
        for (int j = 0; j < 4; j++) wmma::fill_fragment(acc[i][j], 0.0f);

    const uint4* gA  = (const uint4*)A;
    const uint4* gBh = (const uint4*)Bh;
    const uint4* gBl = (const uint4*)Bl;

#pragma unroll
    for (int c = 0; c < KC; c++) {
        // ---- stage A (128 rows x 128 k, fp16) ----
        for (int id = tid; id < 128 * 16; id += 256) {
            int r = id >> 4, q = id & 15;
            if (STAGE == 0) {
                size_t g = (size_t)(rowBase + r) * (KC * 16) + c * 16 + q;
                *(uint4*)&sA[r * 136 + q * 8] = gA[g];
            } else if (STAGE == 1) {
                int e = rowBase + r;
                size_t row = (c == 0) ? (size_t)(e >> 1) : (size_t)(e + 1);
                *(uint4*)&sA[r * 136 + q * 8] = gA[row * 16 + q];
            } else {
                int n = rowBase + r;
                int p  = (n > 0) ? (n - 1) >> 1 : 0;
                int c1 = 2 * n + 1;
                bool vc = c1 < NNODES;
                int nb[4] = {n, p, vc ? c1 : 0, vc ? c1 + 1 : 0};
                float4 af = ((const float4*)g_alp)[(size_t)n * 4 + c];
                float aj[4] = {af.x, af.y, af.z, af.w};
                float z[8] = {0,0,0,0,0,0,0,0};
#pragma unroll
                for (int j = 0; j < 4; j++) {
                    uint4 hv = gA[(size_t)nb[j] * 16 + q];
                    const __half2* hp = (const __half2*)&hv;
                    float a = aj[j];
#pragma unroll
                    for (int u = 0; u < 4; u++) {
                        float2 fh = __half22float2(hp[u]);
                        z[2*u]   = fmaf(a, fh.x, z[2*u]);
                        z[2*u+1] = fmaf(a, fh.y, z[2*u+1]);
                    }
                }
                union { uint4 v; __half2 h[4]; } oz;
#pragma unroll
                for (int u = 0; u < 4; u++) oz.h[u] = __floats2half2_rn(z[2*u], z[2*u+1]);
                *(uint4*)&sA[r * 136 + q * 8] = oz.v;
            }
        }
        // ---- stage B hi/lo (128 rows x 128 k) ----
        for (int id = tid; id < 128 * 16; id += 256) {
            int r = id >> 4, q = id & 15;
            size_t g = (size_t)r * (KC * 16) + c * 16 + q;
            *(uint4*)&sBh[r * 136 + q * 8] = gBh[g];
            *(uint4*)&sBl[r * 136 + q * 8] = gBl[g];
        }
        __syncthreads();

#pragma unroll
        for (int ks = 0; ks < 8; ks++) {
            wmma::fragment<wmma::matrix_a, 16, 16, 16, __half, wmma::row_major> ah[2];
#pragma unroll
            for (int i = 0; i < 2; i++)
                wmma::load_matrix_sync(ah[i], sA + (row_off + i * 16) * 136 + ks * 16, 136);
#pragma unroll
            for (int j = 0; j < 4; j++) {
                wmma::fragment<wmma::matrix_b, 16, 16, 16, __half, wmma::col_major> bh, bl;
                wmma::load_matrix_sync(bh, sBh + (col_off + j * 16) * 136 + ks * 16, 136);
                wmma::load_matrix_sync(bl, sBl + (col_off + j * 16) * 136 + ks * 16, 136);
#pragma unroll
                for (int i = 0; i < 2; i++) {
                    wmma::mma_sync(acc[i][j], ah[i], bh, acc[i][j]);
                    wmma::mma_sync(acc[i][j], ah[i], bl, acc[i][j]);
                }
            }
        }
        __syncthreads();
    }

    // ---- epilogue ----
    float* stage = (float*)smem;     // 128 x 132 fp32 = 67584 B (aliases sA/sB)
#pragma unroll
    for (int i = 0; i < 2; i++)
#pragma unroll
        for (int j = 0; j < 4; j++)
            wmma::store_matrix_sync(stage + (row_off + i * 16) * 132 + col_off + j * 16,
                                    acc[i][j], 132, wmma::mem_row_major);
    __syncthreads();

    // phase A: bias / residual / relu / ef; GAT row sums
    for (int id = tid; id < 128 * 64; id += 256) {
        int r = id >> 6, c2 = (id & 63) * 2;
        int row = rowBase + r;
        float v0 = stage[r * 132 + c2]     + bias[c2];
        float v1 = stage[r * 132 + c2 + 1] + bias[c2 + 1];
        if (EPI == 1) {
            float2 xv = *(const float2*)&xin[(size_t)row * HID + c2];
            v0 += xv.x; v1 += xv.y;
        }
        if (EPI == 2) {
            if (row < NEDGE) {
                float4 e4 = ((const float4*)ef)[row];
                v0 += e4.x * W1c[c2]       + e4.y * W1c[128 + c2]
                    + e4.z * W1c[256 + c2] + e4.w * W1c[384 + c2];
                v1 += e4.x * W1c[c2 + 1]       + e4.y * W1c[128 + c2 + 1]
                    + e4.z * W1c[256 + c2 + 1] + e4.w * W1c[384 + c2 + 1];
            }
            v0 = fmaxf(v0, 0.f); v1 = fmaxf(v1, 0.f);
        }
        if (EPI == 4) { v0 = fmaxf(v0, 0.f); v1 = fmaxf(v1, 0.f); }
        stage[r * 132 + c2]     = v0;
        stage[r * 132 + c2 + 1] = v1;
        if (EPI == 1) {
            float s1 = v0 + v1, s2 = v0 * v0 + v1 * v1;
#pragma unroll
            for (int o = 16; o > 0; o >>= 1) {
                s1 += __shfl_xor_sync(0xffffffffu, s1, o);
                s2 += __shfl_xor_sync(0xffffffffu, s2, o);
            }
            if ((tid & 31) == 0) {
                int hf = (id >> 5) & 1;
                rs1[r * 2 + hf] = s1;
                rs2[r * 2 + hf] = s2;
            }
        }
    }
    __syncthreads();

    // phase B: LN / writes / fp16 store
    for (int id = tid; id < 128 * 64; id += 256) {
        int r = id >> 6, c2 = (id & 63) * 2;
        int row = rowBase + r;
        float v0 = stage[r * 132 + c2];
        float v1 = stage[r * 132 + c2 + 1];
        if (EPI == 1) {
            float mean = (rs1[r * 2] + rs1[r * 2 + 1]) * (1.f / HID);
            float var  = (rs2[r * 2] + rs2[r * 2 + 1]) * (1.f / HID) - mean * mean;
            float rstd = rsqrtf(var + 1e-5f);
            v0 = (v0 - mean) * rstd * lg[c2]     + lb[c2];
            v1 = (v1 - mean) * rstd * lg[c2 + 1] + lb[c2 + 1];
            if (xout) *(float2*)&xout[(size_t)row * HID + c2] = make_float2(v0, v1);
            if (WSD) { stage[r * 132 + c2] = v0; stage[r * 132 + c2 + 1] = v1; }
        }
        if (EPI == 0) *(float2*)&xout[(size_t)row * HID + c2] = make_float2(v0, v1);
        if (EPI == 3 && row < NEDGE) *(float2*)&xout[(size_t)row * HID + c2] = make_float2(v0, v1);
        if (EPI <= 3) {
            *(__half2*)&OA[(size_t)row * HID + c2] = __floats2half2_rn(v0, v1);
        }
    }

    // phase C: per-row dots (scores / logits)
    constexpr bool PHC = (EPI == 0) || (EPI == 4) || (EPI == 1 && WSD);
    if (PHC) {
        __syncthreads();
        int r = tid >> 1, half = tid & 1;
        int row = rowBase + r;
        if (EPI == 4) {
            float s0 = 0.f, s1 = 0.f;
            for (int c = 0; c < 64; c++) {
                int col = half * 64 + c;
                float v = stage[r * 132 + col];
                s0 = fmaf(v, W2[col * 2], s0);
                s1 = fmaf(v, W2[col * 2 + 1], s1);
            }
            s0 += __shfl_xor_sync(0xffffffffu, s0, 1);
            s1 += __shfl_xor_sync(0xffffffffu, s1, 1);
            if (half == 0 && row < NEDGE) {
                lout[(size_t)row * 2]     = s0 + b2[0];
                lout[(size_t)row * 2 + 1] = s1 + b2[1];
            }
        } else {
            float pr[8] = {0,0,0,0,0,0,0,0};
            for (int c = 0; c < 64; c++) {
                int col = half * 64 + c;
                float v = stage[r * 132 + col];
                const float* w = wsd + col * 8;
#pragma unroll
                for (int p = 0; p < 8; p++) pr[p] = fmaf(v, w[p], pr[p]);
            }
#pragma unroll
            for (int p = 0; p < 8; p++) pr[p] += __shfl_xor_sync(0xffffffffu, pr[p], 1);
            if (half == 0) {
                ((float4*)esOut)[row] = make_float4(pr[0], pr[1], pr[2], pr[3]);
                ((float4*)edOut)[row] = make_float4(pr[4], pr[5], pr[6], pr[7]);
            }
        }
    }
}

// ---------------- launch ----------------
extern "C" void kernel_launch(void* const* d_in, const int* in_sizes, int n_in,
                              void* d_out, int out_size) {
    const float* nf    = (const float*)d_in[0];
    const float* ef    = (const float*)d_in[2];
    const float* npW1  = (const float*)d_in[4];
    const float* npb1  = (const float*)d_in[5];
    const float* npW2  = (const float*)d_in[6];
    const float* npb2  = (const float*)d_in[7];
    const float* gatW  = (const float*)d_in[8];
    const float* gatAs = (const float*)d_in[9];
    const float* gatAd = (const float*)d_in[10];
    const float* gatB  = (const float*)d_in[11];
    const float* lnG   = (const float*)d_in[12];
    const float* lnB   = (const float*)d_in[13];
    const float* emW1  = (const float*)d_in[14];
    const float* emb1  = (const float*)d_in[15];
    const float* emW2  = (const float*)d_in[16];
    const float* emb2  = (const float*)d_in[17];
    const float* whW1  = (const float*)d_in[18];
    const float* whb1  = (const float*)d_in[19];
    const float* whW2  = (const float*)d_in[20];
    const float* whb2  = (const float*)d_in[21];

    float* out    = (float*)d_out;
    float* embOut = out + (size_t)NEDGE * 2;

    float *x13, *xA, *xB, *wsd, *es0, *ed0, *es1, *ed1;
    __half *Ah0, *Ah1, *Bnp, *Bg0, *Bg1, *Bg2, *Bem1, *Bem2, *Bwh;
    cudaGetSymbolAddress((void**)&x13, g_x13);
    cudaGetSymbolAddress((void**)&xA,  g_xA);
    cudaGetSymbolAddress((void**)&xB,  g_xB);
    cudaGetSymbolAddress((void**)&wsd, g_wsd);
    cudaGetSymbolAddress((void**)&es0, g_es0);
    cudaGetSymbolAddress((void**)&ed0, g_ed0);
    cudaGetSymbolAddress((void**)&es1, g_es1);
    cudaGetSymbolAddress((void**)&ed1, g_ed1);
    cudaGetSymbolAddress((void**)&Ah0, g_Ah0);
    cudaGetSymbolAddress((void**)&Ah1, g_Ah1);
    cudaGetSymbolAddress((void**)&Bnp, g_Bnp);
    cudaGetSymbolAddress((void**)&Bg0, g_Bg0);
    cudaGetSymbolAddress((void**)&Bg1, g_Bg1);
    cudaGetSymbolAddress((void**)&Bg2, g_Bg2);
    cudaGetSymbolAddress((void**)&Bem1, g_Bem1);
    cudaGetSymbolAddress((void**)&Bem2, g_Bem2);
    cudaGetSymbolAddress((void**)&Bwh, g_Bwh);

    constexpr int SMEM = 104448 + 2048;   // 106496 B/CTA -> 2 CTAs/SM
    auto mmA  = k_mm<1, 0, 0, 1>;
    auto mmB1 = k_mm<4, 2, 1, 1>;
    auto mmB0 = k_mm<4, 2, 1, 0>;
    auto mmC  = k_mm<2, 1, 2, 0>;
    auto mmD  = k_mm<1, 0, 3, 0>;
    auto mmE  = k_mm<1, 0, 4, 0>;
    cudaFuncSetAttribute(mmA,  cudaFuncAttributeMaxDynamicSharedMemorySize, SMEM);
    cudaFuncSetAttribute(mmB1, cudaFuncAttributeMaxDynamicSharedMemorySize, SMEM);
    cudaFuncSetAttribute(mmB0, cudaFuncAttributeMaxDynamicSharedMemorySize, SMEM);
    cudaFuncSetAttribute(mmC,  cudaFuncAttributeMaxDynamicSharedMemorySize, SMEM);
    cudaFuncSetAttribute(mmD,  cudaFuncAttributeMaxDynamicSharedMemorySize, SMEM);
    cudaFuncSetAttribute(mmE,  cudaFuncAttributeMaxDynamicSharedMemorySize, SMEM);
    cudaFuncSetAttribute(k_prop2, cudaFuncAttributeMaxDynamicSharedMemorySize, 1023 * NF * 4);

    // 0) all weight splits upfront (one kernel)
    k_wprep<<<1089, 256>>>(npW2, gatW, emW1, emW2, whW1);
    k_wsd3<<<NL, 512>>>(gatW, gatAs, gatAd);

    // 1) propagate
    k_prop1<<<512, 256>>>(nf, x13);
    k_prop2<<<1, 512, 1023 * NF * 4>>>(x13);

    // 2) node MLP
    k_mlp1<<<(MPAD * 16) / 256, 256>>>(nf, x13, npW1, npb1);
    mmA<<<512, 256, SMEM>>>(Ah1, Bnp, Bnp + 16384, npb2, nullptr, xA, Ah0,
                            es0, ed0, wsd, nullptr, nullptr,
                            nullptr, nullptr, nullptr, nullptr, nullptr);

    // 3) GAT layers
    k_alpha<<<MPAD / 256, 256>>>(es0, ed0);
    mmB1<<<512, 256, SMEM>>>(Ah0, Bg0, Bg0 + 65536, gatB, xA, xB, Ah1,
                             es1, ed1, wsd + 1024, lnG, lnB,
                             nullptr, nullptr, nullptr, nullptr, nullptr);
    k_alpha<<<MPAD / 256, 256>>>(es1, ed1);
    mmB1<<<512, 256, SMEM>>>(Ah1, Bg1, Bg1 + 65536, gatB + HID, xB, xA, Ah0,
                             es0, ed0, wsd + 2048, lnG + HID, lnB + HID,
                             nullptr, nullptr, nullptr, nullptr, nullptr);
    k_alpha<<<MPAD / 256, 256>>>(es0, ed0);
    mmB0<<<512, 256, SMEM>>>(Ah0, Bg2, Bg2 + 65536, gatB + 2 * HID, xA, nullptr, Ah1,
                             nullptr, nullptr, nullptr, lnG + 2 * HID, lnB + 2 * HID,
                             nullptr, nullptr, nullptr, nullptr, nullptr);

    // 4) edge MLP + head
    mmC<<<512, 256, SMEM>>>(Ah1, Bem1, Bem1 + 32768, emb1, nullptr, nullptr, Ah0,
                            nullptr, nullptr, nullptr, nullptr, nullptr,
                            ef, emW1 + 256 * HID, nullptr, nullptr, nullptr);
    mmD<<<512, 256, SMEM>>>(Ah0, Bem2, Bem2 + 16384, emb2, nullptr, embOut, Ah1,
                            nullptr, nullptr, nullptr, nullptr, nullptr,
                            nullptr, nullptr, nullptr, nullptr, nullptr);
    mmE<<<512, 256, SMEM>>>(Ah1, Bwh, Bwh + 16384, whb1, nullptr, nullptr, nullptr,
                            nullptr, nullptr, nullptr, nullptr, nullptr,
                            nullptr, nullptr, whW2, whb2, out);
}

// round 13
// speedup vs baseline: 2.8866x; 1.0857x over previous
#include <cuda_runtime.h>
#include <cuda_fp16.h>
#include <mma.h>
#include <cstdint>
#include <math.h>

using namespace nvcuda;

#define NNODES 65535
#define NEDGE  65534
#define NINT   32767
#define MPAD   65536
#define HID    128
#define NF     13
#define NL     3

// ---------------- device-global scratch ----------------
__device__ float g_x13[NINT * NF];
__device__ float g_xA [MPAD * HID];
__device__ float g_xB [MPAD * HID];
__device__ __align__(16) float g_es0[MPAD * 4];
__device__ __align__(16) float g_ed0[MPAD * 4];
__device__ __align__(16) float g_es1[MPAD * 4];
__device__ __align__(16) float g_ed1[MPAD * 4];
__device__ float g_wsd[NL * HID * 8];
__device__ __align__(16) __half g_Ah0[(MPAD + 8) * HID];   // activations, single fp16
__device__ __align__(16) __half g_Ah1[(MPAD + 8) * HID];
// weights: [hi | lo], dest layout [N][K]
__device__ __align__(16) __half g_Bnp [2 * 128 * 128];
__device__ __align__(16) __half g_Bg0 [2 * 128 * 512];
__device__ __align__(16) __half g_Bg1 [2 * 128 * 512];
__device__ __align__(16) __half g_Bg2 [2 * 128 * 512];
__device__ __align__(16) __half g_Bem1[2 * 128 * 256];
__device__ __align__(16) __half g_Bem2[2 * 128 * 128];
__device__ __align__(16) __half g_Bwh [2 * 128 * 128];

// ---------------- cp.async helpers ----------------
__device__ __forceinline__ void cp16(uint32_t dst, const void* src) {
    asm volatile("cp.async.ca.shared.global [%0], [%1], 16;" :: "r"(dst), "l"(src) : "memory");
}
__device__ __forceinline__ void cp_wait_all() {
    asm volatile("cp.async.commit_group;\ncp.async.wait_group 0;" ::: "memory");
}

// ---------------- mega-prep: weight splits + wsd + propagate level-1 ----------------
__device__ __forceinline__ void splitW(const float* __restrict__ W, __half* __restrict__ D,
                                       int K, int e) {
    int n = e / K, k = e - n * K;
    float v = W[(size_t)k * 128 + n];
    __half h = __float2half_rn(v);
    D[e] = h;
    D[(size_t)K * 128 + e] = __float2half_rn(v - __half2float(h));
}
__global__ void k_prep(const float* __restrict__ npW2, const float* __restrict__ gatW,
                       const float* __restrict__ emW1, const float* __restrict__ emW2,
                       const float* __restrict__ whW1, const float* __restrict__ as,
                       const float* __restrict__ ad, const float* __restrict__ nf,
                       float* __restrict__ x13) {
    __shared__ float bufA[64 * NF], bufB[32 * NF];
    if (blockIdx.x >= 1094) {                       // propagate bottom 6 levels
        int m = 511 + (blockIdx.x - 1094);
        int tid = threadIdx.x;
        size_t lbase = (size_t)(64 * m + 63) * NF;
        for (int i = tid; i < 64 * NF; i += 256) bufA[i] = nf[lbase + i];
        __syncthreads();
        float* cur = bufA; float* nxt = bufB;
        int cnt = 32;
#pragma unroll
        for (int s = 1; s <= 6; s++) {
            int start = m * cnt + (cnt - 1);
            for (int i = tid; i < cnt * NF; i += 256) {
                int r = i / NF, f = i - r * NF;
                float v = 0.5f * (cur[(2 * r) * NF + f] + cur[(2 * r + 1) * NF + f]);
                nxt[i] = v;
                x13[(size_t)(start + r) * NF + f] = v;
            }
            __syncthreads();
            float* t = cur; cur = nxt; nxt = t;
            cnt >>= 1;
        }
        return;
    }
    int i = blockIdx.x * 256 + threadIdx.x;
    if (i < 16384) { splitW(npW2, g_Bnp, 128, i); return; }
    if (i < 212992) {
        int j = i - 16384;
        int l = j >> 16, e = j & 65535;
        int d = e >> 9, kk = e & 511;
        int h = kk >> 7, k = kk & 127;
        float v = gatW[(size_t)l * 65536 + (size_t)k * 512 + h * 128 + d] * 0.25f;
        __half hh = __float2half_rn(v);
        __half* B = (l == 0) ? g_Bg0 : (l == 1) ? g_Bg1 : g_Bg2;
        B[(size_t)d * 512 + kk] = hh;
        B[65536 + (size_t)d * 512 + kk] = __float2half_rn(v - __half2float(hh));
        return;
    }
    if (i < 245760) { splitW(emW1, g_Bem1, 256, i - 212992); return; }
    if (i < 262144) { splitW(emW2, g_Bem2, 128, i - 245760); return; }
    if (i < 278528) { splitW(whW1, g_Bwh, 128, i - 262144); return; }
    if (i < 280064) {                               // folded attention vectors
        int j = i - 278528;
        int l = j >> 9, t = j & 511;
        int k = t >> 2, h = t & 3;
        const float* wr = gatW + (size_t)l * HID * 512 + (size_t)k * 512 + h * 128;
        const float* av = as + l * 512 + h * 128;
        const float* dv = ad + l * 512 + h * 128;
        float s = 0.f, d2 = 0.f;
        for (int dd = 0; dd < 128; dd++) {
            float w = wr[dd];
            s  = fmaf(w, av[dd], s);
            d2 = fmaf(w, dv[dd], d2);
        }
        g_wsd[l * 1024 + k * 8 + h]     = s;
        g_wsd[l * 1024 + k * 8 + 4 + h] = d2;
    }
}

// ---------------- propagate top levels ----------------
__global__ void k_prop2(float* __restrict__ x13) {
    extern __shared__ float buf[];
    int tid = threadIdx.x;
    for (int i = tid; i < 512 * NF; i += 512) buf[511 * NF + i] = x13[511 * NF + i];
    __syncthreads();
    for (int d = 8; d >= 0; d--) {
        int start = (1 << d) - 1, cnt = 1 << d;
        for (int i = tid; i < cnt * NF; i += 512) {
            int r = i / NF, f = i - r * NF;
            int n = start + r;
            buf[n * NF + f] = 0.5f * (buf[(2 * n + 1) * NF + f] + buf[(2 * n + 2) * NF + f]);
        }
        __syncthreads();
    }
    for (int i = tid; i < 511 * NF; i += 512) x13[i] = buf[i];
}

// ---------------- node MLP layer 1 -> fp16 ----------------
__global__ void k_mlp1(const float* __restrict__ nf, const float* __restrict__ x13,
                       const float* __restrict__ W1, const float* __restrict__ b1) {
    int idx = blockIdx.x * blockDim.x + threadIdx.x;
    if (idx >= MPAD * 16) return;
    int n = idx >> 4, c0 = (idx & 15) << 3;
    float acc[8];
#pragma unroll
    for (int j = 0; j < 8; j++) acc[j] = b1[c0 + j];
    const float* src = nullptr;
    if (n < NINT)        src = x13 + (size_t)n * NF;
    else if (n < NNODES) src = nf  + (size_t)n * NF;
    if (src) {
#pragma unroll
        for (int k = 0; k < NF; k++) {
            float xv = __ldg(src + k);
#pragma unroll
            for (int j = 0; j < 8; j++) acc[j] = fmaf(xv, W1[k * HID + c0 + j], acc[j]);
        }
    }
    union { uint4 v; __half2 h[4]; } o;
#pragma unroll
    for (int u = 0; u < 4; u++)
        o.h[u] = __floats2half2_rn(fmaxf(acc[2 * u], 0.f), fmaxf(acc[2 * u + 1], 0.f));
    *(uint4*)&g_Ah1[(size_t)n * HID + c0] = o.v;
}

// =================== fused WMMA fp16 2-pass GEMM, 128x128 tile, 2 CTAs/SM ===================
template <int KC, int STAGE, int EPI, int WSD>
__global__ void __launch_bounds__(256, 2)
k_mm(const __half* __restrict__ A, const __half* __restrict__ Bh, const __half* __restrict__ Bl,
     const float* __restrict__ bias, const float* __restrict__ xin,
     float* __restrict__ xout, __half* __restrict__ OA,
     const float* __restrict__ esIn, const float* __restrict__ edIn,
     float* __restrict__ esOut, float* __restrict__ edOut,
     const float* __restrict__ wsd, const float* __restrict__ lg, const float* __restrict__ lb,
     const float* __restrict__ ef, const float* __restrict__ W1c,
     const float* __restrict__ W2, const float* __restrict__ b2, float* __restrict__ lout) {
    extern __shared__ char smem[];
    __half* sA  = (__half*)smem;                          // [0, 34816)
    __half* sBh = sA + 128 * 136;                         // [34816, 69632)
    __half* sBl = sBh + 128 * 136;                        // [69632, 104448)
    uint2* salpha = (uint2*)(smem + 104448);              // 4KB fp16 alpha table
    float* rs1 = (float*)(smem + 104448);                 // aliases salpha (dead by epilogue)
    float* rs2 = rs1 + 256;
    const uint32_t sbase = (uint32_t)__cvta_generic_to_shared(smem);

    const int tid = threadIdx.x;
    const int wid = tid >> 5;
    const int rowBase = blockIdx.x * 128;
    const int row_off = (wid & 3) * 32;
    const int col_off = (wid >> 2) * 64;

    if (STAGE == 2) {
        if (tid < 128) {
            int n = rowBase + tid;
            bool vp = n > 0;
            int p  = vp ? (n - 1) >> 1 : 0;
            int c1 = 2 * n + 1;
            bool vc = c1 < NNODES;
            int nb[4] = {n, p, vc ? c1 : 0, vc ? c1 + 1 : 0};
            bool val[4] = {true, vp, vc, vc};
            float4 e4[4];
#pragma unroll
            for (int j = 0; j < 4; j++) e4[j] = ((const float4*)esIn)[nb[j]];
            float4 dD = ((const float4*)edIn)[n];
            float esv[4][4], edv[4] = {dD.x, dD.y, dD.z, dD.w};
#pragma unroll
            for (int j = 0; j < 4; j++) { esv[j][0]=e4[j].x; esv[j][1]=e4[j].y; esv[j][2]=e4[j].z; esv[j][3]=e4[j].w; }
#pragma unroll
            for (int h = 0; h < 4; h++) {
                float e[4], m = -1e30f;
#pragma unroll
                for (int j = 0; j < 4; j++) {
                    float s = esv[j][h] + edv[h];
                    s = (s >= 0.f) ? s : 0.2f * s;
                    e[j] = s;
                    if (val[j]) m = fmaxf(m, s);
                }
                float sum = 0.f;
#pragma unroll
                for (int j = 0; j < 4; j++) { e[j] = val[j] ? expf(e[j] - m) : 0.f; sum += e[j]; }
                float inv = 1.f / sum;
                uint2 pk;
                *(__half2*)&pk.x = __floats2half2_rn(e[0] * inv, e[1] * inv);
                *(__half2*)&pk.y = __floats2half2_rn(e[2] * inv, e[3] * inv);
                salpha[tid * 4 + h] = pk;
            }
        }
        __syncthreads();
    }

    wmma::fragment<wmma::accumulator, 16, 16, 16, float> acc[2][4];
#pragma unroll
    for (int i = 0; i < 2; i++)
#pragma unroll
        for (int j = 0; j < 4; j++) wmma::fill_fragment(acc[i][j], 0.0f);

    const uint4* gA  = (const uint4*)A;
    const uint4* gBh = (const uint4*)Bh;
    const uint4* gBl = (const uint4*)Bl;

#pragma unroll
    for (int c = 0; c < KC; c++) {
        for (int id = tid; id < 128 * 16; id += 256) {
            int r = id >> 4, q = id & 15;
            uint32_t dstA = sbase + r * 272 + q * 16;
            if (STAGE == 0) {
                size_t g = (size_t)(rowBase + r) * (KC * 16) + c * 16 + q;
                cp16(dstA, &gA[g]);
            } else if (STAGE == 1) {
                int e = rowBase + r;
                size_t row = (c == 0) ? (size_t)(e >> 1) : (size_t)(e + 1);
                cp16(dstA, &gA[row * 16 + q]);
            } else {
                int n = rowBase + r;
                int p  = (n > 0) ? (n - 1) >> 1 : 0;
                int c1 = 2 * n + 1;
                bool vc = c1 < NNODES;
                int nb[4] = {n, p, vc ? c1 : 0, vc ? c1 + 1 : 0};
                uint2 av = salpha[r * 4 + c];
                float2 f01 = __half22float2(*(__half2*)&av.x);
                float2 f23 = __half22float2(*(__half2*)&av.y);
                float aj[4] = {f01.x, f01.y, f23.x, f23.y};
                float z[8] = {0,0,0,0,0,0,0,0};
#pragma unroll
                for (int j = 0; j < 4; j++) {
                    uint4 hv = gA[(size_t)nb[j] * 16 + q];
                    const __half2* hp = (const __half2*)&hv;
                    float a = aj[j];
#pragma unroll
                    for (int u = 0; u < 4; u++) {
                        float2 fh = __half22float2(hp[u]);
                        z[2*u]   = fmaf(a, fh.x, z[2*u]);
                        z[2*u+1] = fmaf(a, fh.y, z[2*u+1]);
                    }
                }
                union { uint4 v; __half2 h[4]; } oz;
#pragma unroll
                for (int u = 0; u < 4; u++) oz.h[u] = __floats2half2_rn(z[2*u], z[2*u+1]);
                *(uint4*)&sA[r * 136 + q * 8] = oz.v;
            }
        }
        for (int id = tid; id < 128 * 16; id += 256) {
            int r = id >> 4, q = id & 15;
            size_t g = (size_t)r * (KC * 16) + c * 16 + q;
            uint32_t dst = sbase + 34816 + r * 272 + q * 16;
            cp16(dst, &gBh[g]);
            cp16(dst + 34816, &gBl[g]);
        }
        cp_wait_all();
        __syncthreads();

#pragma unroll
        for (int ks = 0; ks < 8; ks++) {
            wmma::fragment<wmma::matrix_a, 16, 16, 16, __half, wmma::row_major> ah[2];
#pragma unroll
            for (int i = 0; i < 2; i++)
                wmma::load_matrix_sync(ah[i], sA + (row_off + i * 16) * 136 + ks * 16, 136);
#pragma unroll
            for (int j = 0; j < 4; j++) {
                wmma::fragment<wmma::matrix_b, 16, 16, 16, __half, wmma::col_major> bh, bl;
                wmma::load_matrix_sync(bh, sBh + (col_off + j * 16) * 136 + ks * 16, 136);
                wmma::load_matrix_sync(bl, sBl + (col_off + j * 16) * 136 + ks * 16, 136);
#pragma unroll
                for (int i = 0; i < 2; i++) {
                    wmma::mma_sync(acc[i][j], ah[i], bh, acc[i][j]);
                    wmma::mma_sync(acc[i][j], ah[i], bl, acc[i][j]);
                }
            }
        }
        __syncthreads();
    }

    float* stage = (float*)smem;
#pragma unroll
    for (int i = 0; i < 2; i++)
#pragma unroll
        for (int j = 0; j < 4; j++)
            wmma::store_matrix_sync(stage + (row_off + i * 16) * 132 + col_off + j * 16,
                                    acc[i][j], 132, wmma::mem_row_major);
    __syncthreads();

    for (int id = tid; id < 128 * 64; id += 256) {
        int r = id >> 6, c2 = (id & 63) * 2;
        int row = rowBase + r;
        float v0 = stage[r * 132 + c2]     + bias[c2];
        float v1 = stage[r * 132 + c2 + 1] + bias[c2 + 1];
        if (EPI == 1) {
            float2 xv = *(const float2*)&xin[(size_t)row * HID + c2];
            v0 += xv.x; v1 += xv.y;
        }
        if (EPI == 2) {
            if (row < NEDGE) {
                float4 e4 = ((const float4*)ef)[row];
                v0 += e4.x * W1c[c2]       + e4.y * W1c[128 + c2]
                    + e4.z * W1c[256 + c2] + e4.w * W1c[384 + c2];
                v1 += e4.x * W1c[c2 + 1]       + e4.y * W1c[128 + c2 + 1]
                    + e4.z * W1c[256 + c2 + 1] + e4.w * W1c[384 + c2 + 1];
            }
            v0 = fmaxf(v0, 0.f); v1 = fmaxf(v1, 0.f);
        }
        if (EPI == 4) { v0 = fmaxf(v0, 0.f); v1 = fmaxf(v1, 0.f); }
        stage[r * 132 + c2]     = v0;
        stage[r * 132 + c2 + 1] = v1;
        if (EPI == 1) {
            float s1 = v0 + v1, s2 = v0 * v0 + v1 * v1;
#pragma unroll
            for (int o = 16; o > 0; o >>= 1) {
                s1 += __shfl_xor_sync(0xffffffffu, s1, o);
                s2 += __shfl_xor_sync(0xffffffffu, s2, o);
            }
            if ((tid & 31) == 0) {
                int hf = (id >> 5) & 1;
                rs1[r * 2 + hf] = s1;
                rs2[r * 2 + hf] = s2;
            }
        }
    }
    __syncthreads();

    for (int id = tid; id < 128 * 64; id += 256) {
        int r = id >> 6, c2 = (id & 63) * 2;
        int row = rowBase + r;
        float v0 = stage[r * 132 + c2];
        float v1 = stage[r * 132 + c2 + 1];
        if (EPI == 1) {
            float mean = (rs1[r * 2] + rs1[r * 2 + 1]) * (1.f / HID);
            float var  = (rs2[r * 2] + rs2[r * 2 + 1]) * (1.f / HID) - mean * mean;
            float rstd = rsqrtf(var + 1e-5f);
            v0 = (v0 - mean) * rstd * lg[c2]     + lb[c2];
            v1 = (v1 - mean) * rstd * lg[c2 + 1] + lb[c2 + 1];
            if (xout) *(float2*)&xout[(size_t)row * HID + c2] = make_float2(v0, v1);
            if (WSD) { stage[r * 132 + c2] = v0; stage[r * 132 + c2 + 1] = v1; }
        }
        if (EPI == 0) *(float2*)&xout[(size_t)row * HID + c2] = make_float2(v0, v1);
        if (EPI == 3 && row < NEDGE) *(float2*)&xout[(size_t)row * HID + c2] = make_float2(v0, v1);
        if (EPI <= 3) {
            *(__half2*)&OA[(size_t)row * HID + c2] = __floats2half2_rn(v0, v1);
        }
    }

    constexpr bool PHC = (EPI == 0) || (EPI == 4) || (EPI == 1 && WSD);
    if (PHC) {
        __syncthreads();
        int r = tid >> 1, half = tid & 1;
        int row = rowBase + r;
        if (EPI == 4) {
            float s0 = 0.f, s1 = 0.f;
            for (int c = 0; c < 64; c++) {
                int col = half * 64 + c;
                float v = stage[r * 132 + col];
                s0 = fmaf(v, W2[col * 2], s0);
                s1 = fmaf(v, W2[col * 2 + 1], s1);
            }
            s0 += __shfl_xor_sync(0xffffffffu, s0, 1);
            s1 += __shfl_xor_sync(0xffffffffu, s1, 1);
            if (half == 0 && row < NEDGE) {
                lout[(size_t)row * 2]     = s0 + b2[0];
                lout[(size_t)row * 2 + 1] = s1 + b2[1];
            }
        } else {
            float pr[8] = {0,0,0,0,0,0,0,0};
            for (int c = 0; c < 64; c++) {
                int col = half * 64 + c;
                float v = stage[r * 132 + col];
                const float* w = wsd + col * 8;
#pragma unroll
                for (int p = 0; p < 8; p++) pr[p] = fmaf(v, w[p], pr[p]);
            }
#pragma unroll
            for (int p = 0; p < 8; p++) pr[p] += __shfl_xor_sync(0xffffffffu, pr[p], 1);
            if (half == 0) {
                ((float4*)esOut)[row] = make_float4(pr[0], pr[1], pr[2], pr[3]);
                ((float4*)edOut)[row] = make_float4(pr[4], pr[5], pr[6], pr[7]);
            }
        }
    }
}

// ---------------- launch ----------------
extern "C" void kernel_launch(void* const* d_in, const int* in_sizes, int n_in,
                              void* d_out, int out_size) {
    const float* nf    = (const float*)d_in[0];
    const float* ef    = (const float*)d_in[2];
    const float* npW1  = (const float*)d_in[4];
    const float* npb1  = (const float*)d_in[5];
    const float* npW2  = (const float*)d_in[6];
    const float* npb2  = (const float*)d_in[7];
    const float* gatW  = (const float*)d_in[8];
    const float* gatAs = (const float*)d_in[9];
    const float* gatAd = (const float*)d_in[10];
    const float* gatB  = (const float*)d_in[11];
    const float* lnG   = (const float*)d_in[12];
    const float* lnB   = (const float*)d_in[13];
    const float* emW1  = (const float*)d_in[14];
    const float* emb1  = (const float*)d_in[15];
    const float* emW2  = (const float*)d_in[16];
    const float* emb2  = (const float*)d_in[17];
    const float* whW1  = (const float*)d_in[18];
    const float* whb1  = (const float*)d_in[19];
    const float* whW2  = (const float*)d_in[20];
    const float* whb2  = (const float*)d_in[21];

    float* out    = (float*)d_out;
    float* embOut = out + (size_t)NEDGE * 2;

    float *x13, *xA, *xB, *wsd, *es0, *ed0, *es1, *ed1;
    __half *Ah0, *Ah1, *Bnp, *Bg0, *Bg1, *Bg2, *Bem1, *Bem2, *Bwh;
    cudaGetSymbolAddress((void**)&x13, g_x13);
    cudaGetSymbolAddress((void**)&xA,  g_xA);
    cudaGetSymbolAddress((void**)&xB,  g_xB);
    cudaGetSymbolAddress((void**)&wsd, g_wsd);
    cudaGetSymbolAddress((void**)&es0, g_es0);
    cudaGetSymbolAddress((void**)&ed0, g_ed0);
    cudaGetSymbolAddress((void**)&es1, g_es1);
    cudaGetSymbolAddress((void**)&ed1, g_ed1);
    cudaGetSymbolAddress((void**)&Ah0, g_Ah0);
    cudaGetSymbolAddress((void**)&Ah1, g_Ah1);
    cudaGetSymbolAddress((void**)&Bnp, g_Bnp);
    cudaGetSymbolAddress((void**)&Bg0, g_Bg0);
    cudaGetSymbolAddress((void**)&Bg1, g_Bg1);
    cudaGetSymbolAddress((void**)&Bg2, g_Bg2);
    cudaGetSymbolAddress((void**)&Bem1, g_Bem1);
    cudaGetSymbolAddress((void**)&Bem2, g_Bem2);
    cudaGetSymbolAddress((void**)&Bwh, g_Bwh);

    constexpr int SMEM = 104448 + 4096;   // 108544 B/CTA -> 2 CTAs/SM
    auto mmA  = k_mm<1, 0, 0, 1>;
    auto mmB1 = k_mm<4, 2, 1, 1>;
    auto mmB0 = k_mm<4, 2, 1, 0>;
    auto mmC  = k_mm<2, 1, 2, 0>;
    auto mmD  = k_mm<1, 0, 3, 0>;
    auto mmE  = k_mm<1, 0, 4, 0>;
    cudaFuncSetAttribute(mmA,  cudaFuncAttributeMaxDynamicSharedMemorySize, SMEM);
    cudaFuncSetAttribute(mmB1, cudaFuncAttributeMaxDynamicSharedMemorySize, SMEM);
    cudaFuncSetAttribute(mmB0, cudaFuncAttributeMaxDynamicSharedMemorySize, SMEM);
    cudaFuncSetAttribute(mmC,  cudaFuncAttributeMaxDynamicSharedMemorySize, SMEM);
    cudaFuncSetAttribute(mmD,  cudaFuncAttributeMaxDynamicSharedMemorySize, SMEM);
    cudaFuncSetAttribute(mmE,  cudaFuncAttributeMaxDynamicSharedMemorySize, SMEM);
    cudaFuncSetAttribute(k_prop2, cudaFuncAttributeMaxDynamicSharedMemorySize, 1023 * NF * 4);

    // 0) mega-prep (weight splits + folded vectors + propagate level-1), then top levels
    k_prep<<<1606, 256>>>(npW2, gatW, emW1, emW2, whW1, gatAs, gatAd, nf, x13);
    k_prop2<<<1, 512, 1023 * NF * 4>>>(x13);

    // 1) node MLP
    k_mlp1<<<(MPAD * 16) / 256, 256>>>(nf, x13, npW1, npb1);
    mmA<<<512, 256, SMEM>>>(Ah1, Bnp, Bnp + 16384, npb2, nullptr, xA, Ah0,
                            nullptr, nullptr, es0, ed0, wsd, nullptr, nullptr,
                            nullptr, nullptr, nullptr, nullptr, nullptr);

    // 2) GAT layers (alpha computed in-kernel from es/ed)
    mmB1<<<512, 256, SMEM>>>(Ah0, Bg0, Bg0 + 65536, gatB, xA, xB, Ah1,
                             es0, ed0, es1, ed1, wsd + 1024, lnG, lnB,
                             nullptr, nullptr, nullptr, nullptr, nullptr);
    mmB1<<<512, 256, SMEM>>>(Ah1, Bg1, Bg1 + 65536, gatB + HID, xB, xA, Ah0,
                             es1, ed1, es0, ed0, wsd + 2048, lnG + HID, lnB + HID,
                             nullptr, nullptr, nullptr, nullptr, nullptr);
    mmB0<<<512, 256, SMEM>>>(Ah0, Bg2, Bg2 + 65536, gatB + 2 * HID, xA, nullptr, Ah1,
                             es0, ed0, nullptr, nullptr, nullptr, lnG + 2 * HID, lnB + 2 * HID,
                             nullptr, nullptr, nullptr, nullptr, nullptr);

    // 3) edge MLP + head
    mmC<<<512, 256, SMEM>>>(Ah1, Bem1, Bem1 + 32768, emb1, nullptr, nullptr, Ah0,
                            nullptr, nullptr, nullptr, nullptr, nullptr, nullptr, nullptr,
                            ef, emW1 + 256 * HID, nullptr, nullptr, nullptr);
    mmD<<<512, 256, SMEM>>>(Ah0, Bem2, Bem2 + 16384, emb2, nullptr, embOut, Ah1,
                            nullptr, nullptr, nullptr, nullptr, nullptr, nullptr, nullptr,
                            nullptr, nullptr, nullptr, nullptr, nullptr);
    mmE<<<512, 256, SMEM>>>(Ah1, Bwh, Bwh + 16384, whb1, nullptr, nullptr, nullptr,
                            nullptr, nullptr, nullptr, nullptr, nullptr, nullptr, nullptr,
                            nullptr, nullptr, whW2, whb2, out);
}

// round 16
// speedup vs baseline: 3.2606x; 1.1296x over previous
#include <cuda_runtime.h>
#include <cuda_fp16.h>
#include <mma.h>
#include <cstdint>
#include <math.h>

using namespace nvcuda;

#define NNODES 65535
#define NEDGE  65534
#define NINT   32767
#define MPAD   65536
#define HID    128
#define NF     13
#define NL     3

// ---------------- device-global scratch ----------------
__device__ float g_x13[NINT * NF];
__device__ float g_xA [MPAD * HID];
__device__ float g_xB [MPAD * HID];
__device__ __align__(16) float g_es0[MPAD * 4];
__device__ __align__(16) float g_ed0[MPAD * 4];
__device__ __align__(16) float g_es1[MPAD * 4];
__device__ __align__(16) float g_ed1[MPAD * 4];
__device__ float g_wsd[NL * HID * 8];
__device__ __align__(16) __half g_Ah0[(MPAD + 8) * HID];   // activations, single fp16
__device__ __align__(16) __half g_Ah1[(MPAD + 8) * HID];
// weights: [hi | lo], dest layout [N][K]
__device__ __align__(16) __half g_Bnp [2 * 128 * 128];
__device__ __align__(16) __half g_Bg0 [2 * 128 * 512];
__device__ __align__(16) __half g_Bg1 [2 * 128 * 512];
__device__ __align__(16) __half g_Bg2 [2 * 128 * 512];
__device__ __align__(16) __half g_Bem1[2 * 128 * 256];
__device__ __align__(16) __half g_Bem2[2 * 128 * 128];
__device__ __align__(16) __half g_Bwh [2 * 128 * 128];

// ---------------- cp.async helpers ----------------
__device__ __forceinline__ void cp16(uint32_t dst, const void* src) {
    asm volatile("cp.async.ca.shared.global [%0], [%1], 16;" :: "r"(dst), "l"(src) : "memory");
}
__device__ __forceinline__ void cp_wait_all() {
    asm volatile("cp.async.commit_group;\ncp.async.wait_group 0;" ::: "memory");
}

// ---------------- mega-prep: weight splits + wsd + propagate level-1 ----------------
__device__ __forceinline__ void splitW(const float* __restrict__ W, __half* __restrict__ D,
                                       int K, int e) {
    int n = e / K, k = e - n * K;
    float v = W[(size_t)k * 128 + n];
    __half h = __float2half_rn(v);
    D[e] = h;
    D[(size_t)K * 128 + e] = __float2half_rn(v - __half2float(h));
}
__global__ void k_prep(const float* __restrict__ npW2, const float* __restrict__ gatW,
                       const float* __restrict__ emW1, const float* __restrict__ emW2,
                       const float* __restrict__ whW1, const float* __restrict__ as,
                       const float* __restrict__ ad, const float* __restrict__ nf,
                       float* __restrict__ x13) {
    __shared__ float bufA[64 * NF], bufB[32 * NF];
    if (blockIdx.x >= 1094) {                       // propagate bottom 6 levels
        int m = 511 + (blockIdx.x - 1094);
        int tid = threadIdx.x;
        size_t lbase = (size_t)(64 * m + 63) * NF;
        for (int i = tid; i < 64 * NF; i += 256) bufA[i] = nf[lbase + i];
        __syncthreads();
        float* cur = bufA; float* nxt = bufB;
        int cnt = 32;
#pragma unroll
        for (int s = 1; s <= 6; s++) {
            int start = m * cnt + (cnt - 1);
            for (int i = tid; i < cnt * NF; i += 256) {
                int r = i / NF, f = i - r * NF;
                float v = 0.5f * (cur[(2 * r) * NF + f] + cur[(2 * r + 1) * NF + f]);
                nxt[i] = v;
                x13[(size_t)(start + r) * NF + f] = v;
            }
            __syncthreads();
            float* t = cur; cur = nxt; nxt = t;
            cnt >>= 1;
        }
        return;
    }
    int i = blockIdx.x * 256 + threadIdx.x;
    if (i < 16384) { splitW(npW2, g_Bnp, 128, i); return; }
    if (i < 212992) {
        int j = i - 16384;
        int l = j >> 16, e = j & 65535;
        int d = e >> 9, kk = e & 511;
        int h = kk >> 7, k = kk & 127;
        float v = gatW[(size_t)l * 65536 + (size_t)k * 512 + h * 128 + d] * 0.25f;
        __half hh = __float2half_rn(v);
        __half* B = (l == 0) ? g_Bg0 : (l == 1) ? g_Bg1 : g_Bg2;
        B[(size_t)d * 512 + kk] = hh;
        B[65536 + (size_t)d * 512 + kk] = __float2half_rn(v - __half2float(hh));
        return;
    }
    if (i < 245760) { splitW(emW1, g_Bem1, 256, i - 212992); return; }
    if (i < 262144) { splitW(emW2, g_Bem2, 128, i - 245760); return; }
    if (i < 278528) { splitW(whW1, g_Bwh, 128, i - 262144); return; }
    if (i < 280064) {                               // folded attention vectors
        int j = i - 278528;
        int l = j >> 9, t = j & 511;
        int k = t >> 2, h = t & 3;
        const float* wr = gatW + (size_t)l * HID * 512 + (size_t)k * 512 + h * 128;
        const float* av = as + l * 512 + h * 128;
        const float* dv = ad + l * 512 + h * 128;
        float s = 0.f, d2 = 0.f;
        for (int dd = 0; dd < 128; dd++) {
            float w = wr[dd];
            s  = fmaf(w, av[dd], s);
            d2 = fmaf(w, dv[dd], d2);
        }
        g_wsd[l * 1024 + k * 8 + h]     = s;
        g_wsd[l * 1024 + k * 8 + 4 + h] = d2;
    }
}

// ---------------- propagate top levels ----------------
__global__ void k_prop2(float* __restrict__ x13) {
    extern __shared__ float buf[];
    int tid = threadIdx.x;
    for (int i = tid; i < 512 * NF; i += 512) buf[511 * NF + i] = x13[511 * NF + i];
    __syncthreads();
    for (int d = 8; d >= 0; d--) {
        int start = (1 << d) - 1, cnt = 1 << d;
        for (int i = tid; i < cnt * NF; i += 512) {
            int r = i / NF, f = i - r * NF;
            int n = start + r;
            buf[n * NF + f] = 0.5f * (buf[(2 * n + 1) * NF + f] + buf[(2 * n + 2) * NF + f]);
        }
        __syncthreads();
    }
    for (int i = tid; i < 511 * NF; i += 512) x13[i] = buf[i];
}

// ---------------- node MLP layer 1 -> fp16 ----------------
__global__ void k_mlp1(const float* __restrict__ nf, const float* __restrict__ x13,
                       const float* __restrict__ W1, const float* __restrict__ b1) {
    int idx = blockIdx.x * blockDim.x + threadIdx.x;
    if (idx >= MPAD * 16) return;
    int n = idx >> 4, c0 = (idx & 15) << 3;
    float acc[8];
#pragma unroll
    for (int j = 0; j < 8; j++) acc[j] = b1[c0 + j];
    const float* src = nullptr;
    if (n < NINT)        src = x13 + (size_t)n * NF;
    else if (n < NNODES) src = nf  + (size_t)n * NF;
    if (src) {
#pragma unroll
        for (int k = 0; k < NF; k++) {
            float xv = __ldg(src + k);
#pragma unroll
            for (int j = 0; j < 8; j++) acc[j] = fmaf(xv, W1[k * HID + c0 + j], acc[j]);
        }
    }
    union { uint4 v; __half2 h[4]; } o;
#pragma unroll
    for (int u = 0; u < 4; u++)
        o.h[u] = __floats2half2_rn(fmaxf(acc[2 * u], 0.f), fmaxf(acc[2 * u + 1], 0.f));
    *(uint4*)&g_Ah1[(size_t)n * HID + c0] = o.v;
}

// =================== fused WMMA fp16 GEMM, 128x128 tile, 2 CTAs/SM ===================
// PASS: 1 = A*Bh only, 2 = A*Bh + A*Bl.
// STAGE: 0 plain, 1 edge gather, 2 attention aggregate (in-kernel alphas).
// EPI: 0 ATTN  1 GAT(residual+LN[+scores])  2 EF  3 BIASO  4 HEAD  5 fused edgeMLP2+HEAD
template <int KC, int STAGE, int EPI, int WSD, int PASS>
__global__ void __launch_bounds__(256, 2)
k_mm(const __half* __restrict__ A, const __half* __restrict__ Bh, const __half* __restrict__ Bl,
     const float* __restrict__ bias, const float* __restrict__ xin,
     float* __restrict__ xout, __half* __restrict__ OA,
     const float* __restrict__ esIn, const float* __restrict__ edIn,
     float* __restrict__ esOut, float* __restrict__ edOut,
     const float* __restrict__ wsd, const float* __restrict__ lg, const float* __restrict__ lb,
     const float* __restrict__ ef, const float* __restrict__ W1c,
     const float* __restrict__ W2, const float* __restrict__ b2,
     const __half* __restrict__ B2, const float* __restrict__ bias2,
     float* __restrict__ lout) {
    extern __shared__ char smem[];
    __half* sA  = (__half*)smem;                          // [0, 34816)
    __half* sBh = sA + 128 * 136;                         // [34816, 69632)
    __half* sBl = sBh + 128 * 136;                        // [69632, 104448)
    uint2* salpha = (uint2*)(smem + 104448);              // 4KB fp16 alpha table
    float* rs1 = (float*)(smem + 104448);                 // aliases salpha (dead by epilogue)
    float* rs2 = rs1 + 256;
    const uint32_t sbase = (uint32_t)__cvta_generic_to_shared(smem);

    const int tid = threadIdx.x;
    const int wid = tid >> 5;
    const int rowBase = blockIdx.x * 128;
    const int row_off = (wid & 3) * 32;
    const int col_off = (wid >> 2) * 64;

    if (STAGE == 2) {
        if (tid < 128) {
            int n = rowBase + tid;
            bool vp = n > 0;
            int p  = vp ? (n - 1) >> 1 : 0;
            int c1 = 2 * n + 1;
            bool vc = c1 < NNODES;
            int nb[4] = {n, p, vc ? c1 : 0, vc ? c1 + 1 : 0};
            bool val[4] = {true, vp, vc, vc};
            float4 e4[4];
#pragma unroll
            for (int j = 0; j < 4; j++) e4[j] = ((const float4*)esIn)[nb[j]];
            float4 dD = ((const float4*)edIn)[n];
            float esv[4][4], edv[4] = {dD.x, dD.y, dD.z, dD.w};
#pragma unroll
            for (int j = 0; j < 4; j++) { esv[j][0]=e4[j].x; esv[j][1]=e4[j].y; esv[j][2]=e4[j].z; esv[j][3]=e4[j].w; }
#pragma unroll
            for (int h = 0; h < 4; h++) {
                float e[4], m = -1e30f;
#pragma unroll
                for (int j = 0; j < 4; j++) {
                    float s = esv[j][h] + edv[h];
                    s = (s >= 0.f) ? s : 0.2f * s;
                    e[j] = s;
                    if (val[j]) m = fmaxf(m, s);
                }
                float sum = 0.f;
#pragma unroll
                for (int j = 0; j < 4; j++) { e[j] = val[j] ? expf(e[j] - m) : 0.f; sum += e[j]; }
                float inv = 1.f / sum;
                uint2 pk;
                *(__half2*)&pk.x = __floats2half2_rn(e[0] * inv, e[1] * inv);
                *(__half2*)&pk.y = __floats2half2_rn(e[2] * inv, e[3] * inv);
                salpha[tid * 4 + h] = pk;
            }
        }
        __syncthreads();
    }

    wmma::fragment<wmma::accumulator, 16, 16, 16, float> acc[2][4];
#pragma unroll
    for (int i = 0; i < 2; i++)
#pragma unroll
        for (int j = 0; j < 4; j++) wmma::fill_fragment(acc[i][j], 0.0f);

    const uint4* gA  = (const uint4*)A;
    const uint4* gBh = (const uint4*)Bh;
    const uint4* gBl = (const uint4*)Bl;

#pragma unroll
    for (int c = 0; c < KC; c++) {
        for (int id = tid; id < 128 * 16; id += 256) {
            int r = id >> 4, q = id & 15;
            uint32_t dstA = sbase + r * 272 + q * 16;
            if (STAGE == 0) {
                size_t g = (size_t)(rowBase + r) * (KC * 16) + c * 16 + q;
                cp16(dstA, &gA[g]);
            } else if (STAGE == 1) {
                int e = rowBase + r;
                size_t row = (c == 0) ? (size_t)(e >> 1) : (size_t)(e + 1);
                cp16(dstA, &gA[row * 16 + q]);
            } else {
                int n = rowBase + r;
                int p  = (n > 0) ? (n - 1) >> 1 : 0;
                int c1 = 2 * n + 1;
                bool vc = c1 < NNODES;
                int nb[4] = {n, p, vc ? c1 : 0, vc ? c1 + 1 : 0};
                uint2 av = salpha[r * 4 + c];
                float2 f01 = __half22float2(*(__half2*)&av.x);
                float2 f23 = __half22float2(*(__half2*)&av.y);
                float aj[4] = {f01.x, f01.y, f23.x, f23.y};
                float z[8] = {0,0,0,0,0,0,0,0};
#pragma unroll
                for (int j = 0; j < 4; j++) {
                    uint4 hv = gA[(size_t)nb[j] * 16 + q];
                    const __half2* hp = (const __half2*)&hv;
                    float a = aj[j];
#pragma unroll
                    for (int u = 0; u < 4; u++) {
                        float2 fh = __half22float2(hp[u]);
                        z[2*u]   = fmaf(a, fh.x, z[2*u]);
                        z[2*u+1] = fmaf(a, fh.y, z[2*u+1]);
                    }
                }
                union { uint4 v; __half2 h[4]; } oz;
#pragma unroll
                for (int u = 0; u < 4; u++) oz.h[u] = __floats2half2_rn(z[2*u], z[2*u+1]);
                *(uint4*)&sA[r * 136 + q * 8] = oz.v;
            }
        }
        for (int id = tid; id < 128 * 16; id += 256) {
            int r = id >> 4, q = id & 15;
            size_t g = (size_t)r * (KC * 16) + c * 16 + q;
            uint32_t dst = sbase + 34816 + r * 272 + q * 16;
            cp16(dst, &gBh[g]);
            if (PASS == 2) cp16(dst + 34816, &gBl[g]);
        }
        cp_wait_all();
        __syncthreads();

#pragma unroll
        for (int ks = 0; ks < 8; ks++) {
            wmma::fragment<wmma::matrix_a, 16, 16, 16, __half, wmma::row_major> ah[2];
#pragma unroll
            for (int i = 0; i < 2; i++)
                wmma::load_matrix_sync(ah[i], sA + (row_off + i * 16) * 136 + ks * 16, 136);
#pragma unroll
            for (int j = 0; j < 4; j++) {
                wmma::fragment<wmma::matrix_b, 16, 16, 16, __half, wmma::col_major> bh, bl;
                wmma::load_matrix_sync(bh, sBh + (col_off + j * 16) * 136 + ks * 16, 136);
                if (PASS == 2)
                    wmma::load_matrix_sync(bl, sBl + (col_off + j * 16) * 136 + ks * 16, 136);
#pragma unroll
                for (int i = 0; i < 2; i++) {
                    wmma::mma_sync(acc[i][j], ah[i], bh, acc[i][j]);
                    if (PASS == 2) wmma::mma_sync(acc[i][j], ah[i], bl, acc[i][j]);
                }
            }
        }
        __syncthreads();
    }

    float* stage = (float*)smem;
#pragma unroll
    for (int i = 0; i < 2; i++)
#pragma unroll
        for (int j = 0; j < 4; j++)
            wmma::store_matrix_sync(stage + (row_off + i * 16) * 132 + col_off + j * 16,
                                    acc[i][j], 132, wmma::mem_row_major);
    __syncthreads();

    if (EPI == 5) {
        // ---- fused: emb output + fp16 convert into high smem ----
        __half* sA2 = (__half*)(smem + 69632);
        for (int id = tid; id < 128 * 64; id += 256) {
            int r = id >> 6, c2 = (id & 63) * 2;
            int row = rowBase + r;
            float v0 = stage[r * 132 + c2]     + bias[c2];
            float v1 = stage[r * 132 + c2 + 1] + bias[c2 + 1];
            if (row < NEDGE) *(float2*)&xout[(size_t)row * HID + c2] = make_float2(v0, v1);
            *(__half2*)&sA2[r * 136 + c2] = __floats2half2_rn(v0, v1);
        }
        __syncthreads();
        // ---- stage whW1 hi/lo into [0, 69632) (stage is dead) ----
        const uint4* gB2h = (const uint4*)B2;
        const uint4* gB2l = (const uint4*)(B2 + 16384);
        for (int id = tid; id < 128 * 16; id += 256) {
            int r = id >> 4, q = id & 15;
            size_t g = (size_t)r * 16 + q;
            uint32_t dst = sbase + r * 272 + q * 16;
            cp16(dst, &gB2h[g]);
            cp16(dst + 34816, &gB2l[g]);
        }
        cp_wait_all();
        __syncthreads();
        // ---- second GEMM: emb @ whW1 accumulators ----
#pragma unroll
        for (int i = 0; i < 2; i++)
#pragma unroll
            for (int j = 0; j < 4; j++) wmma::fill_fragment(acc[i][j], 0.0f);
        __half* b2h = (__half*)smem;
        __half* b2l = (__half*)(smem + 34816);
#pragma unroll
        for (int ks = 0; ks < 8; ks++) {
            wmma::fragment<wmma::matrix_a, 16, 16, 16, __half, wmma::row_major> ah[2];
#pragma unroll
            for (int i = 0; i < 2; i++)
                wmma::load_matrix_sync(ah[i], sA2 + (row_off + i * 16) * 136 + ks * 16, 136);
#pragma unroll
            for (int j = 0; j < 4; j++) {
                wmma::fragment<wmma::matrix_b, 16, 16, 16, __half, wmma::col_major> bh, bl;
                wmma::load_matrix_sync(bh, b2h + (col_off + j * 16) * 136 + ks * 16, 136);
                wmma::load_matrix_sync(bl, b2l + (col_off + j * 16) * 136 + ks * 16, 136);
#pragma unroll
                for (int i = 0; i < 2; i++) {
                    wmma::mma_sync(acc[i][j], ah[i], bh, acc[i][j]);
                    wmma::mma_sync(acc[i][j], ah[i], bl, acc[i][j]);
                }
            }
        }
        __syncthreads();
#pragma unroll
        for (int i = 0; i < 2; i++)
#pragma unroll
            for (int j = 0; j < 4; j++)
                wmma::store_matrix_sync(stage + (row_off + i * 16) * 132 + col_off + j * 16,
                                        acc[i][j], 132, wmma::mem_row_major);
        __syncthreads();
        // ---- logits: relu(v + whb1) . W2 + b2 ----
        int r = tid >> 1, half = tid & 1;
        int row = rowBase + r;
        float s0 = 0.f, s1 = 0.f;
        for (int c = 0; c < 64; c++) {
            int col = half * 64 + c;
            float v = fmaxf(stage[r * 132 + col] + bias2[col], 0.f);
            s0 = fmaf(v, W2[col * 2], s0);
            s1 = fmaf(v, W2[col * 2 + 1], s1);
        }
        s0 += __shfl_xor_sync(0xffffffffu, s0, 1);
        s1 += __shfl_xor_sync(0xffffffffu, s1, 1);
        if (half == 0 && row < NEDGE) {
            lout[(size_t)row * 2]     = s0 + b2[0];
            lout[(size_t)row * 2 + 1] = s1 + b2[1];
        }
        return;
    }

    for (int id = tid; id < 128 * 64; id += 256) {
        int r = id >> 6, c2 = (id & 63) * 2;
        int row = rowBase + r;
        float v0 = stage[r * 132 + c2]     + bias[c2];
        float v1 = stage[r * 132 + c2 + 1] + bias[c2 + 1];
        if (EPI == 1) {
            float2 xv = *(const float2*)&xin[(size_t)row * HID + c2];
            v0 += xv.x; v1 += xv.y;
        }
        if (EPI == 2) {
            if (row < NEDGE) {
                float4 e4 = ((const float4*)ef)[row];
                v0 += e4.x * W1c[c2]       + e4.y * W1c[128 + c2]
                    + e4.z * W1c[256 + c2] + e4.w * W1c[384 + c2];
                v1 += e4.x * W1c[c2 + 1]       + e4.y * W1c[128 + c2 + 1]
                    + e4.z * W1c[256 + c2 + 1] + e4.w * W1c[384 + c2 + 1];
            }
            v0 = fmaxf(v0, 0.f); v1 = fmaxf(v1, 0.f);
        }
        if (EPI == 4) { v0 = fmaxf(v0, 0.f); v1 = fmaxf(v1, 0.f); }
        stage[r * 132 + c2]     = v0;
        stage[r * 132 + c2 + 1] = v1;
        if (EPI == 1) {
            float s1 = v0 + v1, s2 = v0 * v0 + v1 * v1;
#pragma unroll
            for (int o = 16; o > 0; o >>= 1) {
                s1 += __shfl_xor_sync(0xffffffffu, s1, o);
                s2 += __shfl_xor_sync(0xffffffffu, s2, o);
            }
            if ((tid & 31) == 0) {
                int hf = (id >> 5) & 1;
                rs1[r * 2 + hf] = s1;
                rs2[r * 2 + hf] = s2;
            }
        }
    }
    __syncthreads();

    for (int id = tid; id < 128 * 64; id += 256) {
        int r = id >> 6, c2 = (id & 63) * 2;
        int row = rowBase + r;
        float v0 = stage[r * 132 + c2];
        float v1 = stage[r * 132 + c2 + 1];
        if (EPI == 1) {
            float mean = (rs1[r * 2] + rs1[r * 2 + 1]) * (1.f / HID);
            float var  = (rs2[r * 2] + rs2[r * 2 + 1]) * (1.f / HID) - mean * mean;
            float rstd = rsqrtf(var + 1e-5f);
            v0 = (v0 - mean) * rstd * lg[c2]     + lb[c2];
            v1 = (v1 - mean) * rstd * lg[c2 + 1] + lb[c2 + 1];
            if (xout) *(float2*)&xout[(size_t)row * HID + c2] = make_float2(v0, v1);
            if (WSD) { stage[r * 132 + c2] = v0; stage[r * 132 + c2 + 1] = v1; }
        }
        if (EPI == 0) *(float2*)&xout[(size_t)row * HID + c2] = make_float2(v0, v1);
        if (EPI == 3 && row < NEDGE) *(float2*)&xout[(size_t)row * HID + c2] = make_float2(v0, v1);
        if (EPI <= 3) {
            *(__half2*)&OA[(size_t)row * HID + c2] = __floats2half2_rn(v0, v1);
        }
    }

    constexpr bool PHC = (EPI == 0) || (EPI == 4) || (EPI == 1 && WSD);
    if (PHC) {
        __syncthreads();
        int r = tid >> 1, half = tid & 1;
        int row = rowBase + r;
        if (EPI == 4) {
            float s0 = 0.f, s1 = 0.f;
            for (int c = 0; c < 64; c++) {
                int col = half * 64 + c;
                float v = stage[r * 132 + col];
                s0 = fmaf(v, W2[col * 2], s0);
                s1 = fmaf(v, W2[col * 2 + 1], s1);
            }
            s0 += __shfl_xor_sync(0xffffffffu, s0, 1);
            s1 += __shfl_xor_sync(0xffffffffu, s1, 1);
            if (half == 0 && row < NEDGE) {
                lout[(size_t)row * 2]     = s0 + b2[0];
                lout[(size_t)row * 2 + 1] = s1 + b2[1];
            }
        } else {
            float pr[8] = {0,0,0,0,0,0,0,0};
            for (int c = 0; c < 64; c++) {
                int col = half * 64 + c;
                float v = stage[r * 132 + col];
                const float* w = wsd + col * 8;
#pragma unroll
                for (int p = 0; p < 8; p++) pr[p] = fmaf(v, w[p], pr[p]);
            }
#pragma unroll
            for (int p = 0; p < 8; p++) pr[p] += __shfl_xor_sync(0xffffffffu, pr[p], 1);
            if (half == 0) {
                ((float4*)esOut)[row] = make_float4(pr[0], pr[1], pr[2], pr[3]);
                ((float4*)edOut)[row] = make_float4(pr[4], pr[5], pr[6], pr[7]);
            }
        }
    }
}

// ---------------- launch ----------------
extern "C" void kernel_launch(void* const* d_in, const int* in_sizes, int n_in,
                              void* d_out, int out_size) {
    const float* nf    = (const float*)d_in[0];
    const float* ef    = (const float*)d_in[2];
    const float* npW1  = (const float*)d_in[4];
    const float* npb1  = (const float*)d_in[5];
    const float* npW2  = (const float*)d_in[6];
    const float* npb2  = (const float*)d_in[7];
    const float* gatW  = (const float*)d_in[8];
    const float* gatAs = (const float*)d_in[9];
    const float* gatAd = (const float*)d_in[10];
    const float* gatB  = (const float*)d_in[11];
    const float* lnG   = (const float*)d_in[12];
    const float* lnB   = (const float*)d_in[13];
    const float* emW1  = (const float*)d_in[14];
    const float* emb1  = (const float*)d_in[15];
    const float* emW2  = (const float*)d_in[16];
    const float* emb2  = (const float*)d_in[17];
    const float* whW1  = (const float*)d_in[18];
    const float* whb1  = (const float*)d_in[19];
    const float* whW2  = (const float*)d_in[20];
    const float* whb2  = (const float*)d_in[21];

    float* out    = (float*)d_out;
    float* embOut = out + (size_t)NEDGE * 2;

    float *x13, *xA, *xB, *wsd, *es0, *ed0, *es1, *ed1;
    __half *Ah0, *Ah1, *Bnp, *Bg0, *Bg1, *Bg2, *Bem1, *Bem2, *Bwh;
    cudaGetSymbolAddress((void**)&x13, g_x13);
    cudaGetSymbolAddress((void**)&xA,  g_xA);
    cudaGetSymbolAddress((void**)&xB,  g_xB);
    cudaGetSymbolAddress((void**)&wsd, g_wsd);
    cudaGetSymbolAddress((void**)&es0, g_es0);
    cudaGetSymbolAddress((void**)&ed0, g_ed0);
    cudaGetSymbolAddress((void**)&es1, g_es1);
    cudaGetSymbolAddress((void**)&ed1, g_ed1);
    cudaGetSymbolAddress((void**)&Ah0, g_Ah0);
    cudaGetSymbolAddress((void**)&Ah1, g_Ah1);
    cudaGetSymbolAddress((void**)&Bnp, g_Bnp);
    cudaGetSymbolAddress((void**)&Bg0, g_Bg0);
    cudaGetSymbolAddress((void**)&Bg1, g_Bg1);
    cudaGetSymbolAddress((void**)&Bg2, g_Bg2);
    cudaGetSymbolAddress((void**)&Bem1, g_Bem1);
    cudaGetSymbolAddress((void**)&Bem2, g_Bem2);
    cudaGetSymbolAddress((void**)&Bwh, g_Bwh);

    constexpr int SMEM = 104448 + 4096;   // 108544 B/CTA -> 2 CTAs/SM
    auto mmA  = k_mm<1, 0, 0, 1, 2>;
    auto mmB1 = k_mm<4, 2, 1, 1, 1>;   // GAT: single-pass weights
    auto mmB0 = k_mm<4, 2, 1, 0, 1>;
    auto mmC  = k_mm<2, 1, 2, 0, 2>;
    auto mmDE = k_mm<1, 0, 5, 0, 2>;   // fused edge MLP2 + head
    cudaFuncSetAttribute(mmA,  cudaFuncAttributeMaxDynamicSharedMemorySize, SMEM);
    cudaFuncSetAttribute(mmB1, cudaFuncAttributeMaxDynamicSharedMemorySize, SMEM);
    cudaFuncSetAttribute(mmB0, cudaFuncAttributeMaxDynamicSharedMemorySize, SMEM);
    cudaFuncSetAttribute(mmC,  cudaFuncAttributeMaxDynamicSharedMemorySize, SMEM);
    cudaFuncSetAttribute(mmDE, cudaFuncAttributeMaxDynamicSharedMemorySize, SMEM);
    cudaFuncSetAttribute(k_prop2, cudaFuncAttributeMaxDynamicSharedMemorySize, 1023 * NF * 4);

    // 0) mega-prep (weight splits + folded vectors + propagate level-1), then top levels
    k_prep<<<1606, 256>>>(npW2, gatW, emW1, emW2, whW1, gatAs, gatAd, nf, x13);
    k_prop2<<<1, 512, 1023 * NF * 4>>>(x13);

    // 1) node MLP
    k_mlp1<<<(MPAD * 16) / 256, 256>>>(nf, x13, npW1, npb1);
    mmA<<<512, 256, SMEM>>>(Ah1, Bnp, Bnp + 16384, npb2, nullptr, xA, Ah0,
                            nullptr, nullptr, es0, ed0, wsd, nullptr, nullptr,
                            nullptr, nullptr, nullptr, nullptr, nullptr, nullptr, nullptr);

    // 2) GAT layers (alpha computed in-kernel; single-pass weights)
    mmB1<<<512, 256, SMEM>>>(Ah0, Bg0, Bg0 + 65536, gatB, xA, xB, Ah1,
                             es0, ed0, es1, ed1, wsd + 1024, lnG, lnB,
                             nullptr, nullptr, nullptr, nullptr, nullptr, nullptr, nullptr);
    mmB1<<<512, 256, SMEM>>>(Ah1, Bg1, Bg1 + 65536, gatB + HID, xB, xA, Ah0,
                             es1, ed1, es0, ed0, wsd + 2048, lnG + HID, lnB + HID,
                             nullptr, nullptr, nullptr, nullptr, nullptr, nullptr, nullptr);
    mmB0<<<512, 256, SMEM>>>(Ah0, Bg2, Bg2 + 65536, gatB + 2 * HID, xA, nullptr, Ah1,
                             es0, ed0, nullptr, nullptr, nullptr, lnG + 2 * HID, lnB + 2 * HID,
                             nullptr, nullptr, nullptr, nullptr, nullptr, nullptr, nullptr);

    // 3) edge MLP1 (gather) then fused edge MLP2 + head
    mmC<<<512, 256, SMEM>>>(Ah1, Bem1, Bem1 + 32768, emb1, nullptr, nullptr, Ah0,
                            nullptr, nullptr, nullptr, nullptr, nullptr, nullptr, nullptr,
                            ef, emW1 + 256 * HID, nullptr, nullptr, nullptr, nullptr, nullptr);
    mmDE<<<512, 256, SMEM>>>(Ah0, Bem2, Bem2 + 16384, emb2, nullptr, embOut, nullptr,
                             nullptr, nullptr, nullptr, nullptr, nullptr, nullptr, nullptr,
                             nullptr, nullptr, whW2, whb2, Bwh, whb1, out);
}

// round 17
// speedup vs baseline: 3.4145x; 1.0472x over previous
#include <cuda_runtime.h>
#include <cuda_fp16.h>
#include <mma.h>
#include <cstdint>
#include <math.h>

using namespace nvcuda;

#define NNODES 65535
#define NEDGE  65534
#define NINT   32767
#define MPAD   65536
#define HID    128
#define NF     13
#define NL     3

// ---------------- device-global scratch ----------------
__device__ float g_x13[NINT * NF];
__device__ float g_xA [MPAD * HID];
__device__ float g_xB [MPAD * HID];
__device__ __align__(16) float g_es0[MPAD * 4];
__device__ __align__(16) float g_ed0[MPAD * 4];
__device__ __align__(16) float g_es1[MPAD * 4];
__device__ __align__(16) float g_ed1[MPAD * 4];
__device__ float g_wsd[NL * HID * 8];
__device__ __align__(16) __half g_Ah0[(MPAD + 8) * HID];   // activations, single fp16
__device__ __align__(16) __half g_Ah1[(MPAD + 8) * HID];
// weights: [hi | lo], dest layout [N][K]  (lo halves now unused; kept for layout stability)
__device__ __align__(16) __half g_Bnp [2 * 128 * 128];
__device__ __align__(16) __half g_Bg0 [2 * 128 * 512];
__device__ __align__(16) __half g_Bg1 [2 * 128 * 512];
__device__ __align__(16) __half g_Bg2 [2 * 128 * 512];
__device__ __align__(16) __half g_Bem1[2 * 128 * 256];
__device__ __align__(16) __half g_Bem2[2 * 128 * 128];
__device__ __align__(16) __half g_Bwh [2 * 128 * 128];

// ---------------- cp.async helpers ----------------
__device__ __forceinline__ void cp16(uint32_t dst, const void* src) {
    asm volatile("cp.async.ca.shared.global [%0], [%1], 16;" :: "r"(dst), "l"(src) : "memory");
}
__device__ __forceinline__ void cp_wait_all() {
    asm volatile("cp.async.commit_group;\ncp.async.wait_group 0;" ::: "memory");
}

// ---------------- mega-prep: weight splits + wsd + propagate level-1 ----------------
__device__ __forceinline__ void splitW(const float* __restrict__ W, __half* __restrict__ D,
                                       int K, int e) {
    int n = e / K, k = e - n * K;
    float v = W[(size_t)k * 128 + n];
    D[e] = __float2half_rn(v);
}
__global__ void k_prep(const float* __restrict__ npW2, const float* __restrict__ gatW,
                       const float* __restrict__ emW1, const float* __restrict__ emW2,
                       const float* __restrict__ whW1, const float* __restrict__ as,
                       const float* __restrict__ ad, const float* __restrict__ nf,
                       float* __restrict__ x13) {
    __shared__ float bufA[64 * NF], bufB[32 * NF];
    if (blockIdx.x >= 1094) {                       // propagate bottom 6 levels
        int m = 511 + (blockIdx.x - 1094);
        int tid = threadIdx.x;
        size_t lbase = (size_t)(64 * m + 63) * NF;
        for (int i = tid; i < 64 * NF; i += 256) bufA[i] = nf[lbase + i];
        __syncthreads();
        float* cur = bufA; float* nxt = bufB;
        int cnt = 32;
#pragma unroll
        for (int s = 1; s <= 6; s++) {
            int start = m * cnt + (cnt - 1);
            for (int i = tid; i < cnt * NF; i += 256) {
                int r = i / NF, f = i - r * NF;
                float v = 0.5f * (cur[(2 * r) * NF + f] + cur[(2 * r + 1) * NF + f]);
                nxt[i] = v;
                x13[(size_t)(start + r) * NF + f] = v;
            }
            __syncthreads();
            float* t = cur; cur = nxt; nxt = t;
            cnt >>= 1;
        }
        return;
    }
    int i = blockIdx.x * 256 + threadIdx.x;
    if (i < 16384) { splitW(npW2, g_Bnp, 128, i); return; }
    if (i < 212992) {
        int j = i - 16384;
        int l = j >> 16, e = j & 65535;
        int d = e >> 9, kk = e & 511;
        int h = kk >> 7, k = kk & 127;
        float v = gatW[(size_t)l * 65536 + (size_t)k * 512 + h * 128 + d] * 0.25f;
        __half* B = (l == 0) ? g_Bg0 : (l == 1) ? g_Bg1 : g_Bg2;
        B[(size_t)d * 512 + kk] = __float2half_rn(v);
        return;
    }
    if (i < 245760) { splitW(emW1, g_Bem1, 256, i - 212992); return; }
    if (i < 262144) { splitW(emW2, g_Bem2, 128, i - 245760); return; }
    if (i < 278528) { splitW(whW1, g_Bwh, 128, i - 262144); return; }
    if (i < 280064) {                               // folded attention vectors
        int j = i - 278528;
        int l = j >> 9, t = j & 511;
        int k = t >> 2, h = t & 3;
        const float* wr = gatW + (size_t)l * HID * 512 + (size_t)k * 512 + h * 128;
        const float* av = as + l * 512 + h * 128;
        const float* dv = ad + l * 512 + h * 128;
        float s = 0.f, d2 = 0.f;
        for (int dd = 0; dd < 128; dd++) {
            float w = wr[dd];
            s  = fmaf(w, av[dd], s);
            d2 = fmaf(w, dv[dd], d2);
        }
        g_wsd[l * 1024 + k * 8 + h]     = s;
        g_wsd[l * 1024 + k * 8 + 4 + h] = d2;
    }
}

// ---------------- propagate top levels ----------------
__global__ void k_prop2(float* __restrict__ x13) {
    extern __shared__ float buf[];
    int tid = threadIdx.x;
    for (int i = tid; i < 512 * NF; i += 512) buf[511 * NF + i] = x13[511 * NF + i];
    __syncthreads();
    for (int d = 8; d >= 0; d--) {
        int start = (1 << d) - 1, cnt = 1 << d;
        for (int i = tid; i < cnt * NF; i += 512) {
            int r = i / NF, f = i - r * NF;
            int n = start + r;
            buf[n * NF + f] = 0.5f * (buf[(2 * n + 1) * NF + f] + buf[(2 * n + 2) * NF + f]);
        }
        __syncthreads();
    }
    for (int i = tid; i < 511 * NF; i += 512) x13[i] = buf[i];
}

// ---------------- node MLP layer 1 -> fp16 ----------------
__global__ void k_mlp1(const float* __restrict__ nf, const float* __restrict__ x13,
                       const float* __restrict__ W1, const float* __restrict__ b1) {
    int idx = blockIdx.x * blockDim.x + threadIdx.x;
    if (idx >= MPAD * 16) return;
    int n = idx >> 4, c0 = (idx & 15) << 3;
    float acc[8];
#pragma unroll
    for (int j = 0; j < 8; j++) acc[j] = b1[c0 + j];
    const float* src = nullptr;
    if (n < NINT)        src = x13 + (size_t)n * NF;
    else if (n < NNODES) src = nf  + (size_t)n * NF;
    if (src) {
#pragma unroll
        for (int k = 0; k < NF; k++) {
            float xv = __ldg(src + k);
#pragma unroll
            for (int j = 0; j < 8; j++) acc[j] = fmaf(xv, W1[k * HID + c0 + j], acc[j]);
        }
    }
    union { uint4 v; __half2 h[4]; } o;
#pragma unroll
    for (int u = 0; u < 4; u++)
        o.h[u] = __floats2half2_rn(fmaxf(acc[2 * u], 0.f), fmaxf(acc[2 * u + 1], 0.f));
    *(uint4*)&g_Ah1[(size_t)n * HID + c0] = o.v;
}

// =================== fused WMMA fp16 GEMM, 128x128 tile, 2 CTAs/SM ===================
// Single-pass fp16 weights everywhere.
// STAGE: 0 plain, 1 edge gather, 2 attention aggregate (in-kernel alphas).
// EPI: 0 ATTN  1 GAT(residual+LN[+scores])  2 EF  3 BIASO  4 HEAD  5 fused edgeMLP2+HEAD
template <int KC, int STAGE, int EPI, int WSD>
__global__ void __launch_bounds__(256, 2)
k_mm(const __half* __restrict__ A, const __half* __restrict__ Bh,
     const float* __restrict__ bias, const float* __restrict__ xin,
     float* __restrict__ xout, __half* __restrict__ OA,
     const float* __restrict__ esIn, const float* __restrict__ edIn,
     float* __restrict__ esOut, float* __restrict__ edOut,
     const float* __restrict__ wsd, const float* __restrict__ lg, const float* __restrict__ lb,
     const float* __restrict__ ef, const float* __restrict__ W1c,
     const float* __restrict__ W2, const float* __restrict__ b2,
     const __half* __restrict__ B2, const float* __restrict__ bias2,
     float* __restrict__ lout) {
    extern __shared__ char smem[];
    __half* sA  = (__half*)smem;                          // [0, 34816)
    __half* sBh = sA + 128 * 136;                         // [34816, 69632)
    uint2* salpha = (uint2*)(smem + 104448);              // 4KB fp16 alpha table
    float* rs1 = (float*)(smem + 104448);                 // aliases salpha (dead by epilogue)
    float* rs2 = rs1 + 256;
    const uint32_t sbase = (uint32_t)__cvta_generic_to_shared(smem);

    const int tid = threadIdx.x;
    const int wid = tid >> 5;
    const int rowBase = blockIdx.x * 128;
    const int row_off = (wid & 3) * 32;
    const int col_off = (wid >> 2) * 64;

    if (STAGE == 2) {
        if (tid < 128) {
            int n = rowBase + tid;
            bool vp = n > 0;
            int p  = vp ? (n - 1) >> 1 : 0;
            int c1 = 2 * n + 1;
            bool vc = c1 < NNODES;
            int nb[4] = {n, p, vc ? c1 : 0, vc ? c1 + 1 : 0};
            bool val[4] = {true, vp, vc, vc};
            float4 e4[4];
#pragma unroll
            for (int j = 0; j < 4; j++) e4[j] = ((const float4*)esIn)[nb[j]];
            float4 dD = ((const float4*)edIn)[n];
            float esv[4][4], edv[4] = {dD.x, dD.y, dD.z, dD.w};
#pragma unroll
            for (int j = 0; j < 4; j++) { esv[j][0]=e4[j].x; esv[j][1]=e4[j].y; esv[j][2]=e4[j].z; esv[j][3]=e4[j].w; }
#pragma unroll
            for (int h = 0; h < 4; h++) {
                float e[4], m = -1e30f;
#pragma unroll
                for (int j = 0; j < 4; j++) {
                    float s = esv[j][h] + edv[h];
                    s = (s >= 0.f) ? s : 0.2f * s;
                    e[j] = s;
                    if (val[j]) m = fmaxf(m, s);
                }
                float sum = 0.f;
#pragma unroll
                for (int j = 0; j < 4; j++) { e[j] = val[j] ? expf(e[j] - m) : 0.f; sum += e[j]; }
                float inv = 1.f / sum;
                uint2 pk;
                *(__half2*)&pk.x = __floats2half2_rn(e[0] * inv, e[1] * inv);
                *(__half2*)&pk.y = __floats2half2_rn(e[2] * inv, e[3] * inv);
                salpha[tid * 4 + h] = pk;
            }
        }
        __syncthreads();
    }

    wmma::fragment<wmma::accumulator, 16, 16, 16, float> acc[2][4];
#pragma unroll
    for (int i = 0; i < 2; i++)
#pragma unroll
        for (int j = 0; j < 4; j++) wmma::fill_fragment(acc[i][j], 0.0f);

    const uint4* gA  = (const uint4*)A;
    const uint4* gBh = (const uint4*)Bh;

#pragma unroll
    for (int c = 0; c < KC; c++) {
        for (int id = tid; id < 128 * 16; id += 256) {
            int r = id >> 4, q = id & 15;
            uint32_t dstA = sbase + r * 272 + q * 16;
            if (STAGE == 0) {
                size_t g = (size_t)(rowBase + r) * (KC * 16) + c * 16 + q;
                cp16(dstA, &gA[g]);
            } else if (STAGE == 1) {
                int e = rowBase + r;
                size_t row = (c == 0) ? (size_t)(e >> 1) : (size_t)(e + 1);
                cp16(dstA, &gA[row * 16 + q]);
            } else {
                int n = rowBase + r;
                int p  = (n > 0) ? (n - 1) >> 1 : 0;
                int c1 = 2 * n + 1;
                bool vc = c1 < NNODES;
                int nb[4] = {n, p, vc ? c1 : 0, vc ? c1 + 1 : 0};
                uint2 av = salpha[r * 4 + c];
                float2 f01 = __half22float2(*(__half2*)&av.x);
                float2 f23 = __half22float2(*(__half2*)&av.y);
                float aj[4] = {f01.x, f01.y, f23.x, f23.y};
                float z[8] = {0,0,0,0,0,0,0,0};
#pragma unroll
                for (int j = 0; j < 4; j++) {
                    uint4 hv = gA[(size_t)nb[j] * 16 + q];
                    const __half2* hp = (const __half2*)&hv;
                    float a = aj[j];
#pragma unroll
                    for (int u = 0; u < 4; u++) {
                        float2 fh = __half22float2(hp[u]);
                        z[2*u]   = fmaf(a, fh.x, z[2*u]);
                        z[2*u+1] = fmaf(a, fh.y, z[2*u+1]);
                    }
                }
                union { uint4 v; __half2 h[4]; } oz;
#pragma unroll
                for (int u = 0; u < 4; u++) oz.h[u] = __floats2half2_rn(z[2*u], z[2*u+1]);
                *(uint4*)&sA[r * 136 + q * 8] = oz.v;
            }
        }
        for (int id = tid; id < 128 * 16; id += 256) {
            int r = id >> 4, q = id & 15;
            size_t g = (size_t)r * (KC * 16) + c * 16 + q;
            cp16(sbase + 34816 + r * 272 + q * 16, &gBh[g]);
        }
        cp_wait_all();
        __syncthreads();

#pragma unroll
        for (int ks = 0; ks < 8; ks++) {
            wmma::fragment<wmma::matrix_a, 16, 16, 16, __half, wmma::row_major> ah[2];
#pragma unroll
            for (int i = 0; i < 2; i++)
                wmma::load_matrix_sync(ah[i], sA + (row_off + i * 16) * 136 + ks * 16, 136);
#pragma unroll
            for (int j = 0; j < 4; j++) {
                wmma::fragment<wmma::matrix_b, 16, 16, 16, __half, wmma::col_major> bh;
                wmma::load_matrix_sync(bh, sBh + (col_off + j * 16) * 136 + ks * 16, 136);
#pragma unroll
                for (int i = 0; i < 2; i++)
                    wmma::mma_sync(acc[i][j], ah[i], bh, acc[i][j]);
            }
        }
        __syncthreads();
    }

    float* stage = (float*)smem;
#pragma unroll
    for (int i = 0; i < 2; i++)
#pragma unroll
        for (int j = 0; j < 4; j++)
            wmma::store_matrix_sync(stage + (row_off + i * 16) * 132 + col_off + j * 16,
                                    acc[i][j], 132, wmma::mem_row_major);
    __syncthreads();

    if (EPI == 5) {
        // ---- fused: emb output + fp16 convert into high smem ----
        __half* sA2 = (__half*)(smem + 69632);
        for (int id = tid; id < 128 * 64; id += 256) {
            int r = id >> 6, c2 = (id & 63) * 2;
            int row = rowBase + r;
            float v0 = stage[r * 132 + c2]     + bias[c2];
            float v1 = stage[r * 132 + c2 + 1] + bias[c2 + 1];
            if (row < NEDGE) *(float2*)&xout[(size_t)row * HID + c2] = make_float2(v0, v1);
            *(__half2*)&sA2[r * 136 + c2] = __floats2half2_rn(v0, v1);
        }
        __syncthreads();
        // ---- stage whW1 into [0, 34816) (stage is dead) ----
        const uint4* gB2h = (const uint4*)B2;
        for (int id = tid; id < 128 * 16; id += 256) {
            int r = id >> 4, q = id & 15;
            cp16(sbase + r * 272 + q * 16, &gB2h[(size_t)r * 16 + q]);
        }
        cp_wait_all();
        __syncthreads();
        // ---- second GEMM: emb @ whW1 ----
#pragma unroll
        for (int i = 0; i < 2; i++)
#pragma unroll
            for (int j = 0; j < 4; j++) wmma::fill_fragment(acc[i][j], 0.0f);
        __half* b2h = (__half*)smem;
#pragma unroll
        for (int ks = 0; ks < 8; ks++) {
            wmma::fragment<wmma::matrix_a, 16, 16, 16, __half, wmma::row_major> ah[2];
#pragma unroll
            for (int i = 0; i < 2; i++)
                wmma::load_matrix_sync(ah[i], sA2 + (row_off + i * 16) * 136 + ks * 16, 136);
#pragma unroll
            for (int j = 0; j < 4; j++) {
                wmma::fragment<wmma::matrix_b, 16, 16, 16, __half, wmma::col_major> bh;
                wmma::load_matrix_sync(bh, b2h + (col_off + j * 16) * 136 + ks * 16, 136);
#pragma unroll
                for (int i = 0; i < 2; i++)
                    wmma::mma_sync(acc[i][j], ah[i], bh, acc[i][j]);
            }
        }
        __syncthreads();
#pragma unroll
        for (int i = 0; i < 2; i++)
#pragma unroll
            for (int j = 0; j < 4; j++)
                wmma::store_matrix_sync(stage + (row_off + i * 16) * 132 + col_off + j * 16,
                                        acc[i][j], 132, wmma::mem_row_major);
        __syncthreads();
        // ---- logits: relu(v + whb1) . W2 + b2 ----
        int r = tid >> 1, half = tid & 1;
        int row = rowBase + r;
        float s0 = 0.f, s1 = 0.f;
        for (int c = 0; c < 64; c++) {
            int col = half * 64 + c;
            float v = fmaxf(stage[r * 132 + col] + bias2[col], 0.f);
            s0 = fmaf(v, W2[col * 2], s0);
            s1 = fmaf(v, W2[col * 2 + 1], s1);
        }
        s0 += __shfl_xor_sync(0xffffffffu, s0, 1);
        s1 += __shfl_xor_sync(0xffffffffu, s1, 1);
        if (half == 0 && row < NEDGE) {
            lout[(size_t)row * 2]     = s0 + b2[0];
            lout[(size_t)row * 2 + 1] = s1 + b2[1];
        }
        return;
    }

    for (int id = tid; id < 128 * 64; id += 256) {
        int r = id >> 6, c2 = (id & 63) * 2;
        int row = rowBase + r;
        float v0 = stage[r * 132 + c2]     + bias[c2];
        float v1 = stage[r * 132 + c2 + 1] + bias[c2 + 1];
        if (EPI == 1) {
            float2 xv = *(const float2*)&xin[(size_t)row * HID + c2];
            v0 += xv.x; v1 += xv.y;
        }
        if (EPI == 2) {
            if (row < NEDGE) {
                float4 e4 = ((const float4*)ef)[row];
                v0 += e4.x * W1c[c2]       + e4.y * W1c[128 + c2]
                    + e4.z * W1c[256 + c2] + e4.w * W1c[384 + c2];
                v1 += e4.x * W1c[c2 + 1]       + e4.y * W1c[128 + c2 + 1]
                    + e4.z * W1c[256 + c2 + 1] + e4.w * W1c[384 + c2 + 1];
            }
            v0 = fmaxf(v0, 0.f); v1 = fmaxf(v1, 0.f);
        }
        if (EPI == 4) { v0 = fmaxf(v0, 0.f); v1 = fmaxf(v1, 0.f); }
        stage[r * 132 + c2]     = v0;
        stage[r * 132 + c2 + 1] = v1;
        if (EPI == 1) {
            float s1 = v0 + v1, s2 = v0 * v0 + v1 * v1;
#pragma unroll
            for (int o = 16; o > 0; o >>= 1) {
                s1 += __shfl_xor_sync(0xffffffffu, s1, o);
                s2 += __shfl_xor_sync(0xffffffffu, s2, o);
            }
            if ((tid & 31) == 0) {
                int hf = (id >> 5) & 1;
                rs1[r * 2 + hf] = s1;
                rs2[r * 2 + hf] = s2;
            }
        }
    }
    __syncthreads();

    for (int id = tid; id < 128 * 64; id += 256) {
        int r = id >> 6, c2 = (id & 63) * 2;
        int row = rowBase + r;
        float v0 = stage[r * 132 + c2];
        float v1 = stage[r * 132 + c2 + 1];
        if (EPI == 1) {
            float mean = (rs1[r * 2] + rs1[r * 2 + 1]) * (1.f / HID);
            float var  = (rs2[r * 2] + rs2[r * 2 + 1]) * (1.f / HID) - mean * mean;
            float rstd = rsqrtf(var + 1e-5f);
            v0 = (v0 - mean) * rstd * lg[c2]     + lb[c2];
            v1 = (v1 - mean) * rstd * lg[c2 + 1] + lb[c2 + 1];
            if (xout) *(float2*)&xout[(size_t)row * HID + c2] = make_float2(v0, v1);
            if (WSD) { stage[r * 132 + c2] = v0; stage[r * 132 + c2 + 1] = v1; }
        }
        if (EPI == 0) *(float2*)&xout[(size_t)row * HID + c2] = make_float2(v0, v1);
        if (EPI == 3 && row < NEDGE) *(float2*)&xout[(size_t)row * HID + c2] = make_float2(v0, v1);
        if (EPI <= 3) {
            *(__half2*)&OA[(size_t)row * HID + c2] = __floats2half2_rn(v0, v1);
        }
    }

    constexpr bool PHC = (EPI == 0) || (EPI == 4) || (EPI == 1 && WSD);
    if (PHC) {
        __syncthreads();
        int r = tid >> 1, half = tid & 1;
        int row = rowBase + r;
        if (EPI == 4) {
            float s0 = 0.f, s1 = 0.f;
            for (int c = 0; c < 64; c++) {
                int col = half * 64 + c;
                float v = stage[r * 132 + col];
                s0 = fmaf(v, W2[col * 2], s0);
                s1 = fmaf(v, W2[col * 2 + 1], s1);
            }
            s0 += __shfl_xor_sync(0xffffffffu, s0, 1);
            s1 += __shfl_xor_sync(0xffffffffu, s1, 1);
            if (half == 0 && row < NEDGE) {
                lout[(size_t)row * 2]     = s0 + b2[0];
                lout[(size_t)row * 2 + 1] = s1 + b2[1];
            }
        } else {
            float pr[8] = {0,0,0,0,0,0,0,0};
            for (int c = 0; c < 64; c++) {
                int col = half * 64 + c;
                float v = stage[r * 132 + col];
                const float* w = wsd + col * 8;
#pragma unroll
                for (int p = 0; p < 8; p++) pr[p] = fmaf(v, w[p], pr[p]);
            }
#pragma unroll
            for (int p = 0; p < 8; p++) pr[p] += __shfl_xor_sync(0xffffffffu, pr[p], 1);
            if (half == 0) {
                ((float4*)esOut)[row] = make_float4(pr[0], pr[1], pr[2], pr[3]);
                ((float4*)edOut)[row] = make_float4(pr[4], pr[5], pr[6], pr[7]);
            }
        }
    }
}

// ---------------- launch ----------------
extern "C" void kernel_launch(void* const* d_in, const int* in_sizes, int n_in,
                              void* d_out, int out_size) {
    const float* nf    = (const float*)d_in[0];
    const float* ef    = (const float*)d_in[2];
    const float* npW1  = (const float*)d_in[4];
    const float* npb1  = (const float*)d_in[5];
    const float* npW2  = (const float*)d_in[6];
    const float* npb2  = (const float*)d_in[7];
    const float* gatW  = (const float*)d_in[8];
    const float* gatAs = (const float*)d_in[9];
    const float* gatAd = (const float*)d_in[10];
    const float* gatB  = (const float*)d_in[11];
    const float* lnG   = (const float*)d_in[12];
    const float* lnB   = (const float*)d_in[13];
    const float* emW1  = (const float*)d_in[14];
    const float* emb1  = (const float*)d_in[15];
    const float* emW2  = (const float*)d_in[16];
    const float* emb2  = (const float*)d_in[17];
    const float* whW1  = (const float*)d_in[18];
    const float* whb1  = (const float*)d_in[19];
    const float* whW2  = (const float*)d_in[20];
    const float* whb2  = (const float*)d_in[21];

    float* out    = (float*)d_out;
    float* embOut = out + (size_t)NEDGE * 2;

    float *x13, *xA, *xB, *wsd, *es0, *ed0, *es1, *ed1;
    __half *Ah0, *Ah1, *Bnp, *Bg0, *Bg1, *Bg2, *Bem1, *Bem2, *Bwh;
    cudaGetSymbolAddress((void**)&x13, g_x13);
    cudaGetSymbolAddress((void**)&xA,  g_xA);
    cudaGetSymbolAddress((void**)&xB,  g_xB);
    cudaGetSymbolAddress((void**)&wsd, g_wsd);
    cudaGetSymbolAddress((void**)&es0, g_es0);
    cudaGetSymbolAddress((void**)&ed0, g_ed0);
    cudaGetSymbolAddress((void**)&es1, g_es1);
    cudaGetSymbolAddress((void**)&ed1, g_ed1);
    cudaGetSymbolAddress((void**)&Ah0, g_Ah0);
    cudaGetSymbolAddress((void**)&Ah1, g_Ah1);
    cudaGetSymbolAddress((void**)&Bnp, g_Bnp);
    cudaGetSymbolAddress((void**)&Bg0, g_Bg0);
    cudaGetSymbolAddress((void**)&Bg1, g_Bg1);
    cudaGetSymbolAddress((void**)&Bg2, g_Bg2);
    cudaGetSymbolAddress((void**)&Bem1, g_Bem1);
    cudaGetSymbolAddress((void**)&Bem2, g_Bem2);
    cudaGetSymbolAddress((void**)&Bwh, g_Bwh);

    constexpr int SMEM = 104448 + 4096;   // 108544 B/CTA -> 2 CTAs/SM
    auto mmA  = k_mm<1, 0, 0, 1>;
    auto mmB1 = k_mm<4, 2, 1, 1>;
    auto mmB0 = k_mm<4, 2, 1, 0>;
    auto mmC  = k_mm<2, 1, 2, 0>;
    auto mmDE = k_mm<1, 0, 5, 0>;   // fused edge MLP2 + head
    cudaFuncSetAttribute(mmA,  cudaFuncAttributeMaxDynamicSharedMemorySize, SMEM);
    cudaFuncSetAttribute(mmB1, cudaFuncAttributeMaxDynamicSharedMemorySize, SMEM);
    cudaFuncSetAttribute(mmB0, cudaFuncAttributeMaxDynamicSharedMemorySize, SMEM);
    cudaFuncSetAttribute(mmC,  cudaFuncAttributeMaxDynamicSharedMemorySize, SMEM);
    cudaFuncSetAttribute(mmDE, cudaFuncAttributeMaxDynamicSharedMemorySize, SMEM);
    cudaFuncSetAttribute(k_prop2, cudaFuncAttributeMaxDynamicSharedMemorySize, 1023 * NF * 4);

    // 0) mega-prep (weight converts + folded vectors + propagate level-1), then top levels
    k_prep<<<1606, 256>>>(npW2, gatW, emW1, emW2, whW1, gatAs, gatAd, nf, x13);
    k_prop2<<<1, 512, 1023 * NF * 4>>>(x13);

    // 1) node MLP
    k_mlp1<<<(MPAD * 16) / 256, 256>>>(nf, x13, npW1, npb1);
    mmA<<<512, 256, SMEM>>>(Ah1, Bnp, npb2, nullptr, xA, Ah0,
                            nullptr, nullptr, es0, ed0, wsd, nullptr, nullptr,
                            nullptr, nullptr, nullptr, nullptr, nullptr, nullptr, nullptr);

    // 2) GAT layers (alpha computed in-kernel; single-pass weights)
    mmB1<<<512, 256, SMEM>>>(Ah0, Bg0, gatB, xA, xB, Ah1,
                             es0, ed0, es1, ed1, wsd + 1024, lnG, lnB,
                             nullptr, nullptr, nullptr, nullptr, nullptr, nullptr, nullptr);
    mmB1<<<512, 256, SMEM>>>(Ah1, Bg1, gatB + HID, xB, xA, Ah0,
                             es1, ed1, es0, ed0, wsd + 2048, lnG + HID, lnB + HID,
                             nullptr, nullptr, nullptr, nullptr, nullptr, nullptr, nullptr);
    mmB0<<<512, 256, SMEM>>>(Ah0, Bg2, gatB + 2 * HID, xA, nullptr, Ah1,
                             es0, ed0, nullptr, nullptr, nullptr, lnG + 2 * HID, lnB + 2 * HID,
                             nullptr, nullptr, nullptr, nullptr, nullptr, nullptr, nullptr);

    // 3) edge MLP1 (gather) then fused edge MLP2 + head
    mmC<<<512, 256, SMEM>>>(Ah1, Bem1, emb1, nullptr, nullptr, Ah0,
                            nullptr, nullptr, nullptr, nullptr, nullptr, nullptr, nullptr,
                            ef, emW1 + 256 * HID, nullptr, nullptr, nullptr, nullptr, nullptr);
    mmDE<<<512, 256, SMEM>>>(Ah0, Bem2, emb2, nullptr, embOut, nullptr,
                             nullptr, nullptr, nullptr, nullptr, nullptr, nullptr, nullptr,
                             nullptr, nullptr, whW2, whb2, Bwh, whb1, out);
}